// round 6
// baseline (speedup 1.0000x reference)
#include <cuda_runtime.h>
#include <cuda_fp16.h>
#include <math.h>
#include <stdint.h>

// Problem shape (fixed)
#define B_  2
#define T_  2048
#define D_  1024
#define H_  16
#define HD_ 64
#define M_  (B_*T_)   // 4096

// ---------------------------------------------------------------------------
// Scratch (__device__ globals; no allocations allowed)
// ---------------------------------------------------------------------------
__device__ __half g_XH[(size_t)M_ * D_];
__device__ __half g_XL[(size_t)M_ * D_];
__device__ __half g_QH[(size_t)M_ * D_];
__device__ __half g_QL[(size_t)M_ * D_];
__device__ __half g_KH[(size_t)M_ * D_];
__device__ __half g_KL[(size_t)M_ * D_];
__device__ __half g_VH[(size_t)M_ * D_];
__device__ __half g_VL[(size_t)M_ * D_];
__device__ __half g_CH[(size_t)M_ * D_];
__device__ __half g_CL[(size_t)M_ * D_];
// Transposed+split weights [N][K]
__device__ __half g_WT16[8][(size_t)D_ * D_];

// ---------------------------------------------------------------------------
// PTX helpers (sm_80-level features only)
// ---------------------------------------------------------------------------
__device__ __forceinline__ uint32_t smem_u32(const void* p) {
    uint32_t a;
    asm("{ .reg .u64 t; cvta.to.shared.u64 t, %1; cvt.u32.u64 %0, t; }"
        : "=r"(a) : "l"(p));
    return a;
}

__device__ __forceinline__ void cp_async16(uint32_t saddr, const void* gaddr) {
    asm volatile("cp.async.cg.shared.global [%0], [%1], 16;"
                 :: "r"(saddr), "l"(gaddr));
}
#define CP_COMMIT() asm volatile("cp.async.commit_group;" ::: "memory")
#define CP_WAIT(n)  asm volatile("cp.async.wait_group %0;" :: "n"(n) : "memory")

__device__ __forceinline__ void ldm4(uint32_t* r, uint32_t addr) {
    asm volatile("ldmatrix.sync.aligned.m8n8.x4.shared.b16 {%0,%1,%2,%3}, [%4];"
                 : "=r"(r[0]), "=r"(r[1]), "=r"(r[2]), "=r"(r[3]) : "r"(addr));
}

__device__ __forceinline__ void ldm4t(uint32_t* r, uint32_t addr) {
    asm volatile("ldmatrix.sync.aligned.m8n8.x4.trans.shared.b16 {%0,%1,%2,%3}, [%4];"
                 : "=r"(r[0]), "=r"(r[1]), "=r"(r[2]), "=r"(r[3]) : "r"(addr));
}

__device__ __forceinline__ void mma16816(float* d, const uint32_t* a,
                                         uint32_t b0, uint32_t b1) {
    asm volatile(
        "mma.sync.aligned.m16n8k16.row.col.f32.f16.f16.f32 "
        "{%0,%1,%2,%3},{%4,%5,%6,%7},{%8,%9},{%0,%1,%2,%3};"
        : "+f"(d[0]), "+f"(d[1]), "+f"(d[2]), "+f"(d[3])
        : "r"(a[0]), "r"(a[1]), "r"(a[2]), "r"(a[3]), "r"(b0), "r"(b1));
}

__device__ __forceinline__ uint32_t h2_bits(__half2 v) {
    return *(uint32_t*)&v;
}

// ---------------------------------------------------------------------------
// Prepass 1: fp32 -> (fp16 hi, fp16 lo) split
// ---------------------------------------------------------------------------
__global__ void split16_kernel(const float4* __restrict__ in,
                               uint2* __restrict__ hi, uint2* __restrict__ lo,
                               int n4) {
    int i = blockIdx.x * blockDim.x + threadIdx.x;
    if (i >= n4) return;
    float4 v = in[i];
    __half hx = __float2half_rn(v.x), hy = __float2half_rn(v.y);
    __half hz = __float2half_rn(v.z), hw = __float2half_rn(v.w);
    __half lx = __float2half_rn(v.x - __half2float(hx));
    __half ly = __float2half_rn(v.y - __half2float(hy));
    __half lz = __float2half_rn(v.z - __half2float(hz));
    __half lw = __float2half_rn(v.w - __half2float(hw));
    __half2 h0 = __halves2half2(hx, hy), h1 = __halves2half2(hz, hw);
    __half2 l0 = __halves2half2(lx, ly), l1 = __halves2half2(lz, lw);
    hi[i] = make_uint2(h2_bits(h0), h2_bits(h1));
    lo[i] = make_uint2(h2_bits(l0), h2_bits(l1));
}

// ---------------------------------------------------------------------------
// Prepass 2: W[k][n] -> WT_hi[n][k], WT_lo[n][k] (transpose + fp16 split)
// ---------------------------------------------------------------------------
__global__ void transpose_split16_kernel(const float* __restrict__ W,
                                         __half* __restrict__ TH,
                                         __half* __restrict__ TL) {
    __shared__ float t[32][33];
    const int tx = threadIdx.x, ty = threadIdx.y;   // 32 x 8
    const int bn = blockIdx.x * 32;
    const int bk = blockIdx.y * 32;
#pragma unroll
    for (int i = 0; i < 4; i++)
        t[ty + 8 * i][tx] = W[(size_t)(bk + ty + 8 * i) * D_ + bn + tx];
    __syncthreads();
#pragma unroll
    for (int i = 0; i < 4; i++) {
        int row = ty + 8 * i;
        float v = t[tx][row];
        __half h = __float2half_rn(v);
        size_t o = (size_t)(bn + row) * D_ + bk + tx;
        TH[o] = h;
        TL[o] = __float2half_rn(v - __half2float(h));
    }
}

// ---------------------------------------------------------------------------
// mma.sync fp16 3-term GEMM: CTA tile 128x256, 8 warps (2x4), warp tile 64x64,
// BK=32, 2-stage cp.async. Grid (4, 32) -> 128 CTAs (single wave).
// ---------------------------------------------------------------------------
#define GA_TB    (128 * 80)          // A sub-tile (hi or lo): 128 rows x 80B
#define GB_TB    (256 * 80)          // B sub-tile: 256 rows x 80B
#define G_STAGE  (2 * GA_TB + 2 * GB_TB)   // 61440
#define G_SMEM   (2 * G_STAGE)             // 122880
#define G_NK     32
#define G_NCH    (D_ / G_NK)

__device__ __forceinline__ void g16_load(
    const __half* __restrict__ AH, const __half* __restrict__ AL,
    const __half* __restrict__ BH, const __half* __restrict__ BL,
    uint32_t sbase, int bm, int bn, int c, int tid)
{
    const int k0 = c * G_NK;
    // A: 128 rows x 4 x 16B
#pragma unroll
    for (int i = 0; i < 2; i++) {
        int idx = tid + (i << 8);
        int r = idx >> 2, ch = idx & 3;
        uint32_t so = (uint32_t)(r * 80 + ch * 16);
        size_t ga = (size_t)(bm + r) * D_ + k0 + ch * 8;
        cp_async16(sbase + so,         AH + ga);
        cp_async16(sbase + GA_TB + so, AL + ga);
    }
    // B: 256 rows x 4 x 16B
#pragma unroll
    for (int i = 0; i < 4; i++) {
        int idx = tid + (i << 8);
        int r = idx >> 2, ch = idx & 3;
        uint32_t so = (uint32_t)(2 * GA_TB + r * 80 + ch * 16);
        size_t gb = (size_t)(bn + r) * D_ + k0 + ch * 8;
        cp_async16(sbase + so,         BH + gb);
        cp_async16(sbase + GB_TB + so, BL + gb);
    }
}

__global__ void __launch_bounds__(256, 1) gemm16_kernel(
    const __half* __restrict__ AH, const __half* __restrict__ AL,
    const __half* __restrict__ BH, const __half* __restrict__ BL,
    const float* __restrict__ bias, float scale,
    float* __restrict__ outF,
    __half* __restrict__ outH, __half* __restrict__ outL)
{
    extern __shared__ char smem[];
    const uint32_t sb = smem_u32(smem);
    const int tid = threadIdx.x;
    const int lid = tid & 31;
    const int wid = tid >> 5;
    const int wm  = wid >> 2;       // 0..1 -> 64 rows
    const int wn  = wid & 3;        // 0..3 -> 64 cols
    const int row16 = lid & 15;
    const int sel   = lid >> 4;
    const int bm = blockIdx.y << 7;   // 128
    const int bn = blockIdx.x << 8;   // 256

    float acc[4][8][4];
#pragma unroll
    for (int mi = 0; mi < 4; mi++)
#pragma unroll
        for (int ni = 0; ni < 8; ni++)
#pragma unroll
            for (int j = 0; j < 4; j++) acc[mi][ni][j] = 0.f;

    g16_load(AH, AL, BH, BL, sb, bm, bn, 0, tid);
    CP_COMMIT();
    g16_load(AH, AL, BH, BL, sb + G_STAGE, bm, bn, 1, tid);
    CP_COMMIT();

    for (int c = 0; c < G_NCH; c++) {
        if (c < G_NCH - 1) CP_WAIT(1); else CP_WAIT(0);
        __syncthreads();

        const uint32_t s = sb + (uint32_t)(c & 1) * G_STAGE;
#pragma unroll
        for (int kk = 0; kk < 2; kk++) {
            const uint32_t koff = (uint32_t)((kk * 2 + sel) * 16);
            uint32_t ah[4][4], al[4][4];
#pragma unroll
            for (int mi = 0; mi < 4; mi++) {
                uint32_t addr = s + (uint32_t)((wm * 64 + mi * 16 + row16) * 80) + koff;
                ldm4(ah[mi], addr);
                ldm4(al[mi], addr + GA_TB);
            }
#pragma unroll
            for (int g = 0; g < 4; g++) {
                uint32_t addr = s + 2 * GA_TB +
                                (uint32_t)((wn * 64 + g * 16 + row16) * 80) + koff;
                uint32_t bh4[4], bl4[4];
                ldm4(bh4, addr);
                ldm4(bl4, addr + GB_TB);
#pragma unroll
                for (int mi = 0; mi < 4; mi++)
#pragma unroll
                    for (int o = 0; o < 2; o++) {
                        mma16816(acc[mi][2 * g + o], ah[mi], bh4[o], bh4[o + 2]);
                        mma16816(acc[mi][2 * g + o], ah[mi], bl4[o], bl4[o + 2]);
                        mma16816(acc[mi][2 * g + o], al[mi], bh4[o], bh4[o + 2]);
                    }
            }
        }
        __syncthreads();
        if (c + 2 < G_NCH) {
            g16_load(AH, AL, BH, BL, sb + (uint32_t)(c & 1) * G_STAGE,
                     bm, bn, c + 2, tid);
            CP_COMMIT();
        }
    }

#pragma unroll
    for (int mi = 0; mi < 4; mi++)
#pragma unroll
        for (int ni = 0; ni < 8; ni++) {
            int row = bm + wm * 64 + mi * 16 + (lid >> 2);
            int col = bn + wn * 64 + ni * 8 + (lid & 3) * 2;
            float v0 = acc[mi][ni][0] * scale, v1 = acc[mi][ni][1] * scale;
            float v2 = acc[mi][ni][2] * scale, v3 = acc[mi][ni][3] * scale;
            if (outF) {
                float b0 = bias ? bias[col] : 0.f, b1 = bias ? bias[col + 1] : 0.f;
                *(float2*)&outF[(size_t)row * D_ + col]       = make_float2(v0 + b0, v1 + b1);
                *(float2*)&outF[(size_t)(row + 8) * D_ + col] = make_float2(v2 + b0, v3 + b1);
            } else {
                __half2 h0 = __floats2half2_rn(v0, v1);
                __half2 l0 = __floats2half2_rn(v0 - __low2float(h0), v1 - __high2float(h0));
                __half2 h1 = __floats2half2_rn(v2, v3);
                __half2 l1 = __floats2half2_rn(v2 - __low2float(h1), v3 - __high2float(h1));
                *(__half2*)&outH[(size_t)row * D_ + col]       = h0;
                *(__half2*)&outL[(size_t)row * D_ + col]       = l0;
                *(__half2*)&outH[(size_t)(row + 8) * D_ + col] = h1;
                *(__half2*)&outL[(size_t)(row + 8) * D_ + col] = l1;
            }
        }
}

// ---------------------------------------------------------------------------
// Flash attention v3: BM=128 (8 warps x 16 rows), BN=64, fp16 split mma.sync.
// K/V traffic per output halved vs BM=64. q-tiles launched big-first.
// ---------------------------------------------------------------------------
#define F_QT   (128 * 144)             // 18432 (one Q sub-tile)
#define F_KT   (64 * 144)              // 9216  (one K/V sub-tile)
#define F_STG  (4 * F_KT)              // Kh, Kl, Vh, Vl = 36864
#define F_SMEM (2 * F_QT + 2 * F_STG)  // 110592

__device__ __forceinline__ void f_load_kv(
    const __half* __restrict__ KH, const __half* __restrict__ KL,
    const __half* __restrict__ VH, const __half* __restrict__ VL,
    uint32_t sbase, size_t base, int kt, int tid)
{
#pragma unroll
    for (int t = 0; t < 4; t++) {
        const __half* src = (t == 0) ? KH : (t == 1) ? KL : (t == 2) ? VH : VL;
#pragma unroll
        for (int i = 0; i < 2; i++) {
            int idx = tid + (i << 8);
            int r = idx >> 3, c = idx & 7;
            cp_async16(sbase + (uint32_t)(t * F_KT + r * 144 + c * 16),
                       src + base + (size_t)(kt * 64 + r) * D_ + c * 8);
        }
    }
}

__global__ void __launch_bounds__(256) flash16_kernel(
    const __half* __restrict__ QH, const __half* __restrict__ QL,
    const __half* __restrict__ KH, const __half* __restrict__ KL,
    const __half* __restrict__ VH, const __half* __restrict__ VL,
    __half* __restrict__ CH, __half* __restrict__ CL)
{
    extern __shared__ char fsm[];
    const uint32_t sb = smem_u32(fsm);
    const int qt = (int)gridDim.x - 1 - (int)blockIdx.x;   // big tiles first
    const int bh = blockIdx.y;
    const int b = bh >> 4, h = bh & 15;
    const int tid = threadIdx.x, wid = tid >> 5, lid = tid & 31;
    const size_t base = ((size_t)b * T_) * D_ + (size_t)h * HD_;
    const int ktmax = 2 * qt + 1;

    // Q tiles (hi, lo) -> smem
#pragma unroll
    for (int part = 0; part < 2; part++) {
        const __half* src = part ? QL : QH;
#pragma unroll
        for (int i = 0; i < 4; i++) {
            int idx = tid + (i << 8);
            int r = idx >> 3, c = idx & 7;
            cp_async16(sb + (uint32_t)(part * F_QT + r * 144 + c * 16),
                       src + base + (size_t)(qt * 128 + r) * D_ + c * 8);
        }
    }
    f_load_kv(KH, KL, VH, VL, sb + 2 * F_QT, base, 0, tid);
    CP_COMMIT();
    f_load_kv(KH, KL, VH, VL, sb + 2 * F_QT + F_STG, base, 1, tid);
    CP_COMMIT();

    uint32_t qfh[4][4], qfl[4][4];
    float oacc[8][4];
    float m_[2] = {-INFINITY, -INFINITY}, l_[2] = {0.f, 0.f};
#pragma unroll
    for (int ni = 0; ni < 8; ni++)
#pragma unroll
        for (int j = 0; j < 4; j++) oacc[ni][j] = 0.f;

    for (int kt = 0; kt <= ktmax; kt++) {
        if (kt < ktmax) CP_WAIT(1); else CP_WAIT(0);
        __syncthreads();

        if (kt == 0) {
#pragma unroll
            for (int dc = 0; dc < 4; dc++) {
                uint32_t a = sb + (uint32_t)((wid * 16 + (lid & 15)) * 144
                             + dc * 32 + (lid >> 4) * 16);
                ldm4(qfh[dc], a);
                ldm4(qfl[dc], a + F_QT);
            }
        }

        const uint32_t ks = sb + 2 * F_QT + (uint32_t)(kt & 1) * F_STG;

        // ---- S = Q K^T (3-term) ----
        float sacc[8][4];
#pragma unroll
        for (int ni = 0; ni < 8; ni++)
#pragma unroll
            for (int j = 0; j < 4; j++) sacc[ni][j] = 0.f;

#pragma unroll
        for (int dc = 0; dc < 4; dc++) {
#pragma unroll
            for (int g = 0; g < 4; g++) {
                uint32_t ka = ks + (uint32_t)((g * 16 + (lid & 7) + ((lid >> 4) & 1) * 8) * 144
                              + dc * 32 + ((lid >> 3) & 1) * 16);
                uint32_t kh4[4], kl4[4];
                ldm4(kh4, ka);
                ldm4(kl4, ka + F_KT);
                mma16816(sacc[2 * g],     qfh[dc], kh4[0], kh4[1]);
                mma16816(sacc[2 * g],     qfh[dc], kl4[0], kl4[1]);
                mma16816(sacc[2 * g],     qfl[dc], kh4[0], kh4[1]);
                mma16816(sacc[2 * g + 1], qfh[dc], kh4[2], kh4[3]);
                mma16816(sacc[2 * g + 1], qfh[dc], kl4[2], kl4[3]);
                mma16816(sacc[2 * g + 1], qfl[dc], kh4[2], kh4[3]);
            }
        }

        // ---- causal mask (last two k-tiles touch the diagonal) ----
        if (kt >= 2 * qt) {
            int r0 = qt * 128 + wid * 16 + (lid >> 2);
            int cb = kt * 64 + (lid & 3) * 2;
#pragma unroll
            for (int ni = 0; ni < 8; ni++) {
                int c0 = cb + ni * 8;
                if (c0     > r0)     sacc[ni][0] = -INFINITY;
                if (c0 + 1 > r0)     sacc[ni][1] = -INFINITY;
                if (c0     > r0 + 8) sacc[ni][2] = -INFINITY;
                if (c0 + 1 > r0 + 8) sacc[ni][3] = -INFINITY;
            }
        }

        // ---- online softmax ----
#pragma unroll
        for (int r = 0; r < 2; r++) {
            float mt = -INFINITY;
#pragma unroll
            for (int ni = 0; ni < 8; ni++)
                mt = fmaxf(mt, fmaxf(sacc[ni][2 * r], sacc[ni][2 * r + 1]));
            mt = fmaxf(mt, __shfl_xor_sync(0xffffffffu, mt, 1));
            mt = fmaxf(mt, __shfl_xor_sync(0xffffffffu, mt, 2));
            float mn = fmaxf(m_[r], mt);
            float sc = __expf(m_[r] - mn);
            float ps = 0.f;
#pragma unroll
            for (int ni = 0; ni < 8; ni++) {
                float p0 = __expf(sacc[ni][2 * r]     - mn);
                float p1 = __expf(sacc[ni][2 * r + 1] - mn);
                sacc[ni][2 * r] = p0; sacc[ni][2 * r + 1] = p1;
                ps += p0 + p1;
            }
            ps += __shfl_xor_sync(0xffffffffu, ps, 1);
            ps += __shfl_xor_sync(0xffffffffu, ps, 2);
            l_[r] = l_[r] * sc + ps;
            m_[r] = mn;
#pragma unroll
            for (int ni = 0; ni < 8; ni++) {
                oacc[ni][2 * r]     *= sc;
                oacc[ni][2 * r + 1] *= sc;
            }
        }

        // ---- pack P into A-fragments (hi + lo) ----
        uint32_t pah[4][4], pal[4][4];
#pragma unroll
        for (int kc = 0; kc < 4; kc++) {
#pragma unroll
            for (int q = 0; q < 4; q++) {
                int ni = 2 * kc + (q >> 1);
                float p0 = sacc[ni][(q & 1) * 2];
                float p1 = sacc[ni][(q & 1) * 2 + 1];
                __half2 hp = __floats2half2_rn(p0, p1);
                __half2 lp = __floats2half2_rn(p0 - __low2float(hp),
                                               p1 - __high2float(hp));
                pah[kc][q] = h2_bits(hp);
                pal[kc][q] = h2_bits(lp);
            }
        }

        // ---- O += P V (3-term) ----
        const uint32_t vs = ks + 2 * F_KT;
#pragma unroll
        for (int kc = 0; kc < 4; kc++) {
#pragma unroll
            for (int g = 0; g < 4; g++) {
                uint32_t va = vs + (uint32_t)((kc * 16 + (lid & 7) + ((lid >> 3) & 1) * 8) * 144
                              + (g * 16 + ((lid >> 4) & 1) * 8) * 2);
                uint32_t vh4[4], vl4[4];
                ldm4t(vh4, va);
                ldm4t(vl4, va + F_KT);
                mma16816(oacc[2 * g],     pah[kc], vh4[0], vh4[1]);
                mma16816(oacc[2 * g],     pah[kc], vl4[0], vl4[1]);
                mma16816(oacc[2 * g],     pal[kc], vh4[0], vh4[1]);
                mma16816(oacc[2 * g + 1], pah[kc], vh4[2], vh4[3]);
                mma16816(oacc[2 * g + 1], pah[kc], vl4[2], vl4[3]);
                mma16816(oacc[2 * g + 1], pal[kc], vh4[2], vh4[3]);
            }
        }

        __syncthreads();
        if (kt + 2 <= ktmax) {
            f_load_kv(KH, KL, VH, VL, sb + 2 * F_QT + (uint32_t)(kt & 1) * F_STG,
                      base, kt + 2, tid);
            CP_COMMIT();
        }
    }

    // ---- epilogue: normalize and write split C ----
    float inv0 = 1.f / l_[0], inv1 = 1.f / l_[1];
    int row0 = qt * 128 + wid * 16 + (lid >> 2);
#pragma unroll
    for (int ni = 0; ni < 8; ni++) {
        int col = ni * 8 + (lid & 3) * 2;
        float v0 = oacc[ni][0] * inv0, v1 = oacc[ni][1] * inv0;
        float v2 = oacc[ni][2] * inv1, v3 = oacc[ni][3] * inv1;
        __half2 h0 = __floats2half2_rn(v0, v1);
        __half2 l0 = __floats2half2_rn(v0 - __low2float(h0), v1 - __high2float(h0));
        __half2 h1 = __floats2half2_rn(v2, v3);
        __half2 l1 = __floats2half2_rn(v2 - __low2float(h1), v3 - __high2float(h1));
        size_t o0 = base + (size_t)row0 * D_ + col;
        size_t o1 = base + (size_t)(row0 + 8) * D_ + col;
        *(__half2*)&CH[o0] = h0;
        *(__half2*)&CL[o0] = l0;
        *(__half2*)&CH[o1] = h1;
        *(__half2*)&CL[o1] = l1;
    }
}

// ---------------------------------------------------------------------------
extern "C" void kernel_launch(void* const* d_in, const int* in_sizes, int n_in,
                              void* d_out, int out_size)
{
    const float* X  = (const float*)d_in[0];
    const float* Wq = (const float*)d_in[1];
    const float* Wk = (const float*)d_in[2];
    const float* Wv = (const float*)d_in[3];
    const float* Wo = (const float*)d_in[4];
    const float* bo = (const float*)d_in[5];
    float* Y = (float*)d_out;

    __half *gXH, *gXL, *gQH, *gQL, *gKH, *gKL, *gVH, *gVL, *gCH, *gCL, *gWT;
    cudaGetSymbolAddress((void**)&gXH, g_XH);
    cudaGetSymbolAddress((void**)&gXL, g_XL);
    cudaGetSymbolAddress((void**)&gQH, g_QH);
    cudaGetSymbolAddress((void**)&gQL, g_QL);
    cudaGetSymbolAddress((void**)&gKH, g_KH);
    cudaGetSymbolAddress((void**)&gKL, g_KL);
    cudaGetSymbolAddress((void**)&gVH, g_VH);
    cudaGetSymbolAddress((void**)&gVL, g_VL);
    cudaGetSymbolAddress((void**)&gCH, g_CH);
    cudaGetSymbolAddress((void**)&gCL, g_CL);
    cudaGetSymbolAddress((void**)&gWT, g_WT16);
    const size_t WSZ = (size_t)D_ * D_;

    cudaFuncSetAttribute(gemm16_kernel,
                         cudaFuncAttributeMaxDynamicSharedMemorySize, G_SMEM);
    cudaFuncSetAttribute(flash16_kernel,
                         cudaFuncAttributeMaxDynamicSharedMemorySize, F_SMEM);

    const int n4 = (M_ * D_) / 4;
    split16_kernel<<<(n4 + 255) / 256, 256>>>((const float4*)X,
                                              (uint2*)gXH, (uint2*)gXL, n4);
    dim3 tb(32, 8), tg(32, 32);
    transpose_split16_kernel<<<tg, tb>>>(Wq, gWT + 0 * WSZ, gWT + 1 * WSZ);
    transpose_split16_kernel<<<tg, tb>>>(Wk, gWT + 2 * WSZ, gWT + 3 * WSZ);
    transpose_split16_kernel<<<tg, tb>>>(Wv, gWT + 4 * WSZ, gWT + 5 * WSZ);
    transpose_split16_kernel<<<tg, tb>>>(Wo, gWT + 6 * WSZ, gWT + 7 * WSZ);

    dim3 gg(D_ / 256, M_ / 128);   // (4, 32) = 128 CTAs (single wave)
    gemm16_kernel<<<gg, 256, G_SMEM>>>(gXH, gXL, gWT + 0 * WSZ, gWT + 1 * WSZ,
                                       nullptr, 0.125f, nullptr, gQH, gQL);
    gemm16_kernel<<<gg, 256, G_SMEM>>>(gXH, gXL, gWT + 2 * WSZ, gWT + 3 * WSZ,
                                       nullptr, 1.0f, nullptr, gKH, gKL);
    gemm16_kernel<<<gg, 256, G_SMEM>>>(gXH, gXL, gWT + 4 * WSZ, gWT + 5 * WSZ,
                                       nullptr, 1.0f, nullptr, gVH, gVL);

    flash16_kernel<<<dim3(T_ / 128, B_ * H_), 256, F_SMEM>>>(
        gQH, gQL, gKH, gKL, gVH, gVL, gCH, gCL);

    gemm16_kernel<<<gg, 256, G_SMEM>>>(gCH, gCL, gWT + 6 * WSZ, gWT + 7 * WSZ,
                                       bo, 1.0f, Y, nullptr, nullptr);
}

// round 7
// speedup vs baseline: 1.0124x; 1.0124x over previous
#include <cuda_runtime.h>
#include <cuda_fp16.h>
#include <math.h>
#include <stdint.h>

// Problem shape (fixed)
#define B_  2
#define T_  2048
#define D_  1024
#define H_  16
#define HD_ 64
#define M_  (B_*T_)   // 4096

// ---------------------------------------------------------------------------
// Scratch (__device__ globals; no allocations allowed)
// ---------------------------------------------------------------------------
__device__ __half g_XH[(size_t)M_ * D_];
__device__ __half g_XL[(size_t)M_ * D_];
__device__ __half g_QH[(size_t)M_ * D_];
__device__ __half g_QL[(size_t)M_ * D_];
__device__ __half g_KH[(size_t)M_ * D_];
__device__ __half g_KL[(size_t)M_ * D_];
__device__ __half g_VH[(size_t)M_ * D_];
__device__ __half g_VL[(size_t)M_ * D_];
__device__ __half g_CH[(size_t)M_ * D_];
__device__ __half g_CL[(size_t)M_ * D_];
// Transposed+split weights [N][K]
__device__ __half g_WT16[8][(size_t)D_ * D_];

// ---------------------------------------------------------------------------
// PTX helpers (sm_80-level features only)
// ---------------------------------------------------------------------------
__device__ __forceinline__ uint32_t smem_u32(const void* p) {
    uint32_t a;
    asm("{ .reg .u64 t; cvta.to.shared.u64 t, %1; cvt.u32.u64 %0, t; }"
        : "=r"(a) : "l"(p));
    return a;
}

__device__ __forceinline__ void cp_async16(uint32_t saddr, const void* gaddr) {
    asm volatile("cp.async.cg.shared.global [%0], [%1], 16;"
                 :: "r"(saddr), "l"(gaddr));
}
#define CP_COMMIT() asm volatile("cp.async.commit_group;" ::: "memory")
#define CP_WAIT(n)  asm volatile("cp.async.wait_group %0;" :: "n"(n) : "memory")

__device__ __forceinline__ void ldm4(uint32_t* r, uint32_t addr) {
    asm volatile("ldmatrix.sync.aligned.m8n8.x4.shared.b16 {%0,%1,%2,%3}, [%4];"
                 : "=r"(r[0]), "=r"(r[1]), "=r"(r[2]), "=r"(r[3]) : "r"(addr));
}

__device__ __forceinline__ void ldm4t(uint32_t* r, uint32_t addr) {
    asm volatile("ldmatrix.sync.aligned.m8n8.x4.trans.shared.b16 {%0,%1,%2,%3}, [%4];"
                 : "=r"(r[0]), "=r"(r[1]), "=r"(r[2]), "=r"(r[3]) : "r"(addr));
}

__device__ __forceinline__ void mma16816(float* d, const uint32_t* a,
                                         uint32_t b0, uint32_t b1) {
    asm volatile(
        "mma.sync.aligned.m16n8k16.row.col.f32.f16.f16.f32 "
        "{%0,%1,%2,%3},{%4,%5,%6,%7},{%8,%9},{%0,%1,%2,%3};"
        : "+f"(d[0]), "+f"(d[1]), "+f"(d[2]), "+f"(d[3])
        : "r"(a[0]), "r"(a[1]), "r"(a[2]), "r"(a[3]), "r"(b0), "r"(b1));
}

__device__ __forceinline__ uint32_t h2_bits(__half2 v) {
    return *(uint32_t*)&v;
}

// ---------------------------------------------------------------------------
// Prepass 1: fp32 -> (fp16 hi, fp16 lo) split
// ---------------------------------------------------------------------------
__global__ void split16_kernel(const float4* __restrict__ in,
                               uint2* __restrict__ hi, uint2* __restrict__ lo,
                               int n4) {
    int i = blockIdx.x * blockDim.x + threadIdx.x;
    if (i >= n4) return;
    float4 v = in[i];
    __half hx = __float2half_rn(v.x), hy = __float2half_rn(v.y);
    __half hz = __float2half_rn(v.z), hw = __float2half_rn(v.w);
    __half lx = __float2half_rn(v.x - __half2float(hx));
    __half ly = __float2half_rn(v.y - __half2float(hy));
    __half lz = __float2half_rn(v.z - __half2float(hz));
    __half lw = __float2half_rn(v.w - __half2float(hw));
    __half2 h0 = __halves2half2(hx, hy), h1 = __halves2half2(hz, hw);
    __half2 l0 = __halves2half2(lx, ly), l1 = __halves2half2(lz, lw);
    hi[i] = make_uint2(h2_bits(h0), h2_bits(h1));
    lo[i] = make_uint2(h2_bits(l0), h2_bits(l1));
}

// ---------------------------------------------------------------------------
// Prepass 2: W[k][n] -> WT_hi[n][k], WT_lo[n][k] (transpose + fp16 split)
// ---------------------------------------------------------------------------
__global__ void transpose_split16_kernel(const float* __restrict__ W,
                                         __half* __restrict__ TH,
                                         __half* __restrict__ TL) {
    __shared__ float t[32][33];
    const int tx = threadIdx.x, ty = threadIdx.y;   // 32 x 8
    const int bn = blockIdx.x * 32;
    const int bk = blockIdx.y * 32;
#pragma unroll
    for (int i = 0; i < 4; i++)
        t[ty + 8 * i][tx] = W[(size_t)(bk + ty + 8 * i) * D_ + bn + tx];
    __syncthreads();
#pragma unroll
    for (int i = 0; i < 4; i++) {
        int row = ty + 8 * i;
        float v = t[tx][row];
        __half h = __float2half_rn(v);
        size_t o = (size_t)(bn + row) * D_ + bk + tx;
        TH[o] = h;
        TL[o] = __float2half_rn(v - __half2float(h));
    }
}

// ---------------------------------------------------------------------------
// mma.sync fp16 3-term GEMM (R5-verified config): CTA 128x128, 8 warps (2x4),
// warp tile 64x32, BK=32, 2-stage cp.async. Grid (8, 32) = 256 CTAs.
// ---------------------------------------------------------------------------
#define G_TB     (128 * 80)
#define G_STAGE  (4 * G_TB)
#define G_SMEM   (2 * G_STAGE)       // 81920 B
#define G_NK     32
#define G_NCH    (D_ / G_NK)

__device__ __forceinline__ void g16_load(
    const __half* __restrict__ AH, const __half* __restrict__ AL,
    const __half* __restrict__ BH, const __half* __restrict__ BL,
    uint32_t sbase, int bm, int bn, int c, int tid)
{
    const int k0 = c * G_NK;
#pragma unroll
    for (int i = 0; i < 2; i++) {
        int idx = tid + (i << 8);
        int r = idx >> 2, ch = idx & 3;
        uint32_t so = (uint32_t)(r * 80 + ch * 16);
        size_t ga = (size_t)(bm + r) * D_ + k0 + ch * 8;
        size_t gb = (size_t)(bn + r) * D_ + k0 + ch * 8;
        cp_async16(sbase + so,            AH + ga);
        cp_async16(sbase + G_TB + so,     AL + ga);
        cp_async16(sbase + 2 * G_TB + so, BH + gb);
        cp_async16(sbase + 3 * G_TB + so, BL + gb);
    }
}

__global__ void __launch_bounds__(256, 1) gemm16_kernel(
    const __half* __restrict__ AH, const __half* __restrict__ AL,
    const __half* __restrict__ BH, const __half* __restrict__ BL,
    const float* __restrict__ bias, float scale,
    float* __restrict__ outF,
    __half* __restrict__ outH, __half* __restrict__ outL)
{
    extern __shared__ char smem[];
    const uint32_t sb = smem_u32(smem);
    const int tid = threadIdx.x;
    const int lid = tid & 31;
    const int wid = tid >> 5;
    const int wm  = wid >> 2;
    const int wn  = wid & 3;
    const int row16 = lid & 15;
    const int sel   = lid >> 4;
    const int bm = blockIdx.y << 7;
    const int bn = blockIdx.x << 7;

    float acc[4][4][4];
#pragma unroll
    for (int mi = 0; mi < 4; mi++)
#pragma unroll
        for (int ni = 0; ni < 4; ni++)
#pragma unroll
            for (int j = 0; j < 4; j++) acc[mi][ni][j] = 0.f;

    g16_load(AH, AL, BH, BL, sb, bm, bn, 0, tid);
    CP_COMMIT();
    g16_load(AH, AL, BH, BL, sb + G_STAGE, bm, bn, 1, tid);
    CP_COMMIT();

    for (int c = 0; c < G_NCH; c++) {
        if (c < G_NCH - 1) CP_WAIT(1); else CP_WAIT(0);
        __syncthreads();

        const uint32_t s = sb + (uint32_t)(c & 1) * G_STAGE;
#pragma unroll
        for (int kk = 0; kk < 2; kk++) {
            const uint32_t koff = (uint32_t)((kk * 2 + sel) * 16);
            uint32_t ah[4][4], al[4][4];
#pragma unroll
            for (int mi = 0; mi < 4; mi++) {
                uint32_t addr = s + (uint32_t)((wm * 64 + mi * 16 + row16) * 80) + koff;
                ldm4(ah[mi], addr);
                ldm4(al[mi], addr + G_TB);
            }
            uint32_t bh[2][4], bl[2][4];
#pragma unroll
            for (int g = 0; g < 2; g++) {
                uint32_t addr = s + 2 * G_TB +
                                (uint32_t)((wn * 32 + g * 16 + row16) * 80) + koff;
                ldm4(bh[g], addr);
                ldm4(bl[g], addr + G_TB);
            }
#pragma unroll
            for (int mi = 0; mi < 4; mi++)
#pragma unroll
                for (int ni = 0; ni < 4; ni++) {
                    const int g = ni >> 1, o = ni & 1;
                    mma16816(acc[mi][ni], ah[mi], bh[g][o], bh[g][o + 2]);
                    mma16816(acc[mi][ni], ah[mi], bl[g][o], bl[g][o + 2]);
                    mma16816(acc[mi][ni], al[mi], bh[g][o], bh[g][o + 2]);
                }
        }
        __syncthreads();
        if (c + 2 < G_NCH) {
            g16_load(AH, AL, BH, BL, sb + (uint32_t)(c & 1) * G_STAGE,
                     bm, bn, c + 2, tid);
            CP_COMMIT();
        }
    }

#pragma unroll
    for (int mi = 0; mi < 4; mi++)
#pragma unroll
        for (int ni = 0; ni < 4; ni++) {
            int row = bm + wm * 64 + mi * 16 + (lid >> 2);
            int col = bn + wn * 32 + ni * 8 + (lid & 3) * 2;
            float v0 = acc[mi][ni][0] * scale, v1 = acc[mi][ni][1] * scale;
            float v2 = acc[mi][ni][2] * scale, v3 = acc[mi][ni][3] * scale;
            if (outF) {
                float b0 = bias ? bias[col] : 0.f, b1 = bias ? bias[col + 1] : 0.f;
                *(float2*)&outF[(size_t)row * D_ + col]       = make_float2(v0 + b0, v1 + b1);
                *(float2*)&outF[(size_t)(row + 8) * D_ + col] = make_float2(v2 + b0, v3 + b1);
            } else {
                __half2 h0 = __floats2half2_rn(v0, v1);
                __half2 l0 = __floats2half2_rn(v0 - __low2float(h0), v1 - __high2float(h0));
                __half2 h1 = __floats2half2_rn(v2, v3);
                __half2 l1 = __floats2half2_rn(v2 - __low2float(h1), v3 - __high2float(h1));
                *(__half2*)&outH[(size_t)row * D_ + col]       = h0;
                *(__half2*)&outL[(size_t)row * D_ + col]       = l0;
                *(__half2*)&outH[(size_t)(row + 8) * D_ + col] = h1;
                *(__half2*)&outL[(size_t)(row + 8) * D_ + col] = l1;
            }
        }
}

// ---------------------------------------------------------------------------
// Flash attention v3 (kept from R6): BM=128 (8 warps x 16 rows), BN=64,
// fp16 split mma.sync. K/V traffic halved vs BM=64; big q-tiles first.
// ---------------------------------------------------------------------------
#define F_QT   (128 * 144)             // 18432 (one Q sub-tile)
#define F_KT   (64 * 144)              // 9216  (one K/V sub-tile)
#define F_STG  (4 * F_KT)              // 36864
#define F_SMEM (2 * F_QT + 2 * F_STG)  // 110592

__device__ __forceinline__ void f_load_kv(
    const __half* __restrict__ KH, const __half* __restrict__ KL,
    const __half* __restrict__ VH, const __half* __restrict__ VL,
    uint32_t sbase, size_t base, int kt, int tid)
{
#pragma unroll
    for (int t = 0; t < 4; t++) {
        const __half* src = (t == 0) ? KH : (t == 1) ? KL : (t == 2) ? VH : VL;
#pragma unroll
        for (int i = 0; i < 2; i++) {
            int idx = tid + (i << 8);
            int r = idx >> 3, c = idx & 7;
            cp_async16(sbase + (uint32_t)(t * F_KT + r * 144 + c * 16),
                       src + base + (size_t)(kt * 64 + r) * D_ + c * 8);
        }
    }
}

__global__ void __launch_bounds__(256) flash16_kernel(
    const __half* __restrict__ QH, const __half* __restrict__ QL,
    const __half* __restrict__ KH, const __half* __restrict__ KL,
    const __half* __restrict__ VH, const __half* __restrict__ VL,
    __half* __restrict__ CH, __half* __restrict__ CL)
{
    extern __shared__ char fsm[];
    const uint32_t sb = smem_u32(fsm);
    const int qt = (int)gridDim.x - 1 - (int)blockIdx.x;   // big tiles first
    const int bh = blockIdx.y;
    const int b = bh >> 4, h = bh & 15;
    const int tid = threadIdx.x, wid = tid >> 5, lid = tid & 31;
    const size_t base = ((size_t)b * T_) * D_ + (size_t)h * HD_;
    const int ktmax = 2 * qt + 1;

    // Q tiles (hi, lo) -> smem
#pragma unroll
    for (int part = 0; part < 2; part++) {
        const __half* src = part ? QL : QH;
#pragma unroll
        for (int i = 0; i < 4; i++) {
            int idx = tid + (i << 8);
            int r = idx >> 3, c = idx & 7;
            cp_async16(sb + (uint32_t)(part * F_QT + r * 144 + c * 16),
                       src + base + (size_t)(qt * 128 + r) * D_ + c * 8);
        }
    }
    f_load_kv(KH, KL, VH, VL, sb + 2 * F_QT, base, 0, tid);
    CP_COMMIT();
    f_load_kv(KH, KL, VH, VL, sb + 2 * F_QT + F_STG, base, 1, tid);
    CP_COMMIT();

    uint32_t qfh[4][4], qfl[4][4];
    float oacc[8][4];
    float m_[2] = {-INFINITY, -INFINITY}, l_[2] = {0.f, 0.f};
#pragma unroll
    for (int ni = 0; ni < 8; ni++)
#pragma unroll
        for (int j = 0; j < 4; j++) oacc[ni][j] = 0.f;

    for (int kt = 0; kt <= ktmax; kt++) {
        if (kt < ktmax) CP_WAIT(1); else CP_WAIT(0);
        __syncthreads();

        if (kt == 0) {
#pragma unroll
            for (int dc = 0; dc < 4; dc++) {
                uint32_t a = sb + (uint32_t)((wid * 16 + (lid & 15)) * 144
                             + dc * 32 + (lid >> 4) * 16);
                ldm4(qfh[dc], a);
                ldm4(qfl[dc], a + F_QT);
            }
        }

        const uint32_t ks = sb + 2 * F_QT + (uint32_t)(kt & 1) * F_STG;

        // ---- S = Q K^T (3-term) ----
        float sacc[8][4];
#pragma unroll
        for (int ni = 0; ni < 8; ni++)
#pragma unroll
            for (int j = 0; j < 4; j++) sacc[ni][j] = 0.f;

#pragma unroll
        for (int dc = 0; dc < 4; dc++) {
#pragma unroll
            for (int g = 0; g < 4; g++) {
                uint32_t ka = ks + (uint32_t)((g * 16 + (lid & 7) + ((lid >> 4) & 1) * 8) * 144
                              + dc * 32 + ((lid >> 3) & 1) * 16);
                uint32_t kh4[4], kl4[4];
                ldm4(kh4, ka);
                ldm4(kl4, ka + F_KT);
                mma16816(sacc[2 * g],     qfh[dc], kh4[0], kh4[1]);
                mma16816(sacc[2 * g],     qfh[dc], kl4[0], kl4[1]);
                mma16816(sacc[2 * g],     qfl[dc], kh4[0], kh4[1]);
                mma16816(sacc[2 * g + 1], qfh[dc], kh4[2], kh4[3]);
                mma16816(sacc[2 * g + 1], qfh[dc], kl4[2], kl4[3]);
                mma16816(sacc[2 * g + 1], qfl[dc], kh4[2], kh4[3]);
            }
        }

        // ---- causal mask (last two k-tiles touch the diagonal) ----
        if (kt >= 2 * qt) {
            int r0 = qt * 128 + wid * 16 + (lid >> 2);
            int cb = kt * 64 + (lid & 3) * 2;
#pragma unroll
            for (int ni = 0; ni < 8; ni++) {
                int c0 = cb + ni * 8;
                if (c0     > r0)     sacc[ni][0] = -INFINITY;
                if (c0 + 1 > r0)     sacc[ni][1] = -INFINITY;
                if (c0     > r0 + 8) sacc[ni][2] = -INFINITY;
                if (c0 + 1 > r0 + 8) sacc[ni][3] = -INFINITY;
            }
        }

        // ---- online softmax ----
#pragma unroll
        for (int r = 0; r < 2; r++) {
            float mt = -INFINITY;
#pragma unroll
            for (int ni = 0; ni < 8; ni++)
                mt = fmaxf(mt, fmaxf(sacc[ni][2 * r], sacc[ni][2 * r + 1]));
            mt = fmaxf(mt, __shfl_xor_sync(0xffffffffu, mt, 1));
            mt = fmaxf(mt, __shfl_xor_sync(0xffffffffu, mt, 2));
            float mn = fmaxf(m_[r], mt);
            float sc = __expf(m_[r] - mn);
            float ps = 0.f;
#pragma unroll
            for (int ni = 0; ni < 8; ni++) {
                float p0 = __expf(sacc[ni][2 * r]     - mn);
                float p1 = __expf(sacc[ni][2 * r + 1] - mn);
                sacc[ni][2 * r] = p0; sacc[ni][2 * r + 1] = p1;
                ps += p0 + p1;
            }
            ps += __shfl_xor_sync(0xffffffffu, ps, 1);
            ps += __shfl_xor_sync(0xffffffffu, ps, 2);
            l_[r] = l_[r] * sc + ps;
            m_[r] = mn;
#pragma unroll
            for (int ni = 0; ni < 8; ni++) {
                oacc[ni][2 * r]     *= sc;
                oacc[ni][2 * r + 1] *= sc;
            }
        }

        // ---- pack P into A-fragments (hi + lo) ----
        uint32_t pah[4][4], pal[4][4];
#pragma unroll
        for (int kc = 0; kc < 4; kc++) {
#pragma unroll
            for (int q = 0; q < 4; q++) {
                int ni = 2 * kc + (q >> 1);
                float p0 = sacc[ni][(q & 1) * 2];
                float p1 = sacc[ni][(q & 1) * 2 + 1];
                __half2 hp = __floats2half2_rn(p0, p1);
                __half2 lp = __floats2half2_rn(p0 - __low2float(hp),
                                               p1 - __high2float(hp));
                pah[kc][q] = h2_bits(hp);
                pal[kc][q] = h2_bits(lp);
            }
        }

        // ---- O += P V (3-term) ----
        const uint32_t vs = ks + 2 * F_KT;
#pragma unroll
        for (int kc = 0; kc < 4; kc++) {
#pragma unroll
            for (int g = 0; g < 4; g++) {
                uint32_t va = vs + (uint32_t)((kc * 16 + (lid & 7) + ((lid >> 3) & 1) * 8) * 144
                              + (g * 16 + ((lid >> 4) & 1) * 8) * 2);
                uint32_t vh4[4], vl4[4];
                ldm4t(vh4, va);
                ldm4t(vl4, va + F_KT);
                mma16816(oacc[2 * g],     pah[kc], vh4[0], vh4[1]);
                mma16816(oacc[2 * g],     pah[kc], vl4[0], vl4[1]);
                mma16816(oacc[2 * g],     pal[kc], vh4[0], vh4[1]);
                mma16816(oacc[2 * g + 1], pah[kc], vh4[2], vh4[3]);
                mma16816(oacc[2 * g + 1], pah[kc], vl4[2], vl4[3]);
                mma16816(oacc[2 * g + 1], pal[kc], vh4[2], vh4[3]);
            }
        }

        __syncthreads();
        if (kt + 2 <= ktmax) {
            f_load_kv(KH, KL, VH, VL, sb + 2 * F_QT + (uint32_t)(kt & 1) * F_STG,
                      base, kt + 2, tid);
            CP_COMMIT();
        }
    }

    // ---- epilogue: normalize and write split C ----
    float inv0 = 1.f / l_[0], inv1 = 1.f / l_[1];
    int row0 = qt * 128 + wid * 16 + (lid >> 2);
#pragma unroll
    for (int ni = 0; ni < 8; ni++) {
        int col = ni * 8 + (lid & 3) * 2;
        float v0 = oacc[ni][0] * inv0, v1 = oacc[ni][1] * inv0;
        float v2 = oacc[ni][2] * inv1, v3 = oacc[ni][3] * inv1;
        __half2 h0 = __floats2half2_rn(v0, v1);
        __half2 l0 = __floats2half2_rn(v0 - __low2float(h0), v1 - __high2float(h0));
        __half2 h1 = __floats2half2_rn(v2, v3);
        __half2 l1 = __floats2half2_rn(v2 - __low2float(h1), v3 - __high2float(h1));
        size_t o0 = base + (size_t)row0 * D_ + col;
        size_t o1 = base + (size_t)(row0 + 8) * D_ + col;
        *(__half2*)&CH[o0] = h0;
        *(__half2*)&CL[o0] = l0;
        *(__half2*)&CH[o1] = h1;
        *(__half2*)&CL[o1] = l1;
    }
}

// ---------------------------------------------------------------------------
extern "C" void kernel_launch(void* const* d_in, const int* in_sizes, int n_in,
                              void* d_out, int out_size)
{
    const float* X  = (const float*)d_in[0];
    const float* Wq = (const float*)d_in[1];
    const float* Wk = (const float*)d_in[2];
    const float* Wv = (const float*)d_in[3];
    const float* Wo = (const float*)d_in[4];
    const float* bo = (const float*)d_in[5];
    float* Y = (float*)d_out;

    __half *gXH, *gXL, *gQH, *gQL, *gKH, *gKL, *gVH, *gVL, *gCH, *gCL, *gWT;
    cudaGetSymbolAddress((void**)&gXH, g_XH);
    cudaGetSymbolAddress((void**)&gXL, g_XL);
    cudaGetSymbolAddress((void**)&gQH, g_QH);
    cudaGetSymbolAddress((void**)&gQL, g_QL);
    cudaGetSymbolAddress((void**)&gKH, g_KH);
    cudaGetSymbolAddress((void**)&gKL, g_KL);
    cudaGetSymbolAddress((void**)&gVH, g_VH);
    cudaGetSymbolAddress((void**)&gVL, g_VL);
    cudaGetSymbolAddress((void**)&gCH, g_CH);
    cudaGetSymbolAddress((void**)&gCL, g_CL);
    cudaGetSymbolAddress((void**)&gWT, g_WT16);
    const size_t WSZ = (size_t)D_ * D_;

    cudaFuncSetAttribute(gemm16_kernel,
                         cudaFuncAttributeMaxDynamicSharedMemorySize, G_SMEM);
    cudaFuncSetAttribute(flash16_kernel,
                         cudaFuncAttributeMaxDynamicSharedMemorySize, F_SMEM);

    const int n4 = (M_ * D_) / 4;
    split16_kernel<<<(n4 + 255) / 256, 256>>>((const float4*)X,
                                              (uint2*)gXH, (uint2*)gXL, n4);
    dim3 tb(32, 8), tg(32, 32);
    transpose_split16_kernel<<<tg, tb>>>(Wq, gWT + 0 * WSZ, gWT + 1 * WSZ);
    transpose_split16_kernel<<<tg, tb>>>(Wk, gWT + 2 * WSZ, gWT + 3 * WSZ);
    transpose_split16_kernel<<<tg, tb>>>(Wv, gWT + 4 * WSZ, gWT + 5 * WSZ);
    transpose_split16_kernel<<<tg, tb>>>(Wo, gWT + 6 * WSZ, gWT + 7 * WSZ);

    dim3 gg(D_ / 128, M_ / 128);   // (8, 32) = 256 CTAs
    gemm16_kernel<<<gg, 256, G_SMEM>>>(gXH, gXL, gWT + 0 * WSZ, gWT + 1 * WSZ,
                                       nullptr, 0.125f, nullptr, gQH, gQL);
    gemm16_kernel<<<gg, 256, G_SMEM>>>(gXH, gXL, gWT + 2 * WSZ, gWT + 3 * WSZ,
                                       nullptr, 1.0f, nullptr, gKH, gKL);
    gemm16_kernel<<<gg, 256, G_SMEM>>>(gXH, gXL, gWT + 4 * WSZ, gWT + 5 * WSZ,
                                       nullptr, 1.0f, nullptr, gVH, gVL);

    flash16_kernel<<<dim3(T_ / 128, B_ * H_), 256, F_SMEM>>>(
        gQH, gQL, gKH, gKL, gVH, gVL, gCH, gCL);

    gemm16_kernel<<<gg, 256, G_SMEM>>>(gCH, gCL, gWT + 6 * WSZ, gWT + 7 * WSZ,
                                       bo, 1.0f, Y, nullptr, nullptr);
}

// round 8
// speedup vs baseline: 1.0189x; 1.0064x over previous
#include <cuda_runtime.h>
#include <cuda_fp16.h>
#include <math.h>
#include <stdint.h>

// Problem shape (fixed)
#define B_  2
#define T_  2048
#define D_  1024
#define H_  16
#define HD_ 64
#define M_  (B_*T_)   // 4096

// ---------------------------------------------------------------------------
// Scratch (__device__ globals; no allocations allowed)
// ---------------------------------------------------------------------------
__device__ __half g_XH[(size_t)M_ * D_];
__device__ __half g_XL[(size_t)M_ * D_];
__device__ __half g_QH[(size_t)M_ * D_];
__device__ __half g_QL[(size_t)M_ * D_];
__device__ __half g_KH[(size_t)M_ * D_];
__device__ __half g_KL[(size_t)M_ * D_];
__device__ __half g_VH[(size_t)M_ * D_];
__device__ __half g_VL[(size_t)M_ * D_];
__device__ __half g_CH[(size_t)M_ * D_];
__device__ __half g_CL[(size_t)M_ * D_];
// Transposed+split weights [N][K].
// Layout: [0]=WqH [1]=WkH [2]=WvH  (contiguous hi for fused QKV GEMM)
//         [3]=WqL [4]=WkL [5]=WvL  (contiguous lo)
//         [6]=WoH [7]=WoL
__device__ __half g_WT16[8][(size_t)D_ * D_];

// ---------------------------------------------------------------------------
// PTX helpers (sm_80-level features only)
// ---------------------------------------------------------------------------
__device__ __forceinline__ uint32_t smem_u32(const void* p) {
    uint32_t a;
    asm("{ .reg .u64 t; cvta.to.shared.u64 t, %1; cvt.u32.u64 %0, t; }"
        : "=r"(a) : "l"(p));
    return a;
}

__device__ __forceinline__ void cp_async16(uint32_t saddr, const void* gaddr) {
    asm volatile("cp.async.cg.shared.global [%0], [%1], 16;"
                 :: "r"(saddr), "l"(gaddr));
}
#define CP_COMMIT() asm volatile("cp.async.commit_group;" ::: "memory")
#define CP_WAIT(n)  asm volatile("cp.async.wait_group %0;" :: "n"(n) : "memory")

__device__ __forceinline__ void ldm4(uint32_t* r, uint32_t addr) {
    asm volatile("ldmatrix.sync.aligned.m8n8.x4.shared.b16 {%0,%1,%2,%3}, [%4];"
                 : "=r"(r[0]), "=r"(r[1]), "=r"(r[2]), "=r"(r[3]) : "r"(addr));
}

__device__ __forceinline__ void ldm4t(uint32_t* r, uint32_t addr) {
    asm volatile("ldmatrix.sync.aligned.m8n8.x4.trans.shared.b16 {%0,%1,%2,%3}, [%4];"
                 : "=r"(r[0]), "=r"(r[1]), "=r"(r[2]), "=r"(r[3]) : "r"(addr));
}

__device__ __forceinline__ void mma16816(float* d, const uint32_t* a,
                                         uint32_t b0, uint32_t b1) {
    asm volatile(
        "mma.sync.aligned.m16n8k16.row.col.f32.f16.f16.f32 "
        "{%0,%1,%2,%3},{%4,%5,%6,%7},{%8,%9},{%0,%1,%2,%3};"
        : "+f"(d[0]), "+f"(d[1]), "+f"(d[2]), "+f"(d[3])
        : "r"(a[0]), "r"(a[1]), "r"(a[2]), "r"(a[3]), "r"(b0), "r"(b1));
}

__device__ __forceinline__ uint32_t h2_bits(__half2 v) {
    return *(uint32_t*)&v;
}

// ---------------------------------------------------------------------------
// Prepass 1: fp32 -> (fp16 hi, fp16 lo) split
// ---------------------------------------------------------------------------
__global__ void split16_kernel(const float4* __restrict__ in,
                               uint2* __restrict__ hi, uint2* __restrict__ lo,
                               int n4) {
    int i = blockIdx.x * blockDim.x + threadIdx.x;
    if (i >= n4) return;
    float4 v = in[i];
    __half hx = __float2half_rn(v.x), hy = __float2half_rn(v.y);
    __half hz = __float2half_rn(v.z), hw = __float2half_rn(v.w);
    __half lx = __float2half_rn(v.x - __half2float(hx));
    __half ly = __float2half_rn(v.y - __half2float(hy));
    __half lz = __float2half_rn(v.z - __half2float(hz));
    __half lw = __float2half_rn(v.w - __half2float(hw));
    __half2 h0 = __halves2half2(hx, hy), h1 = __halves2half2(hz, hw);
    __half2 l0 = __halves2half2(lx, ly), l1 = __halves2half2(lz, lw);
    hi[i] = make_uint2(h2_bits(h0), h2_bits(h1));
    lo[i] = make_uint2(h2_bits(l0), h2_bits(l1));
}

// ---------------------------------------------------------------------------
// Prepass 2 (fused): all 4 weights transpose+split in one launch (z selects W)
// ---------------------------------------------------------------------------
__global__ void transpose_split16_all(const float* __restrict__ Wq,
                                      const float* __restrict__ Wk,
                                      const float* __restrict__ Wv,
                                      const float* __restrict__ Wo,
                                      __half* __restrict__ baseW) {
    __shared__ float t[32][33];
    const int z = blockIdx.z;
    const float* W = (z == 0) ? Wq : (z == 1) ? Wk : (z == 2) ? Wv : Wo;
    const size_t WSZ = (size_t)D_ * D_;
    __half* TH = baseW + ((z < 3) ? (size_t)z * WSZ : 6 * WSZ);
    __half* TL = baseW + ((z < 3) ? (size_t)(3 + z) * WSZ : 7 * WSZ);

    const int tx = threadIdx.x, ty = threadIdx.y;   // 32 x 8
    const int bn = blockIdx.x * 32;
    const int bk = blockIdx.y * 32;
#pragma unroll
    for (int i = 0; i < 4; i++)
        t[ty + 8 * i][tx] = W[(size_t)(bk + ty + 8 * i) * D_ + bn + tx];
    __syncthreads();
#pragma unroll
    for (int i = 0; i < 4; i++) {
        int row = ty + 8 * i;
        float v = t[tx][row];
        __half h = __float2half_rn(v);
        size_t o = (size_t)(bn + row) * D_ + bk + tx;
        TH[o] = h;
        TL[o] = __float2half_rn(v - __half2float(h));
    }
}

// ---------------------------------------------------------------------------
// mma.sync fp16 3-term GEMM (R5-verified tile config): CTA 128x128,
// 8 warps (2x4), warp tile 64x32, BK=32, 2-stage cp.async.
// QKV mode (outF==null): B rows span [0,3072) over concatenated Wq|Wk|Wv;
// each CTA's 128-col strip lies in exactly one matrix -> select out ptr+scale.
// Wo mode (outF!=null): fp32 output + bias.
// ---------------------------------------------------------------------------
#define G_TB     (128 * 80)
#define G_STAGE  (4 * G_TB)
#define G_SMEM   (2 * G_STAGE)       // 81920 B
#define G_NK     32
#define G_NCH    (D_ / G_NK)

__device__ __forceinline__ void g16_load(
    const __half* __restrict__ AH, const __half* __restrict__ AL,
    const __half* __restrict__ BH, const __half* __restrict__ BL,
    uint32_t sbase, int bm, int bn, int c, int tid)
{
    const int k0 = c * G_NK;
#pragma unroll
    for (int i = 0; i < 2; i++) {
        int idx = tid + (i << 8);
        int r = idx >> 2, ch = idx & 3;
        uint32_t so = (uint32_t)(r * 80 + ch * 16);
        size_t ga = (size_t)(bm + r) * D_ + k0 + ch * 8;
        size_t gb = (size_t)(bn + r) * D_ + k0 + ch * 8;
        cp_async16(sbase + so,            AH + ga);
        cp_async16(sbase + G_TB + so,     AL + ga);
        cp_async16(sbase + 2 * G_TB + so, BH + gb);
        cp_async16(sbase + 3 * G_TB + so, BL + gb);
    }
}

__global__ void __launch_bounds__(256, 1) gemm16_kernel(
    const __half* __restrict__ AH, const __half* __restrict__ AL,
    const __half* __restrict__ BH, const __half* __restrict__ BL,
    const float* __restrict__ bias,
    float* __restrict__ outF,
    __half* __restrict__ oQH, __half* __restrict__ oQL,
    __half* __restrict__ oKH, __half* __restrict__ oKL,
    __half* __restrict__ oVH, __half* __restrict__ oVL)
{
    extern __shared__ char smem[];
    const uint32_t sb = smem_u32(smem);
    const int tid = threadIdx.x;
    const int lid = tid & 31;
    const int wid = tid >> 5;
    const int wm  = wid >> 2;
    const int wn  = wid & 3;
    const int row16 = lid & 15;
    const int sel   = lid >> 4;
    const int bm = blockIdx.y << 7;
    const int bn = blockIdx.x << 7;

    float acc[4][4][4];
#pragma unroll
    for (int mi = 0; mi < 4; mi++)
#pragma unroll
        for (int ni = 0; ni < 4; ni++)
#pragma unroll
            for (int j = 0; j < 4; j++) acc[mi][ni][j] = 0.f;

    g16_load(AH, AL, BH, BL, sb, bm, bn, 0, tid);
    CP_COMMIT();
    g16_load(AH, AL, BH, BL, sb + G_STAGE, bm, bn, 1, tid);
    CP_COMMIT();

    for (int c = 0; c < G_NCH; c++) {
        if (c < G_NCH - 1) CP_WAIT(1); else CP_WAIT(0);
        __syncthreads();

        const uint32_t s = sb + (uint32_t)(c & 1) * G_STAGE;
#pragma unroll
        for (int kk = 0; kk < 2; kk++) {
            const uint32_t koff = (uint32_t)((kk * 2 + sel) * 16);
            uint32_t ah[4][4], al[4][4];
#pragma unroll
            for (int mi = 0; mi < 4; mi++) {
                uint32_t addr = s + (uint32_t)((wm * 64 + mi * 16 + row16) * 80) + koff;
                ldm4(ah[mi], addr);
                ldm4(al[mi], addr + G_TB);
            }
            uint32_t bh[2][4], bl[2][4];
#pragma unroll
            for (int g = 0; g < 2; g++) {
                uint32_t addr = s + 2 * G_TB +
                                (uint32_t)((wn * 32 + g * 16 + row16) * 80) + koff;
                ldm4(bh[g], addr);
                ldm4(bl[g], addr + G_TB);
            }
#pragma unroll
            for (int mi = 0; mi < 4; mi++)
#pragma unroll
                for (int ni = 0; ni < 4; ni++) {
                    const int g = ni >> 1, o = ni & 1;
                    mma16816(acc[mi][ni], ah[mi], bh[g][o], bh[g][o + 2]);
                    mma16816(acc[mi][ni], ah[mi], bl[g][o], bl[g][o + 2]);
                    mma16816(acc[mi][ni], al[mi], bh[g][o], bh[g][o + 2]);
                }
        }
        __syncthreads();
        if (c + 2 < G_NCH) {
            g16_load(AH, AL, BH, BL, sb + (uint32_t)(c & 1) * G_STAGE,
                     bm, bn, c + 2, tid);
            CP_COMMIT();
        }
    }

    // Epilogue
    const int mat = bn >> 10;           // which of Q/K/V (QKV mode)
    const int cb  = bn & 1023;          // column base within the matrix
    const float scl = (outF == nullptr && mat == 0) ? 0.125f : 1.0f;
    __half* oH = (mat == 0) ? oQH : (mat == 1) ? oKH : oVH;
    __half* oL = (mat == 0) ? oQL : (mat == 1) ? oKL : oVL;

#pragma unroll
    for (int mi = 0; mi < 4; mi++)
#pragma unroll
        for (int ni = 0; ni < 4; ni++) {
            int row = bm + wm * 64 + mi * 16 + (lid >> 2);
            int col = cb + wn * 32 + ni * 8 + (lid & 3) * 2;
            float v0 = acc[mi][ni][0] * scl, v1 = acc[mi][ni][1] * scl;
            float v2 = acc[mi][ni][2] * scl, v3 = acc[mi][ni][3] * scl;
            if (outF) {
                float b0 = bias ? bias[col] : 0.f, b1 = bias ? bias[col + 1] : 0.f;
                *(float2*)&outF[(size_t)row * D_ + col]       = make_float2(v0 + b0, v1 + b1);
                *(float2*)&outF[(size_t)(row + 8) * D_ + col] = make_float2(v2 + b0, v3 + b1);
            } else {
                __half2 h0 = __floats2half2_rn(v0, v1);
                __half2 l0 = __floats2half2_rn(v0 - __low2float(h0), v1 - __high2float(h0));
                __half2 h1 = __floats2half2_rn(v2, v3);
                __half2 l1 = __floats2half2_rn(v2 - __low2float(h1), v3 - __high2float(h1));
                *(__half2*)&oH[(size_t)row * D_ + col]       = h0;
                *(__half2*)&oL[(size_t)row * D_ + col]       = l0;
                *(__half2*)&oH[(size_t)(row + 8) * D_ + col] = h1;
                *(__half2*)&oL[(size_t)(row + 8) * D_ + col] = l1;
            }
        }
}

// ---------------------------------------------------------------------------
// Flash attention (R5-verified BM=64 config), with 2-term P·V
// (O += Ph·Vh + Ph·Vl; the Pl·Vh term is dropped — error ~1e-4 rel).
// Block: 64 q-rows, 4 warps x 16 rows, 128 threads. K-tiles of 64.
// ---------------------------------------------------------------------------
#define F_QTILE 9216                       // 64 * 144
#define F_STAGE (4 * F_QTILE)              // Kh, Kl, Vh, Vl
#define F_SMEM  (2 * F_QTILE + 2 * F_STAGE)  // 92160

__device__ __forceinline__ void f_load_kv(
    const __half* __restrict__ KH, const __half* __restrict__ KL,
    const __half* __restrict__ VH, const __half* __restrict__ VL,
    uint32_t sbase, size_t base, int kt, int tid)
{
#pragma unroll
    for (int i = 0; i < 16; i++) {
        const __half* src = (i < 4) ? KH : (i < 8) ? KL : (i < 12) ? VH : VL;
        int tile = i >> 2;
        int r = (tid >> 3) + (i & 3) * 16;
        uint32_t sa = sbase + (uint32_t)(tile * F_QTILE + r * 144 + (tid & 7) * 16);
        cp_async16(sa, src + base + (size_t)(kt * 64 + r) * D_ + (tid & 7) * 8);
    }
}

__global__ void __launch_bounds__(128) flash16_kernel(
    const __half* __restrict__ QH, const __half* __restrict__ QL,
    const __half* __restrict__ KH, const __half* __restrict__ KL,
    const __half* __restrict__ VH, const __half* __restrict__ VL,
    __half* __restrict__ CH, __half* __restrict__ CL)
{
    extern __shared__ char fsm[];
    const uint32_t sb = smem_u32(fsm);
    const int qt = blockIdx.x;
    const int bh = blockIdx.y;
    const int b = bh >> 4, h = bh & 15;
    const int tid = threadIdx.x, wid = tid >> 5, lid = tid & 31;
    const size_t base = ((size_t)b * T_) * D_ + (size_t)h * HD_;

    // Q tiles (hi, lo) -> smem
#pragma unroll
    for (int i = 0; i < 8; i++) {
        const __half* src = (i < 4) ? QH : QL;
        int r = (tid >> 3) + (i & 3) * 16;
        uint32_t sa = sb + (uint32_t)((i < 4 ? 0 : F_QTILE) + r * 144 + (tid & 7) * 16);
        cp_async16(sa, src + base + (size_t)(qt * 64 + r) * D_ + (tid & 7) * 8);
    }
    f_load_kv(KH, KL, VH, VL, sb + 2 * F_QTILE, base, 0, tid);
    CP_COMMIT();
    if (qt >= 1) {
        f_load_kv(KH, KL, VH, VL, sb + 2 * F_QTILE + F_STAGE, base, 1, tid);
        CP_COMMIT();
    }

    uint32_t qfh[4][4], qfl[4][4];
    float oacc[8][4];
    float m_[2] = {-INFINITY, -INFINITY}, l_[2] = {0.f, 0.f};
#pragma unroll
    for (int ni = 0; ni < 8; ni++)
#pragma unroll
        for (int j = 0; j < 4; j++) oacc[ni][j] = 0.f;

    for (int kt = 0; kt <= qt; kt++) {
        if (kt < qt) CP_WAIT(1); else CP_WAIT(0);
        __syncthreads();

        if (kt == 0) {
#pragma unroll
            for (int dc = 0; dc < 4; dc++) {
                uint32_t a = sb + (uint32_t)((wid * 16 + (lid & 15)) * 144
                             + dc * 32 + (lid >> 4) * 16);
                ldm4(qfh[dc], a);
                ldm4(qfl[dc], a + F_QTILE);
            }
        }

        const uint32_t ks = sb + 2 * F_QTILE + (uint32_t)(kt & 1) * F_STAGE;

        // ---- S = Q K^T (3-term) ----
        float sacc[8][4];
#pragma unroll
        for (int ni = 0; ni < 8; ni++)
#pragma unroll
            for (int j = 0; j < 4; j++) sacc[ni][j] = 0.f;

#pragma unroll
        for (int dc = 0; dc < 4; dc++) {
#pragma unroll
            for (int g = 0; g < 4; g++) {
                uint32_t ka = ks + (uint32_t)((g * 16 + (lid & 7) + ((lid >> 4) & 1) * 8) * 144
                              + dc * 32 + ((lid >> 3) & 1) * 16);
                uint32_t kh4[4], kl4[4];
                ldm4(kh4, ka);
                ldm4(kl4, ka + F_QTILE);
                mma16816(sacc[2 * g],     qfh[dc], kh4[0], kh4[1]);
                mma16816(sacc[2 * g],     qfh[dc], kl4[0], kl4[1]);
                mma16816(sacc[2 * g],     qfl[dc], kh4[0], kh4[1]);
                mma16816(sacc[2 * g + 1], qfh[dc], kh4[2], kh4[3]);
                mma16816(sacc[2 * g + 1], qfh[dc], kl4[2], kl4[3]);
                mma16816(sacc[2 * g + 1], qfl[dc], kh4[2], kh4[3]);
            }
        }

        // ---- causal mask (diagonal tile) ----
        if (kt == qt) {
            int r0 = wid * 16 + (lid >> 2);
#pragma unroll
            for (int ni = 0; ni < 8; ni++) {
                int c0 = ni * 8 + (lid & 3) * 2;
                if (c0     > r0)     sacc[ni][0] = -INFINITY;
                if (c0 + 1 > r0)     sacc[ni][1] = -INFINITY;
                if (c0     > r0 + 8) sacc[ni][2] = -INFINITY;
                if (c0 + 1 > r0 + 8) sacc[ni][3] = -INFINITY;
            }
        }

        // ---- online softmax ----
#pragma unroll
        for (int r = 0; r < 2; r++) {
            float mt = -INFINITY;
#pragma unroll
            for (int ni = 0; ni < 8; ni++)
                mt = fmaxf(mt, fmaxf(sacc[ni][2 * r], sacc[ni][2 * r + 1]));
            mt = fmaxf(mt, __shfl_xor_sync(0xffffffffu, mt, 1));
            mt = fmaxf(mt, __shfl_xor_sync(0xffffffffu, mt, 2));
            float mn = fmaxf(m_[r], mt);
            float sc = __expf(m_[r] - mn);
            float ps = 0.f;
#pragma unroll
            for (int ni = 0; ni < 8; ni++) {
                float p0 = __expf(sacc[ni][2 * r]     - mn);
                float p1 = __expf(sacc[ni][2 * r + 1] - mn);
                sacc[ni][2 * r] = p0; sacc[ni][2 * r + 1] = p1;
                ps += p0 + p1;
            }
            ps += __shfl_xor_sync(0xffffffffu, ps, 1);
            ps += __shfl_xor_sync(0xffffffffu, ps, 2);
            l_[r] = l_[r] * sc + ps;
            m_[r] = mn;
#pragma unroll
            for (int ni = 0; ni < 8; ni++) {
                oacc[ni][2 * r]     *= sc;
                oacc[ni][2 * r + 1] *= sc;
            }
        }

        // ---- pack P (hi only) into A-fragments ----
        uint32_t pah[4][4];
#pragma unroll
        for (int kc = 0; kc < 4; kc++) {
#pragma unroll
            for (int q = 0; q < 4; q++) {
                int ni = 2 * kc + (q >> 1);
                __half2 hp = __floats2half2_rn(sacc[ni][(q & 1) * 2],
                                               sacc[ni][(q & 1) * 2 + 1]);
                pah[kc][q] = h2_bits(hp);
            }
        }

        // ---- O += P V (2-term: Ph·Vh + Ph·Vl) ----
        const uint32_t vs = ks + 2 * F_QTILE;
#pragma unroll
        for (int kc = 0; kc < 4; kc++) {
#pragma unroll
            for (int g = 0; g < 4; g++) {
                uint32_t va = vs + (uint32_t)((kc * 16 + (lid & 7) + ((lid >> 3) & 1) * 8) * 144
                              + (g * 16 + ((lid >> 4) & 1) * 8) * 2);
                uint32_t vh4[4], vl4[4];
                ldm4t(vh4, va);
                ldm4t(vl4, va + F_QTILE);
                mma16816(oacc[2 * g],     pah[kc], vh4[0], vh4[1]);
                mma16816(oacc[2 * g],     pah[kc], vl4[0], vl4[1]);
                mma16816(oacc[2 * g + 1], pah[kc], vh4[2], vh4[3]);
                mma16816(oacc[2 * g + 1], pah[kc], vl4[2], vl4[3]);
            }
        }

        __syncthreads();
        if (kt + 2 <= qt) {
            f_load_kv(KH, KL, VH, VL, sb + 2 * F_QTILE + (uint32_t)(kt & 1) * F_STAGE,
                      base, kt + 2, tid);
            CP_COMMIT();
        }
    }

    // ---- epilogue: normalize and write split C ----
    float inv0 = 1.f / l_[0], inv1 = 1.f / l_[1];
    int row0 = qt * 64 + wid * 16 + (lid >> 2);
#pragma unroll
    for (int ni = 0; ni < 8; ni++) {
        int col = ni * 8 + (lid & 3) * 2;
        float v0 = oacc[ni][0] * inv0, v1 = oacc[ni][1] * inv0;
        float v2 = oacc[ni][2] * inv1, v3 = oacc[ni][3] * inv1;
        __half2 h0 = __floats2half2_rn(v0, v1);
        __half2 l0 = __floats2half2_rn(v0 - __low2float(h0), v1 - __high2float(h0));
        __half2 h1 = __floats2half2_rn(v2, v3);
        __half2 l1 = __floats2half2_rn(v2 - __low2float(h1), v3 - __high2float(h1));
        size_t o0 = base + (size_t)row0 * D_ + col;
        size_t o1 = base + (size_t)(row0 + 8) * D_ + col;
        *(__half2*)&CH[o0] = h0;
        *(__half2*)&CL[o0] = l0;
        *(__half2*)&CH[o1] = h1;
        *(__half2*)&CL[o1] = l1;
    }
}

// ---------------------------------------------------------------------------
extern "C" void kernel_launch(void* const* d_in, const int* in_sizes, int n_in,
                              void* d_out, int out_size)
{
    const float* X  = (const float*)d_in[0];
    const float* Wq = (const float*)d_in[1];
    const float* Wk = (const float*)d_in[2];
    const float* Wv = (const float*)d_in[3];
    const float* Wo = (const float*)d_in[4];
    const float* bo = (const float*)d_in[5];
    float* Y = (float*)d_out;

    __half *gXH, *gXL, *gQH, *gQL, *gKH, *gKL, *gVH, *gVL, *gCH, *gCL, *gWT;
    cudaGetSymbolAddress((void**)&gXH, g_XH);
    cudaGetSymbolAddress((void**)&gXL, g_XL);
    cudaGetSymbolAddress((void**)&gQH, g_QH);
    cudaGetSymbolAddress((void**)&gQL, g_QL);
    cudaGetSymbolAddress((void**)&gKH, g_KH);
    cudaGetSymbolAddress((void**)&gKL, g_KL);
    cudaGetSymbolAddress((void**)&gVH, g_VH);
    cudaGetSymbolAddress((void**)&gVL, g_VL);
    cudaGetSymbolAddress((void**)&gCH, g_CH);
    cudaGetSymbolAddress((void**)&gCL, g_CL);
    cudaGetSymbolAddress((void**)&gWT, g_WT16);
    const size_t WSZ = (size_t)D_ * D_;

    cudaFuncSetAttribute(gemm16_kernel,
                         cudaFuncAttributeMaxDynamicSharedMemorySize, G_SMEM);
    cudaFuncSetAttribute(flash16_kernel,
                         cudaFuncAttributeMaxDynamicSharedMemorySize, F_SMEM);

    const int n4 = (M_ * D_) / 4;
    split16_kernel<<<(n4 + 255) / 256, 256>>>((const float4*)X,
                                              (uint2*)gXH, (uint2*)gXL, n4);
    transpose_split16_all<<<dim3(32, 32, 4), dim3(32, 8)>>>(Wq, Wk, Wv, Wo, gWT);

    // Fused QKV projection: N=3072 over concatenated hi/lo weights.
    // Q (mat 0) carries the 1/sqrt(HD)=0.125 scale.
    gemm16_kernel<<<dim3(3 * D_ / 128, M_ / 128), 256, G_SMEM>>>(
        gXH, gXL, gWT + 0 * WSZ, gWT + 3 * WSZ,
        nullptr, nullptr, gQH, gQL, gKH, gKL, gVH, gVL);

    flash16_kernel<<<dim3(T_ / 64, B_ * H_), 128, F_SMEM>>>(
        gQH, gQL, gKH, gKL, gVH, gVL, gCH, gCL);

    // Output projection (fp32 out + bias)
    gemm16_kernel<<<dim3(D_ / 128, M_ / 128), 256, G_SMEM>>>(
        gCH, gCL, gWT + 6 * WSZ, gWT + 7 * WSZ,
        bo, Y, nullptr, nullptr, nullptr, nullptr, nullptr, nullptr);
}

// round 9
// speedup vs baseline: 1.0979x; 1.0776x over previous
#include <cuda_runtime.h>
#include <cuda_fp16.h>
#include <math.h>
#include <stdint.h>

// Problem shape (fixed)
#define B_  2
#define T_  2048
#define D_  1024
#define H_  16
#define HD_ 64
#define M_  (B_*T_)   // 4096

// ---------------------------------------------------------------------------
// Scratch (__device__ globals; no allocations allowed)
// ---------------------------------------------------------------------------
__device__ __half g_XH[(size_t)M_ * D_];
__device__ __half g_XL[(size_t)M_ * D_];
__device__ __half g_QH[(size_t)M_ * D_];
__device__ __half g_QL[(size_t)M_ * D_];
__device__ __half g_KH[(size_t)M_ * D_];
__device__ __half g_KL[(size_t)M_ * D_];
__device__ __half g_VH[(size_t)M_ * D_];
__device__ __half g_VL[(size_t)M_ * D_];
__device__ __half g_CH[(size_t)M_ * D_];
__device__ __half g_CL[(size_t)M_ * D_];
// Transposed+split weights [N][K]:
// [0]=WqH [1]=WkH [2]=WvH [3]=WqL [4]=WkL [5]=WvL [6]=WoH [7]=WoL
__device__ __half g_WT16[8][(size_t)D_ * D_];

// ---------------------------------------------------------------------------
// PTX helpers (sm_80-level features only)
// ---------------------------------------------------------------------------
__device__ __forceinline__ uint32_t smem_u32(const void* p) {
    uint32_t a;
    asm("{ .reg .u64 t; cvta.to.shared.u64 t, %1; cvt.u32.u64 %0, t; }"
        : "=r"(a) : "l"(p));
    return a;
}

__device__ __forceinline__ void cp_async16(uint32_t saddr, const void* gaddr) {
    asm volatile("cp.async.cg.shared.global [%0], [%1], 16;"
                 :: "r"(saddr), "l"(gaddr));
}
#define CP_COMMIT() asm volatile("cp.async.commit_group;" ::: "memory")
#define CP_WAIT(n)  asm volatile("cp.async.wait_group %0;" :: "n"(n) : "memory")

__device__ __forceinline__ void ldm4(uint32_t* r, uint32_t addr) {
    asm volatile("ldmatrix.sync.aligned.m8n8.x4.shared.b16 {%0,%1,%2,%3}, [%4];"
                 : "=r"(r[0]), "=r"(r[1]), "=r"(r[2]), "=r"(r[3]) : "r"(addr));
}

__device__ __forceinline__ void ldm4t(uint32_t* r, uint32_t addr) {
    asm volatile("ldmatrix.sync.aligned.m8n8.x4.trans.shared.b16 {%0,%1,%2,%3}, [%4];"
                 : "=r"(r[0]), "=r"(r[1]), "=r"(r[2]), "=r"(r[3]) : "r"(addr));
}

__device__ __forceinline__ void mma16816(float* d, const uint32_t* a,
                                         uint32_t b0, uint32_t b1) {
    asm volatile(
        "mma.sync.aligned.m16n8k16.row.col.f32.f16.f16.f32 "
        "{%0,%1,%2,%3},{%4,%5,%6,%7},{%8,%9},{%0,%1,%2,%3};"
        : "+f"(d[0]), "+f"(d[1]), "+f"(d[2]), "+f"(d[3])
        : "r"(a[0]), "r"(a[1]), "r"(a[2]), "r"(a[3]), "r"(b0), "r"(b1));
}

__device__ __forceinline__ uint32_t h2_bits(__half2 v) {
    return *(uint32_t*)&v;
}

// ---------------------------------------------------------------------------
// Prepass 1: fp32 -> (fp16 hi, fp16 lo) split
// ---------------------------------------------------------------------------
__global__ void split16_kernel(const float4* __restrict__ in,
                               uint2* __restrict__ hi, uint2* __restrict__ lo,
                               int n4) {
    int i = blockIdx.x * blockDim.x + threadIdx.x;
    if (i >= n4) return;
    float4 v = in[i];
    __half hx = __float2half_rn(v.x), hy = __float2half_rn(v.y);
    __half hz = __float2half_rn(v.z), hw = __float2half_rn(v.w);
    __half lx = __float2half_rn(v.x - __half2float(hx));
    __half ly = __float2half_rn(v.y - __half2float(hy));
    __half lz = __float2half_rn(v.z - __half2float(hz));
    __half lw = __float2half_rn(v.w - __half2float(hw));
    __half2 h0 = __halves2half2(hx, hy), h1 = __halves2half2(hz, hw);
    __half2 l0 = __halves2half2(lx, ly), l1 = __halves2half2(lz, lw);
    hi[i] = make_uint2(h2_bits(h0), h2_bits(h1));
    lo[i] = make_uint2(h2_bits(l0), h2_bits(l1));
}

// ---------------------------------------------------------------------------
// Prepass 2 (fused): all 4 weights transpose+split in one launch (z selects W)
// ---------------------------------------------------------------------------
__global__ void transpose_split16_all(const float* __restrict__ Wq,
                                      const float* __restrict__ Wk,
                                      const float* __restrict__ Wv,
                                      const float* __restrict__ Wo,
                                      __half* __restrict__ baseW) {
    __shared__ float t[32][33];
    const int z = blockIdx.z;
    const float* W = (z == 0) ? Wq : (z == 1) ? Wk : (z == 2) ? Wv : Wo;
    const size_t WSZ = (size_t)D_ * D_;
    __half* TH = baseW + ((z < 3) ? (size_t)z * WSZ : 6 * WSZ);
    __half* TL = baseW + ((z < 3) ? (size_t)(3 + z) * WSZ : 7 * WSZ);

    const int tx = threadIdx.x, ty = threadIdx.y;   // 32 x 8
    const int bn = blockIdx.x * 32;
    const int bk = blockIdx.y * 32;
#pragma unroll
    for (int i = 0; i < 4; i++)
        t[ty + 8 * i][tx] = W[(size_t)(bk + ty + 8 * i) * D_ + bn + tx];
    __syncthreads();
#pragma unroll
    for (int i = 0; i < 4; i++) {
        int row = ty + 8 * i;
        float v = t[tx][row];
        __half h = __float2half_rn(v);
        size_t o = (size_t)(bn + row) * D_ + bk + tx;
        TH[o] = h;
        TL[o] = __float2half_rn(v - __half2float(h));
    }
}

// ---------------------------------------------------------------------------
// mma.sync fp16 3-term GEMM (R5-verified config): CTA 128x128, 8 warps (2x4),
// warp tile 64x32, BK=32, 2-stage cp.async. Grid (8, 32) = 256 CTAs.
// ---------------------------------------------------------------------------
#define G_TB     (128 * 80)
#define G_STAGE  (4 * G_TB)
#define G_SMEM   (2 * G_STAGE)       // 81920 B
#define G_NK     32
#define G_NCH    (D_ / G_NK)

__device__ __forceinline__ void g16_load(
    const __half* __restrict__ AH, const __half* __restrict__ AL,
    const __half* __restrict__ BH, const __half* __restrict__ BL,
    uint32_t sbase, int bm, int bn, int c, int tid)
{
    const int k0 = c * G_NK;
#pragma unroll
    for (int i = 0; i < 2; i++) {
        int idx = tid + (i << 8);
        int r = idx >> 2, ch = idx & 3;
        uint32_t so = (uint32_t)(r * 80 + ch * 16);
        size_t ga = (size_t)(bm + r) * D_ + k0 + ch * 8;
        size_t gb = (size_t)(bn + r) * D_ + k0 + ch * 8;
        cp_async16(sbase + so,            AH + ga);
        cp_async16(sbase + G_TB + so,     AL + ga);
        cp_async16(sbase + 2 * G_TB + so, BH + gb);
        cp_async16(sbase + 3 * G_TB + so, BL + gb);
    }
}

__global__ void __launch_bounds__(256, 1) gemm16_kernel(
    const __half* __restrict__ AH, const __half* __restrict__ AL,
    const __half* __restrict__ BH, const __half* __restrict__ BL,
    const float* __restrict__ bias, float scale,
    float* __restrict__ outF,
    __half* __restrict__ outH, __half* __restrict__ outL)
{
    extern __shared__ char smem[];
    const uint32_t sb = smem_u32(smem);
    const int tid = threadIdx.x;
    const int lid = tid & 31;
    const int wid = tid >> 5;
    const int wm  = wid >> 2;
    const int wn  = wid & 3;
    const int row16 = lid & 15;
    const int sel   = lid >> 4;
    const int bm = blockIdx.y << 7;
    const int bn = blockIdx.x << 7;

    float acc[4][4][4];
#pragma unroll
    for (int mi = 0; mi < 4; mi++)
#pragma unroll
        for (int ni = 0; ni < 4; ni++)
#pragma unroll
            for (int j = 0; j < 4; j++) acc[mi][ni][j] = 0.f;

    g16_load(AH, AL, BH, BL, sb, bm, bn, 0, tid);
    CP_COMMIT();
    g16_load(AH, AL, BH, BL, sb + G_STAGE, bm, bn, 1, tid);
    CP_COMMIT();

    for (int c = 0; c < G_NCH; c++) {
        if (c < G_NCH - 1) CP_WAIT(1); else CP_WAIT(0);
        __syncthreads();

        const uint32_t s = sb + (uint32_t)(c & 1) * G_STAGE;
#pragma unroll
        for (int kk = 0; kk < 2; kk++) {
            const uint32_t koff = (uint32_t)((kk * 2 + sel) * 16);
            uint32_t ah[4][4], al[4][4];
#pragma unroll
            for (int mi = 0; mi < 4; mi++) {
                uint32_t addr = s + (uint32_t)((wm * 64 + mi * 16 + row16) * 80) + koff;
                ldm4(ah[mi], addr);
                ldm4(al[mi], addr + G_TB);
            }
            uint32_t bh[2][4], bl[2][4];
#pragma unroll
            for (int g = 0; g < 2; g++) {
                uint32_t addr = s + 2 * G_TB +
                                (uint32_t)((wn * 32 + g * 16 + row16) * 80) + koff;
                ldm4(bh[g], addr);
                ldm4(bl[g], addr + G_TB);
            }
#pragma unroll
            for (int mi = 0; mi < 4; mi++)
#pragma unroll
                for (int ni = 0; ni < 4; ni++) {
                    const int g = ni >> 1, o = ni & 1;
                    mma16816(acc[mi][ni], ah[mi], bh[g][o], bh[g][o + 2]);
                    mma16816(acc[mi][ni], ah[mi], bl[g][o], bl[g][o + 2]);
                    mma16816(acc[mi][ni], al[mi], bh[g][o], bh[g][o + 2]);
                }
        }
        __syncthreads();
        if (c + 2 < G_NCH) {
            g16_load(AH, AL, BH, BL, sb + (uint32_t)(c & 1) * G_STAGE,
                     bm, bn, c + 2, tid);
            CP_COMMIT();
        }
    }

#pragma unroll
    for (int mi = 0; mi < 4; mi++)
#pragma unroll
        for (int ni = 0; ni < 4; ni++) {
            int row = bm + wm * 64 + mi * 16 + (lid >> 2);
            int col = bn + wn * 32 + ni * 8 + (lid & 3) * 2;
            float v0 = acc[mi][ni][0] * scale, v1 = acc[mi][ni][1] * scale;
            float v2 = acc[mi][ni][2] * scale, v3 = acc[mi][ni][3] * scale;
            if (outF) {
                float b0 = bias ? bias[col] : 0.f, b1 = bias ? bias[col + 1] : 0.f;
                *(float2*)&outF[(size_t)row * D_ + col]       = make_float2(v0 + b0, v1 + b1);
                *(float2*)&outF[(size_t)(row + 8) * D_ + col] = make_float2(v2 + b0, v3 + b1);
            } else {
                __half2 h0 = __floats2half2_rn(v0, v1);
                __half2 l0 = __floats2half2_rn(v0 - __low2float(h0), v1 - __high2float(h0));
                __half2 h1 = __floats2half2_rn(v2, v3);
                __half2 l1 = __floats2half2_rn(v2 - __low2float(h1), v3 - __high2float(h1));
                *(__half2*)&outH[(size_t)row * D_ + col]       = h0;
                *(__half2*)&outL[(size_t)row * D_ + col]       = l0;
                *(__half2*)&outH[(size_t)(row + 8) * D_ + col] = h1;
                *(__half2*)&outL[(size_t)(row + 8) * D_ + col] = l1;
            }
        }
}

// ---------------------------------------------------------------------------
// Flash attention (R8-verified): BM=64, 4 warps, 3-term S, 2-term P·V.
// ---------------------------------------------------------------------------
#define F_QTILE 9216                       // 64 * 144
#define F_STAGE (4 * F_QTILE)              // Kh, Kl, Vh, Vl
#define F_SMEM  (2 * F_QTILE + 2 * F_STAGE)  // 92160

__device__ __forceinline__ void f_load_kv(
    const __half* __restrict__ KH, const __half* __restrict__ KL,
    const __half* __restrict__ VH, const __half* __restrict__ VL,
    uint32_t sbase, size_t base, int kt, int tid)
{
#pragma unroll
    for (int i = 0; i < 16; i++) {
        const __half* src = (i < 4) ? KH : (i < 8) ? KL : (i < 12) ? VH : VL;
        int tile = i >> 2;
        int r = (tid >> 3) + (i & 3) * 16;
        uint32_t sa = sbase + (uint32_t)(tile * F_QTILE + r * 144 + (tid & 7) * 16);
        cp_async16(sa, src + base + (size_t)(kt * 64 + r) * D_ + (tid & 7) * 8);
    }
}

__global__ void __launch_bounds__(128) flash16_kernel(
    const __half* __restrict__ QH, const __half* __restrict__ QL,
    const __half* __restrict__ KH, const __half* __restrict__ KL,
    const __half* __restrict__ VH, const __half* __restrict__ VL,
    __half* __restrict__ CH, __half* __restrict__ CL)
{
    extern __shared__ char fsm[];
    const uint32_t sb = smem_u32(fsm);
    const int qt = blockIdx.x;
    const int bh = blockIdx.y;
    const int b = bh >> 4, h = bh & 15;
    const int tid = threadIdx.x, wid = tid >> 5, lid = tid & 31;
    const size_t base = ((size_t)b * T_) * D_ + (size_t)h * HD_;

    // Q tiles (hi, lo) -> smem
#pragma unroll
    for (int i = 0; i < 8; i++) {
        const __half* src = (i < 4) ? QH : QL;
        int r = (tid >> 3) + (i & 3) * 16;
        uint32_t sa = sb + (uint32_t)((i < 4 ? 0 : F_QTILE) + r * 144 + (tid & 7) * 16);
        cp_async16(sa, src + base + (size_t)(qt * 64 + r) * D_ + (tid & 7) * 8);
    }
    f_load_kv(KH, KL, VH, VL, sb + 2 * F_QTILE, base, 0, tid);
    CP_COMMIT();
    if (qt >= 1) {
        f_load_kv(KH, KL, VH, VL, sb + 2 * F_QTILE + F_STAGE, base, 1, tid);
        CP_COMMIT();
    }

    uint32_t qfh[4][4], qfl[4][4];
    float oacc[8][4];
    float m_[2] = {-INFINITY, -INFINITY}, l_[2] = {0.f, 0.f};
#pragma unroll
    for (int ni = 0; ni < 8; ni++)
#pragma unroll
        for (int j = 0; j < 4; j++) oacc[ni][j] = 0.f;

    for (int kt = 0; kt <= qt; kt++) {
        if (kt < qt) CP_WAIT(1); else CP_WAIT(0);
        __syncthreads();

        if (kt == 0) {
#pragma unroll
            for (int dc = 0; dc < 4; dc++) {
                uint32_t a = sb + (uint32_t)((wid * 16 + (lid & 15)) * 144
                             + dc * 32 + (lid >> 4) * 16);
                ldm4(qfh[dc], a);
                ldm4(qfl[dc], a + F_QTILE);
            }
        }

        const uint32_t ks = sb + 2 * F_QTILE + (uint32_t)(kt & 1) * F_STAGE;

        // ---- S = Q K^T (3-term) ----
        float sacc[8][4];
#pragma unroll
        for (int ni = 0; ni < 8; ni++)
#pragma unroll
            for (int j = 0; j < 4; j++) sacc[ni][j] = 0.f;

#pragma unroll
        for (int dc = 0; dc < 4; dc++) {
#pragma unroll
            for (int g = 0; g < 4; g++) {
                uint32_t ka = ks + (uint32_t)((g * 16 + (lid & 7) + ((lid >> 4) & 1) * 8) * 144
                              + dc * 32 + ((lid >> 3) & 1) * 16);
                uint32_t kh4[4], kl4[4];
                ldm4(kh4, ka);
                ldm4(kl4, ka + F_QTILE);
                mma16816(sacc[2 * g],     qfh[dc], kh4[0], kh4[1]);
                mma16816(sacc[2 * g],     qfh[dc], kl4[0], kl4[1]);
                mma16816(sacc[2 * g],     qfl[dc], kh4[0], kh4[1]);
                mma16816(sacc[2 * g + 1], qfh[dc], kh4[2], kh4[3]);
                mma16816(sacc[2 * g + 1], qfh[dc], kl4[2], kl4[3]);
                mma16816(sacc[2 * g + 1], qfl[dc], kh4[2], kh4[3]);
            }
        }

        // ---- causal mask (diagonal tile) ----
        if (kt == qt) {
            int r0 = wid * 16 + (lid >> 2);
#pragma unroll
            for (int ni = 0; ni < 8; ni++) {
                int c0 = ni * 8 + (lid & 3) * 2;
                if (c0     > r0)     sacc[ni][0] = -INFINITY;
                if (c0 + 1 > r0)     sacc[ni][1] = -INFINITY;
                if (c0     > r0 + 8) sacc[ni][2] = -INFINITY;
                if (c0 + 1 > r0 + 8) sacc[ni][3] = -INFINITY;
            }
        }

        // ---- online softmax ----
#pragma unroll
        for (int r = 0; r < 2; r++) {
            float mt = -INFINITY;
#pragma unroll
            for (int ni = 0; ni < 8; ni++)
                mt = fmaxf(mt, fmaxf(sacc[ni][2 * r], sacc[ni][2 * r + 1]));
            mt = fmaxf(mt, __shfl_xor_sync(0xffffffffu, mt, 1));
            mt = fmaxf(mt, __shfl_xor_sync(0xffffffffu, mt, 2));
            float mn = fmaxf(m_[r], mt);
            float sc = __expf(m_[r] - mn);
            float ps = 0.f;
#pragma unroll
            for (int ni = 0; ni < 8; ni++) {
                float p0 = __expf(sacc[ni][2 * r]     - mn);
                float p1 = __expf(sacc[ni][2 * r + 1] - mn);
                sacc[ni][2 * r] = p0; sacc[ni][2 * r + 1] = p1;
                ps += p0 + p1;
            }
            ps += __shfl_xor_sync(0xffffffffu, ps, 1);
            ps += __shfl_xor_sync(0xffffffffu, ps, 2);
            l_[r] = l_[r] * sc + ps;
            m_[r] = mn;
#pragma unroll
            for (int ni = 0; ni < 8; ni++) {
                oacc[ni][2 * r]     *= sc;
                oacc[ni][2 * r + 1] *= sc;
            }
        }

        // ---- pack P (hi only) into A-fragments ----
        uint32_t pah[4][4];
#pragma unroll
        for (int kc = 0; kc < 4; kc++) {
#pragma unroll
            for (int q = 0; q < 4; q++) {
                int ni = 2 * kc + (q >> 1);
                __half2 hp = __floats2half2_rn(sacc[ni][(q & 1) * 2],
                                               sacc[ni][(q & 1) * 2 + 1]);
                pah[kc][q] = h2_bits(hp);
            }
        }

        // ---- O += P V (2-term: Ph·Vh + Ph·Vl) ----
        const uint32_t vs = ks + 2 * F_QTILE;
#pragma unroll
        for (int kc = 0; kc < 4; kc++) {
#pragma unroll
            for (int g = 0; g < 4; g++) {
                uint32_t va = vs + (uint32_t)((kc * 16 + (lid & 7) + ((lid >> 3) & 1) * 8) * 144
                              + (g * 16 + ((lid >> 4) & 1) * 8) * 2);
                uint32_t vh4[4], vl4[4];
                ldm4t(vh4, va);
                ldm4t(vl4, va + F_QTILE);
                mma16816(oacc[2 * g],     pah[kc], vh4[0], vh4[1]);
                mma16816(oacc[2 * g],     pah[kc], vl4[0], vl4[1]);
                mma16816(oacc[2 * g + 1], pah[kc], vh4[2], vh4[3]);
                mma16816(oacc[2 * g + 1], pah[kc], vl4[2], vl4[3]);
            }
        }

        __syncthreads();
        if (kt + 2 <= qt) {
            f_load_kv(KH, KL, VH, VL, sb + 2 * F_QTILE + (uint32_t)(kt & 1) * F_STAGE,
                      base, kt + 2, tid);
            CP_COMMIT();
        }
    }

    // ---- epilogue: normalize and write split C ----
    float inv0 = 1.f / l_[0], inv1 = 1.f / l_[1];
    int row0 = qt * 64 + wid * 16 + (lid >> 2);
#pragma unroll
    for (int ni = 0; ni < 8; ni++) {
        int col = ni * 8 + (lid & 3) * 2;
        float v0 = oacc[ni][0] * inv0, v1 = oacc[ni][1] * inv0;
        float v2 = oacc[ni][2] * inv1, v3 = oacc[ni][3] * inv1;
        __half2 h0 = __floats2half2_rn(v0, v1);
        __half2 l0 = __floats2half2_rn(v0 - __low2float(h0), v1 - __high2float(h0));
        __half2 h1 = __floats2half2_rn(v2, v3);
        __half2 l1 = __floats2half2_rn(v2 - __low2float(h1), v3 - __high2float(h1));
        size_t o0 = base + (size_t)row0 * D_ + col;
        size_t o1 = base + (size_t)(row0 + 8) * D_ + col;
        *(__half2*)&CH[o0] = h0;
        *(__half2*)&CL[o0] = l0;
        *(__half2*)&CH[o1] = h1;
        *(__half2*)&CL[o1] = l1;
    }
}

// ---------------------------------------------------------------------------
extern "C" void kernel_launch(void* const* d_in, const int* in_sizes, int n_in,
                              void* d_out, int out_size)
{
    const float* X  = (const float*)d_in[0];
    const float* Wq = (const float*)d_in[1];
    const float* Wk = (const float*)d_in[2];
    const float* Wv = (const float*)d_in[3];
    const float* Wo = (const float*)d_in[4];
    const float* bo = (const float*)d_in[5];
    float* Y = (float*)d_out;

    __half *gXH, *gXL, *gQH, *gQL, *gKH, *gKL, *gVH, *gVL, *gCH, *gCL, *gWT;
    cudaGetSymbolAddress((void**)&gXH, g_XH);
    cudaGetSymbolAddress((void**)&gXL, g_XL);
    cudaGetSymbolAddress((void**)&gQH, g_QH);
    cudaGetSymbolAddress((void**)&gQL, g_QL);
    cudaGetSymbolAddress((void**)&gKH, g_KH);
    cudaGetSymbolAddress((void**)&gKL, g_KL);
    cudaGetSymbolAddress((void**)&gVH, g_VH);
    cudaGetSymbolAddress((void**)&gVL, g_VL);
    cudaGetSymbolAddress((void**)&gCH, g_CH);
    cudaGetSymbolAddress((void**)&gCL, g_CL);
    cudaGetSymbolAddress((void**)&gWT, g_WT16);
    const size_t WSZ = (size_t)D_ * D_;

    cudaFuncSetAttribute(gemm16_kernel,
                         cudaFuncAttributeMaxDynamicSharedMemorySize, G_SMEM);
    cudaFuncSetAttribute(flash16_kernel,
                         cudaFuncAttributeMaxDynamicSharedMemorySize, F_SMEM);

    const int n4 = (M_ * D_) / 4;
    split16_kernel<<<(n4 + 255) / 256, 256>>>((const float4*)X,
                                              (uint2*)gXH, (uint2*)gXL, n4);
    transpose_split16_all<<<dim3(32, 32, 4), dim3(32, 8)>>>(Wq, Wk, Wv, Wo, gWT);

    dim3 gg(D_ / 128, M_ / 128);   // (8, 32) = 256 CTAs
    // Q projection carries the 1/sqrt(HD)=0.125 scale
    gemm16_kernel<<<gg, 256, G_SMEM>>>(gXH, gXL, gWT + 0 * WSZ, gWT + 3 * WSZ,
                                       nullptr, 0.125f, nullptr, gQH, gQL);
    gemm16_kernel<<<gg, 256, G_SMEM>>>(gXH, gXL, gWT + 1 * WSZ, gWT + 4 * WSZ,
                                       nullptr, 1.0f, nullptr, gKH, gKL);
    gemm16_kernel<<<gg, 256, G_SMEM>>>(gXH, gXL, gWT + 2 * WSZ, gWT + 5 * WSZ,
                                       nullptr, 1.0f, nullptr, gVH, gVL);

    flash16_kernel<<<dim3(T_ / 64, B_ * H_), 128, F_SMEM>>>(
        gQH, gQL, gKH, gKL, gVH, gVL, gCH, gCL);

    gemm16_kernel<<<gg, 256, G_SMEM>>>(gCH, gCL, gWT + 6 * WSZ, gWT + 7 * WSZ,
                                       bo, 1.0f, Y, nullptr, nullptr);
}

// round 10
// speedup vs baseline: 1.2129x; 1.1047x over previous
#include <cuda_runtime.h>
#include <cuda_fp16.h>
#include <math.h>
#include <stdint.h>

// Problem shape (fixed)
#define B_  2
#define T_  2048
#define D_  1024
#define H_  16
#define HD_ 64
#define M_  (B_*T_)   // 4096

// ---------------------------------------------------------------------------
// Scratch (__device__ globals; no allocations allowed)
// ---------------------------------------------------------------------------
__device__ __half g_XH[(size_t)M_ * D_];
__device__ __half g_XL[(size_t)M_ * D_];
__device__ __half g_QH[(size_t)M_ * D_];
__device__ __half g_QL[(size_t)M_ * D_];
__device__ __half g_KH[(size_t)M_ * D_];
__device__ __half g_KL[(size_t)M_ * D_];
__device__ __half g_VH[(size_t)M_ * D_];
__device__ __half g_VL[(size_t)M_ * D_];
__device__ __half g_CH[(size_t)M_ * D_];
// Transposed+split weights [N][K]:
// [0]=WqH [1]=WkH [2]=WvH [3]=WqL [4]=WkL [5]=WvL [6]=WoH [7]=WoL
__device__ __half g_WT16[8][(size_t)D_ * D_];

// ---------------------------------------------------------------------------
// PTX helpers (sm_80-level features only)
// ---------------------------------------------------------------------------
__device__ __forceinline__ uint32_t smem_u32(const void* p) {
    uint32_t a;
    asm("{ .reg .u64 t; cvta.to.shared.u64 t, %1; cvt.u32.u64 %0, t; }"
        : "=r"(a) : "l"(p));
    return a;
}

__device__ __forceinline__ void cp_async16(uint32_t saddr, const void* gaddr) {
    asm volatile("cp.async.cg.shared.global [%0], [%1], 16;"
                 :: "r"(saddr), "l"(gaddr));
}
#define CP_COMMIT() asm volatile("cp.async.commit_group;" ::: "memory")
#define CP_WAIT(n)  asm volatile("cp.async.wait_group %0;" :: "n"(n) : "memory")

__device__ __forceinline__ void ldm4(uint32_t* r, uint32_t addr) {
    asm volatile("ldmatrix.sync.aligned.m8n8.x4.shared.b16 {%0,%1,%2,%3}, [%4];"
                 : "=r"(r[0]), "=r"(r[1]), "=r"(r[2]), "=r"(r[3]) : "r"(addr));
}

__device__ __forceinline__ void ldm4t(uint32_t* r, uint32_t addr) {
    asm volatile("ldmatrix.sync.aligned.m8n8.x4.trans.shared.b16 {%0,%1,%2,%3}, [%4];"
                 : "=r"(r[0]), "=r"(r[1]), "=r"(r[2]), "=r"(r[3]) : "r"(addr));
}

__device__ __forceinline__ void mma16816(float* d, const uint32_t* a,
                                         uint32_t b0, uint32_t b1) {
    asm volatile(
        "mma.sync.aligned.m16n8k16.row.col.f32.f16.f16.f32 "
        "{%0,%1,%2,%3},{%4,%5,%6,%7},{%8,%9},{%0,%1,%2,%3};"
        : "+f"(d[0]), "+f"(d[1]), "+f"(d[2]), "+f"(d[3])
        : "r"(a[0]), "r"(a[1]), "r"(a[2]), "r"(a[3]), "r"(b0), "r"(b1));
}

__device__ __forceinline__ uint32_t h2_bits(__half2 v) {
    return *(uint32_t*)&v;
}

// ---------------------------------------------------------------------------
// Prepass 1: fp32 -> (fp16 hi, fp16 lo) split
// ---------------------------------------------------------------------------
__global__ void split16_kernel(const float4* __restrict__ in,
                               uint2* __restrict__ hi, uint2* __restrict__ lo,
                               int n4) {
    int i = blockIdx.x * blockDim.x + threadIdx.x;
    if (i >= n4) return;
    float4 v = in[i];
    __half hx = __float2half_rn(v.x), hy = __float2half_rn(v.y);
    __half hz = __float2half_rn(v.z), hw = __float2half_rn(v.w);
    __half lx = __float2half_rn(v.x - __half2float(hx));
    __half ly = __float2half_rn(v.y - __half2float(hy));
    __half lz = __float2half_rn(v.z - __half2float(hz));
    __half lw = __float2half_rn(v.w - __half2float(hw));
    __half2 h0 = __halves2half2(hx, hy), h1 = __halves2half2(hz, hw);
    __half2 l0 = __halves2half2(lx, ly), l1 = __halves2half2(lz, lw);
    hi[i] = make_uint2(h2_bits(h0), h2_bits(h1));
    lo[i] = make_uint2(h2_bits(l0), h2_bits(l1));
}

// ---------------------------------------------------------------------------
// Prepass 2 (fused): all 4 weights transpose+split in one launch (z selects W)
// ---------------------------------------------------------------------------
__global__ void transpose_split16_all(const float* __restrict__ Wq,
                                      const float* __restrict__ Wk,
                                      const float* __restrict__ Wv,
                                      const float* __restrict__ Wo,
                                      __half* __restrict__ baseW) {
    __shared__ float t[32][33];
    const int z = blockIdx.z;
    const float* W = (z == 0) ? Wq : (z == 1) ? Wk : (z == 2) ? Wv : Wo;
    const size_t WSZ = (size_t)D_ * D_;
    __half* TH = baseW + ((z < 3) ? (size_t)z * WSZ : 6 * WSZ);
    __half* TL = baseW + ((z < 3) ? (size_t)(3 + z) * WSZ : 7 * WSZ);

    const int tx = threadIdx.x, ty = threadIdx.y;   // 32 x 8
    const int bn = blockIdx.x * 32;
    const int bk = blockIdx.y * 32;
#pragma unroll
    for (int i = 0; i < 4; i++)
        t[ty + 8 * i][tx] = W[(size_t)(bk + ty + 8 * i) * D_ + bn + tx];
    __syncthreads();
#pragma unroll
    for (int i = 0; i < 4; i++) {
        int row = ty + 8 * i;
        float v = t[tx][row];
        __half h = __float2half_rn(v);
        size_t o = (size_t)(bn + row) * D_ + bk + tx;
        TH[o] = h;
        TL[o] = __float2half_rn(v - __half2float(h));
    }
}

// ---------------------------------------------------------------------------
// mma.sync fp16 split GEMM (TERMS=3: AhBh+AhBl+AlBh; TERMS=2: AhBh+AhBl).
// CTA 128x128, 8 warps (2x4), warp tile 64x32, BK=32, 2-stage cp.async.
// ---------------------------------------------------------------------------
#define G_TB     (128 * 80)
#define G_STAGE  (4 * G_TB)
#define G_SMEM   (2 * G_STAGE)       // 81920 B
#define G_NK     32
#define G_NCH    (D_ / G_NK)

template<int TERMS>
__device__ __forceinline__ void g16_load(
    const __half* __restrict__ AH, const __half* __restrict__ AL,
    const __half* __restrict__ BH, const __half* __restrict__ BL,
    uint32_t sbase, int bm, int bn, int c, int tid)
{
    const int k0 = c * G_NK;
#pragma unroll
    for (int i = 0; i < 2; i++) {
        int idx = tid + (i << 8);
        int r = idx >> 2, ch = idx & 3;
        uint32_t so = (uint32_t)(r * 80 + ch * 16);
        size_t ga = (size_t)(bm + r) * D_ + k0 + ch * 8;
        size_t gb = (size_t)(bn + r) * D_ + k0 + ch * 8;
        cp_async16(sbase + so,            AH + ga);
        if (TERMS == 3) cp_async16(sbase + G_TB + so, AL + ga);
        cp_async16(sbase + 2 * G_TB + so, BH + gb);
        cp_async16(sbase + 3 * G_TB + so, BL + gb);
    }
}

template<int TERMS>
__global__ void __launch_bounds__(256, 1) gemm16_kernel(
    const __half* __restrict__ AH, const __half* __restrict__ AL,
    const __half* __restrict__ BH, const __half* __restrict__ BL,
    const float* __restrict__ bias, float scale,
    float* __restrict__ outF,
    __half* __restrict__ outH, __half* __restrict__ outL)
{
    extern __shared__ char smem[];
    const uint32_t sb = smem_u32(smem);
    const int tid = threadIdx.x;
    const int lid = tid & 31;
    const int wid = tid >> 5;
    const int wm  = wid >> 2;
    const int wn  = wid & 3;
    const int row16 = lid & 15;
    const int sel   = lid >> 4;
    const int bm = blockIdx.y << 7;
    const int bn = blockIdx.x << 7;

    float acc[4][4][4];
#pragma unroll
    for (int mi = 0; mi < 4; mi++)
#pragma unroll
        for (int ni = 0; ni < 4; ni++)
#pragma unroll
            for (int j = 0; j < 4; j++) acc[mi][ni][j] = 0.f;

    g16_load<TERMS>(AH, AL, BH, BL, sb, bm, bn, 0, tid);
    CP_COMMIT();
    g16_load<TERMS>(AH, AL, BH, BL, sb + G_STAGE, bm, bn, 1, tid);
    CP_COMMIT();

    for (int c = 0; c < G_NCH; c++) {
        if (c < G_NCH - 1) CP_WAIT(1); else CP_WAIT(0);
        __syncthreads();

        const uint32_t s = sb + (uint32_t)(c & 1) * G_STAGE;
#pragma unroll
        for (int kk = 0; kk < 2; kk++) {
            const uint32_t koff = (uint32_t)((kk * 2 + sel) * 16);
            uint32_t ah[4][4], al[4][4];
#pragma unroll
            for (int mi = 0; mi < 4; mi++) {
                uint32_t addr = s + (uint32_t)((wm * 64 + mi * 16 + row16) * 80) + koff;
                ldm4(ah[mi], addr);
                if (TERMS == 3) ldm4(al[mi], addr + G_TB);
            }
            uint32_t bh[2][4], bl[2][4];
#pragma unroll
            for (int g = 0; g < 2; g++) {
                uint32_t addr = s + 2 * G_TB +
                                (uint32_t)((wn * 32 + g * 16 + row16) * 80) + koff;
                ldm4(bh[g], addr);
                ldm4(bl[g], addr + G_TB);
            }
#pragma unroll
            for (int mi = 0; mi < 4; mi++)
#pragma unroll
                for (int ni = 0; ni < 4; ni++) {
                    const int g = ni >> 1, o = ni & 1;
                    mma16816(acc[mi][ni], ah[mi], bh[g][o], bh[g][o + 2]);
                    mma16816(acc[mi][ni], ah[mi], bl[g][o], bl[g][o + 2]);
                    if (TERMS == 3)
                        mma16816(acc[mi][ni], al[mi], bh[g][o], bh[g][o + 2]);
                }
        }
        __syncthreads();
        if (c + 2 < G_NCH) {
            g16_load<TERMS>(AH, AL, BH, BL, sb + (uint32_t)(c & 1) * G_STAGE,
                            bm, bn, c + 2, tid);
            CP_COMMIT();
        }
    }

#pragma unroll
    for (int mi = 0; mi < 4; mi++)
#pragma unroll
        for (int ni = 0; ni < 4; ni++) {
            int row = bm + wm * 64 + mi * 16 + (lid >> 2);
            int col = bn + wn * 32 + ni * 8 + (lid & 3) * 2;
            float v0 = acc[mi][ni][0] * scale, v1 = acc[mi][ni][1] * scale;
            float v2 = acc[mi][ni][2] * scale, v3 = acc[mi][ni][3] * scale;
            if (outF) {
                float b0 = bias ? bias[col] : 0.f, b1 = bias ? bias[col + 1] : 0.f;
                *(float2*)&outF[(size_t)row * D_ + col]       = make_float2(v0 + b0, v1 + b1);
                *(float2*)&outF[(size_t)(row + 8) * D_ + col] = make_float2(v2 + b0, v3 + b1);
            } else {
                __half2 h0 = __floats2half2_rn(v0, v1);
                __half2 h1 = __floats2half2_rn(v2, v3);
                *(__half2*)&outH[(size_t)row * D_ + col]       = h0;
                *(__half2*)&outH[(size_t)(row + 8) * D_ + col] = h1;
                if (outL) {
                    __half2 l0 = __floats2half2_rn(v0 - __low2float(h0), v1 - __high2float(h0));
                    __half2 l1 = __floats2half2_rn(v2 - __low2float(h1), v3 - __high2float(h1));
                    *(__half2*)&outL[(size_t)row * D_ + col]       = l0;
                    *(__half2*)&outL[(size_t)(row + 8) * D_ + col] = l1;
                }
            }
        }
}

// ---------------------------------------------------------------------------
// Flash attention: BM=64, 4 warps, 3-term S, 2-term P·V, big q-tiles first.
// Output: CH only (fp16 hi; downstream Wo GEMM is 2-term).
// ---------------------------------------------------------------------------
#define F_QTILE 9216                       // 64 * 144
#define F_STAGE (4 * F_QTILE)              // Kh, Kl, Vh, Vl
#define F_SMEM  (2 * F_QTILE + 2 * F_STAGE)  // 92160

__device__ __forceinline__ void f_load_kv(
    const __half* __restrict__ KH, const __half* __restrict__ KL,
    const __half* __restrict__ VH, const __half* __restrict__ VL,
    uint32_t sbase, size_t base, int kt, int tid)
{
#pragma unroll
    for (int i = 0; i < 16; i++) {
        const __half* src = (i < 4) ? KH : (i < 8) ? KL : (i < 12) ? VH : VL;
        int tile = i >> 2;
        int r = (tid >> 3) + (i & 3) * 16;
        uint32_t sa = sbase + (uint32_t)(tile * F_QTILE + r * 144 + (tid & 7) * 16);
        cp_async16(sa, src + base + (size_t)(kt * 64 + r) * D_ + (tid & 7) * 8);
    }
}

__global__ void __launch_bounds__(128) flash16_kernel(
    const __half* __restrict__ QH, const __half* __restrict__ QL,
    const __half* __restrict__ KH, const __half* __restrict__ KL,
    const __half* __restrict__ VH, const __half* __restrict__ VL,
    __half* __restrict__ CH)
{
    extern __shared__ char fsm[];
    const uint32_t sb = smem_u32(fsm);
    const int qt = (int)gridDim.x - 1 - (int)blockIdx.x;   // big tiles first
    const int bh = blockIdx.y;
    const int b = bh >> 4, h = bh & 15;
    const int tid = threadIdx.x, wid = tid >> 5, lid = tid & 31;
    const size_t base = ((size_t)b * T_) * D_ + (size_t)h * HD_;

    // Q tiles (hi, lo) -> smem
#pragma unroll
    for (int i = 0; i < 8; i++) {
        const __half* src = (i < 4) ? QH : QL;
        int r = (tid >> 3) + (i & 3) * 16;
        uint32_t sa = sb + (uint32_t)((i < 4 ? 0 : F_QTILE) + r * 144 + (tid & 7) * 16);
        cp_async16(sa, src + base + (size_t)(qt * 64 + r) * D_ + (tid & 7) * 8);
    }
    f_load_kv(KH, KL, VH, VL, sb + 2 * F_QTILE, base, 0, tid);
    CP_COMMIT();
    if (qt >= 1) {
        f_load_kv(KH, KL, VH, VL, sb + 2 * F_QTILE + F_STAGE, base, 1, tid);
        CP_COMMIT();
    }

    uint32_t qfh[4][4], qfl[4][4];
    float oacc[8][4];
    float m_[2] = {-INFINITY, -INFINITY}, l_[2] = {0.f, 0.f};
#pragma unroll
    for (int ni = 0; ni < 8; ni++)
#pragma unroll
        for (int j = 0; j < 4; j++) oacc[ni][j] = 0.f;

    for (int kt = 0; kt <= qt; kt++) {
        if (kt < qt) CP_WAIT(1); else CP_WAIT(0);
        __syncthreads();

        if (kt == 0) {
#pragma unroll
            for (int dc = 0; dc < 4; dc++) {
                uint32_t a = sb + (uint32_t)((wid * 16 + (lid & 15)) * 144
                             + dc * 32 + (lid >> 4) * 16);
                ldm4(qfh[dc], a);
                ldm4(qfl[dc], a + F_QTILE);
            }
        }

        const uint32_t ks = sb + 2 * F_QTILE + (uint32_t)(kt & 1) * F_STAGE;

        // ---- S = Q K^T (3-term) ----
        float sacc[8][4];
#pragma unroll
        for (int ni = 0; ni < 8; ni++)
#pragma unroll
            for (int j = 0; j < 4; j++) sacc[ni][j] = 0.f;

#pragma unroll
        for (int dc = 0; dc < 4; dc++) {
#pragma unroll
            for (int g = 0; g < 4; g++) {
                uint32_t ka = ks + (uint32_t)((g * 16 + (lid & 7) + ((lid >> 4) & 1) * 8) * 144
                              + dc * 32 + ((lid >> 3) & 1) * 16);
                uint32_t kh4[4], kl4[4];
                ldm4(kh4, ka);
                ldm4(kl4, ka + F_QTILE);
                mma16816(sacc[2 * g],     qfh[dc], kh4[0], kh4[1]);
                mma16816(sacc[2 * g],     qfh[dc], kl4[0], kl4[1]);
                mma16816(sacc[2 * g],     qfl[dc], kh4[0], kh4[1]);
                mma16816(sacc[2 * g + 1], qfh[dc], kh4[2], kh4[3]);
                mma16816(sacc[2 * g + 1], qfh[dc], kl4[2], kl4[3]);
                mma16816(sacc[2 * g + 1], qfl[dc], kh4[2], kh4[3]);
            }
        }

        // ---- causal mask (diagonal tile) ----
        if (kt == qt) {
            int r0 = wid * 16 + (lid >> 2);
#pragma unroll
            for (int ni = 0; ni < 8; ni++) {
                int c0 = ni * 8 + (lid & 3) * 2;
                if (c0     > r0)     sacc[ni][0] = -INFINITY;
                if (c0 + 1 > r0)     sacc[ni][1] = -INFINITY;
                if (c0     > r0 + 8) sacc[ni][2] = -INFINITY;
                if (c0 + 1 > r0 + 8) sacc[ni][3] = -INFINITY;
            }
        }

        // ---- online softmax ----
#pragma unroll
        for (int r = 0; r < 2; r++) {
            float mt = -INFINITY;
#pragma unroll
            for (int ni = 0; ni < 8; ni++)
                mt = fmaxf(mt, fmaxf(sacc[ni][2 * r], sacc[ni][2 * r + 1]));
            mt = fmaxf(mt, __shfl_xor_sync(0xffffffffu, mt, 1));
            mt = fmaxf(mt, __shfl_xor_sync(0xffffffffu, mt, 2));
            float mn = fmaxf(m_[r], mt);
            float sc = __expf(m_[r] - mn);
            float ps = 0.f;
#pragma unroll
            for (int ni = 0; ni < 8; ni++) {
                float p0 = __expf(sacc[ni][2 * r]     - mn);
                float p1 = __expf(sacc[ni][2 * r + 1] - mn);
                sacc[ni][2 * r] = p0; sacc[ni][2 * r + 1] = p1;
                ps += p0 + p1;
            }
            ps += __shfl_xor_sync(0xffffffffu, ps, 1);
            ps += __shfl_xor_sync(0xffffffffu, ps, 2);
            l_[r] = l_[r] * sc + ps;
            m_[r] = mn;
#pragma unroll
            for (int ni = 0; ni < 8; ni++) {
                oacc[ni][2 * r]     *= sc;
                oacc[ni][2 * r + 1] *= sc;
            }
        }

        // ---- pack P (hi only) into A-fragments ----
        uint32_t pah[4][4];
#pragma unroll
        for (int kc = 0; kc < 4; kc++) {
#pragma unroll
            for (int q = 0; q < 4; q++) {
                int ni = 2 * kc + (q >> 1);
                __half2 hp = __floats2half2_rn(sacc[ni][(q & 1) * 2],
                                               sacc[ni][(q & 1) * 2 + 1]);
                pah[kc][q] = h2_bits(hp);
            }
        }

        // ---- O += P V (2-term: Ph·Vh + Ph·Vl) ----
        const uint32_t vs = ks + 2 * F_QTILE;
#pragma unroll
        for (int kc = 0; kc < 4; kc++) {
#pragma unroll
            for (int g = 0; g < 4; g++) {
                uint32_t va = vs + (uint32_t)((kc * 16 + (lid & 7) + ((lid >> 3) & 1) * 8) * 144
                              + (g * 16 + ((lid >> 4) & 1) * 8) * 2);
                uint32_t vh4[4], vl4[4];
                ldm4t(vh4, va);
                ldm4t(vl4, va + F_QTILE);
                mma16816(oacc[2 * g],     pah[kc], vh4[0], vh4[1]);
                mma16816(oacc[2 * g],     pah[kc], vl4[0], vl4[1]);
                mma16816(oacc[2 * g + 1], pah[kc], vh4[2], vh4[3]);
                mma16816(oacc[2 * g + 1], pah[kc], vl4[2], vl4[3]);
            }
        }

        __syncthreads();
        if (kt + 2 <= qt) {
            f_load_kv(KH, KL, VH, VL, sb + 2 * F_QTILE + (uint32_t)(kt & 1) * F_STAGE,
                      base, kt + 2, tid);
            CP_COMMIT();
        }
    }

    // ---- epilogue: normalize and write C (hi only) ----
    float inv0 = 1.f / l_[0], inv1 = 1.f / l_[1];
    int row0 = qt * 64 + wid * 16 + (lid >> 2);
#pragma unroll
    for (int ni = 0; ni < 8; ni++) {
        int col = ni * 8 + (lid & 3) * 2;
        __half2 h0 = __floats2half2_rn(oacc[ni][0] * inv0, oacc[ni][1] * inv0);
        __half2 h1 = __floats2half2_rn(oacc[ni][2] * inv1, oacc[ni][3] * inv1);
        *(__half2*)&CH[base + (size_t)row0 * D_ + col]       = h0;
        *(__half2*)&CH[base + (size_t)(row0 + 8) * D_ + col] = h1;
    }
}

// ---------------------------------------------------------------------------
extern "C" void kernel_launch(void* const* d_in, const int* in_sizes, int n_in,
                              void* d_out, int out_size)
{
    const float* X  = (const float*)d_in[0];
    const float* Wq = (const float*)d_in[1];
    const float* Wk = (const float*)d_in[2];
    const float* Wv = (const float*)d_in[3];
    const float* Wo = (const float*)d_in[4];
    const float* bo = (const float*)d_in[5];
    float* Y = (float*)d_out;

    __half *gXH, *gXL, *gQH, *gQL, *gKH, *gKL, *gVH, *gVL, *gCH, *gWT;
    cudaGetSymbolAddress((void**)&gXH, g_XH);
    cudaGetSymbolAddress((void**)&gXL, g_XL);
    cudaGetSymbolAddress((void**)&gQH, g_QH);
    cudaGetSymbolAddress((void**)&gQL, g_QL);
    cudaGetSymbolAddress((void**)&gKH, g_KH);
    cudaGetSymbolAddress((void**)&gKL, g_KL);
    cudaGetSymbolAddress((void**)&gVH, g_VH);
    cudaGetSymbolAddress((void**)&gVL, g_VL);
    cudaGetSymbolAddress((void**)&gCH, g_CH);
    cudaGetSymbolAddress((void**)&gWT, g_WT16);
    const size_t WSZ = (size_t)D_ * D_;

    cudaFuncSetAttribute(gemm16_kernel<3>,
                         cudaFuncAttributeMaxDynamicSharedMemorySize, G_SMEM);
    cudaFuncSetAttribute(gemm16_kernel<2>,
                         cudaFuncAttributeMaxDynamicSharedMemorySize, G_SMEM);
    cudaFuncSetAttribute(flash16_kernel,
                         cudaFuncAttributeMaxDynamicSharedMemorySize, F_SMEM);

    const int n4 = (M_ * D_) / 4;
    split16_kernel<<<(n4 + 255) / 256, 256>>>((const float4*)X,
                                              (uint2*)gXH, (uint2*)gXL, n4);
    transpose_split16_all<<<dim3(32, 32, 4), dim3(32, 8)>>>(Wq, Wk, Wv, Wo, gWT);

    dim3 gg(D_ / 128, M_ / 128);   // (8, 32) = 256 CTAs
    // Q projection carries the 1/sqrt(HD)=0.125 scale; Q/K 3-term (feed logits)
    gemm16_kernel<3><<<gg, 256, G_SMEM>>>(gXH, gXL, gWT + 0 * WSZ, gWT + 3 * WSZ,
                                          nullptr, 0.125f, nullptr, gQH, gQL);
    gemm16_kernel<3><<<gg, 256, G_SMEM>>>(gXH, gXL, gWT + 1 * WSZ, gWT + 4 * WSZ,
                                          nullptr, 1.0f, nullptr, gKH, gKL);
    // V projection 2-term (linear path): still emits (hi, lo) for the PV 2-term
    gemm16_kernel<2><<<gg, 256, G_SMEM>>>(gXH, gXL, gWT + 2 * WSZ, gWT + 5 * WSZ,
                                          nullptr, 1.0f, nullptr, gVH, gVL);

    flash16_kernel<<<dim3(T_ / 64, B_ * H_), 128, F_SMEM>>>(
        gQH, gQL, gKH, gKL, gVH, gVL, gCH);

    // Output projection 2-term (C in fp16-hi only), fp32 out + bias
    gemm16_kernel<2><<<gg, 256, G_SMEM>>>(gCH, nullptr, gWT + 6 * WSZ, gWT + 7 * WSZ,
                                          bo, 1.0f, Y, nullptr, nullptr);
}

// round 11
// speedup vs baseline: 1.4003x; 1.1545x over previous
#include <cuda_runtime.h>
#include <cuda_fp16.h>
#include <math.h>
#include <stdint.h>

// Problem shape (fixed)
#define B_  2
#define T_  2048
#define D_  1024
#define H_  16
#define HD_ 64
#define M_  (B_*T_)   // 4096

// ---------------------------------------------------------------------------
// Scratch (__device__ globals; no allocations allowed)
// Tiled layouts: 8KB blocks = 128 rows x 64B (32 halves), SW64-swizzled.
// Block index for element (m, k): (m>>7)*32 + (k>>5).
// ---------------------------------------------------------------------------
__device__ __half g_XH[(size_t)M_ * D_];   // tiled
__device__ __half g_XL[(size_t)M_ * D_];   // tiled
__device__ __half g_QH[(size_t)M_ * D_];   // row-major (flash consumes)
__device__ __half g_QL[(size_t)M_ * D_];
__device__ __half g_KH[(size_t)M_ * D_];
__device__ __half g_KL[(size_t)M_ * D_];
__device__ __half g_VH[(size_t)M_ * D_];
__device__ __half g_VL[(size_t)M_ * D_];
__device__ __half g_CH[(size_t)M_ * D_];   // tiled (Wo GEMM consumes)
// Transposed+split weights, tiled [n][k] blocks:
// [0]=WqH [1]=WkH [2]=WvH [3]=WqL [4]=WkL [5]=WvL [6]=WoH [7]=WoL
__device__ __half g_WT16[8][(size_t)D_ * D_];

// ---------------------------------------------------------------------------
// PTX helpers
// ---------------------------------------------------------------------------
__device__ __forceinline__ uint32_t smem_u32(const void* p) {
    uint32_t a;
    asm("{ .reg .u64 t; cvta.to.shared.u64 t, %1; cvt.u32.u64 %0, t; }"
        : "=r"(a) : "l"(p));
    return a;
}

__device__ __forceinline__ void cp_async16(uint32_t saddr, const void* gaddr) {
    asm volatile("cp.async.cg.shared.global [%0], [%1], 16;"
                 :: "r"(saddr), "l"(gaddr));
}
#define CP_COMMIT() asm volatile("cp.async.commit_group;" ::: "memory")
#define CP_WAIT(n)  asm volatile("cp.async.wait_group %0;" :: "n"(n) : "memory")

// Bulk async copy global->shared with mbarrier completion (sm_90 base feature)
__device__ __forceinline__ void bulk_g2s(uint32_t sdst, const void* gsrc,
                                         uint32_t bytes, uint32_t mbar) {
    asm volatile(
        "cp.async.bulk.shared::cluster.global.mbarrier::complete_tx::bytes "
        "[%0], [%1], %2, [%3];"
        :: "r"(sdst), "l"(gsrc), "r"(bytes), "r"(mbar) : "memory");
}

#define MBAR_INIT(addr, cnt) \
    asm volatile("mbarrier.init.shared.b64 [%0], %1;" :: "r"(addr), "r"(cnt) : "memory")
#define MBAR_EXPECT(addr, bytes) \
    asm volatile("mbarrier.arrive.expect_tx.shared.b64 _, [%0], %1;" \
                 :: "r"(addr), "r"(bytes) : "memory")
#define MBAR_WAIT(addr, par) do {                                                  \
    uint32_t _m = (uint32_t)(addr); uint32_t _p = (uint32_t)(par);                 \
    asm volatile("{\n\t.reg .pred P1;\n\t"                                         \
        "WL_%=:\n\t"                                                                \
        "mbarrier.try_wait.parity.acquire.cta.shared::cta.b64 P1, [%0], %1;\n\t"   \
        "@P1 bra.uni WD_%=;\n\t"                                                    \
        "bra.uni WL_%=;\n\t"                                                        \
        "WD_%=:\n\t}" :: "r"(_m), "r"(_p) : "memory");                              \
} while (0)

__device__ __forceinline__ void ldm4(uint32_t* r, uint32_t addr) {
    asm volatile("ldmatrix.sync.aligned.m8n8.x4.shared.b16 {%0,%1,%2,%3}, [%4];"
                 : "=r"(r[0]), "=r"(r[1]), "=r"(r[2]), "=r"(r[3]) : "r"(addr));
}

__device__ __forceinline__ void ldm4t(uint32_t* r, uint32_t addr) {
    asm volatile("ldmatrix.sync.aligned.m8n8.x4.trans.shared.b16 {%0,%1,%2,%3}, [%4];"
                 : "=r"(r[0]), "=r"(r[1]), "=r"(r[2]), "=r"(r[3]) : "r"(addr));
}

__device__ __forceinline__ void mma16816(float* d, const uint32_t* a,
                                         uint32_t b0, uint32_t b1) {
    asm volatile(
        "mma.sync.aligned.m16n8k16.row.col.f32.f16.f16.f32 "
        "{%0,%1,%2,%3},{%4,%5,%6,%7},{%8,%9},{%0,%1,%2,%3};"
        : "+f"(d[0]), "+f"(d[1]), "+f"(d[2]), "+f"(d[3])
        : "r"(a[0]), "r"(a[1]), "r"(a[2]), "r"(a[3]), "r"(b0), "r"(b1));
}

__device__ __forceinline__ uint32_t h2_bits(__half2 v) {
    return *(uint32_t*)&v;
}

// Tiled+swizzled half-offset for element (m-row, col) in a [*][1024] operand
__device__ __forceinline__ size_t tiled_off(int m, int col) {
    int blk = ((m >> 7) << 5) + (col >> 5);
    int r = m & 127, cb = col & 31;
    int chunk = (cb >> 3) ^ ((r >> 1) & 3);
    return (size_t)blk * 4096 + r * 32 + (chunk << 3) + (cb & 7);
}

// ---------------------------------------------------------------------------
// Prepass 1: fp32 -> (fp16 hi, lo), written TILED+swizzled
// ---------------------------------------------------------------------------
__global__ void split16_kernel(const float4* __restrict__ in,
                               __half* __restrict__ hi, __half* __restrict__ lo,
                               int n4) {
    int i = blockIdx.x * blockDim.x + threadIdx.x;
    if (i >= n4) return;
    float4 v = in[i];
    __half hx = __float2half_rn(v.x), hy = __float2half_rn(v.y);
    __half hz = __float2half_rn(v.z), hw = __float2half_rn(v.w);
    __half lx = __float2half_rn(v.x - __half2float(hx));
    __half ly = __float2half_rn(v.y - __half2float(hy));
    __half lz = __float2half_rn(v.z - __half2float(hz));
    __half lw = __float2half_rn(v.w - __half2float(hw));
    __half2 h0 = __halves2half2(hx, hy), h1 = __halves2half2(hz, hw);
    __half2 l0 = __halves2half2(lx, ly), l1 = __halves2half2(lz, lw);
    int e = i * 4;
    int m = e >> 10, col = e & 1023;
    size_t off = tiled_off(m, col);   // 8B-aligned (col % 4 == 0)
    *(uint2*)&hi[off] = make_uint2(h2_bits(h0), h2_bits(h1));
    *(uint2*)&lo[off] = make_uint2(h2_bits(l0), h2_bits(l1));
}

// ---------------------------------------------------------------------------
// Prepass 2: W[k][n] -> tiled WT_hi[n][k], WT_lo[n][k]
// ---------------------------------------------------------------------------
__global__ void transpose_split16_all(const float* __restrict__ Wq,
                                      const float* __restrict__ Wk,
                                      const float* __restrict__ Wv,
                                      const float* __restrict__ Wo,
                                      __half* __restrict__ baseW) {
    __shared__ float t[32][33];
    const int z = blockIdx.z;
    const float* W = (z == 0) ? Wq : (z == 1) ? Wk : (z == 2) ? Wv : Wo;
    const size_t WSZ = (size_t)D_ * D_;
    __half* TH = baseW + ((z < 3) ? (size_t)z * WSZ : 6 * WSZ);
    __half* TL = baseW + ((z < 3) ? (size_t)(3 + z) * WSZ : 7 * WSZ);

    const int tx = threadIdx.x, ty = threadIdx.y;   // 32 x 8
    const int bn = blockIdx.x * 32;
    const int bk = blockIdx.y * 32;
#pragma unroll
    for (int i = 0; i < 4; i++)
        t[ty + 8 * i][tx] = W[(size_t)(bk + ty + 8 * i) * D_ + bn + tx];
    __syncthreads();
#pragma unroll
    for (int i = 0; i < 4; i++) {
        int row = ty + 8 * i;
        float v = t[tx][row];           // = W[bk+tx][bn+row]
        __half h = __float2half_rn(v);
        size_t o = tiled_off(bn + row, bk + tx);
        TH[o] = h;
        TL[o] = __float2half_rn(v - __half2float(h));
    }
}

// ---------------------------------------------------------------------------
// Bulk-copy GEMM (TERMS=3: AhBh+AhBl+AlBh; TERMS=2: AhBh+AhBl).
// CTA 128x128, 8 warps (2x4), warp tile 64x32, BK=32.
// 3-stage ring, cp.async.bulk + mbarrier, one __syncthreads per chunk.
// Stage layout: [AH 0][AL 8K][BH 16K][BL 24K] (SW64-swizzled 8KB blocks).
// ---------------------------------------------------------------------------
#define G_BLK    8192
#define G_STGB   (4 * G_BLK)          // 32768 per stage
#define G_NSTG   3
#define G_SMEM   (G_NSTG * G_STGB + 64)
#define G_NCH    (D_ / 32)             // 32 chunks

template<int TERMS>
__global__ void __launch_bounds__(256, 1) gemm16_kernel(
    const __half* __restrict__ AH, const __half* __restrict__ AL,
    const __half* __restrict__ BH, const __half* __restrict__ BL,
    const float* __restrict__ bias, float scale,
    float* __restrict__ outF,
    __half* __restrict__ outH, __half* __restrict__ outL)
{
    extern __shared__ char smem[];
    const uint32_t sb  = smem_u32(smem);
    const uint32_t bar = sb + G_NSTG * G_STGB;
    const int tid = threadIdx.x;
    const int lid = tid & 31;
    const int wid = tid >> 5;
    const int wm  = wid >> 2;
    const int wn  = wid & 3;
    const int row16 = lid & 15;
    const int sel   = lid >> 4;
    const int bm = blockIdx.y << 7;
    const int bn = blockIdx.x << 7;
    const int aBlk = blockIdx.y << 5;   // (bm>>7)*32
    const int bBlk = blockIdx.x << 5;

    if (tid == 0) {
#pragma unroll
        for (int s = 0; s < G_NSTG; s++) MBAR_INIT(bar + s * 8, 1);
    }
    __syncthreads();

    const uint32_t BYTES = (TERMS == 3) ? (uint32_t)G_STGB : (uint32_t)(3 * G_BLK);
    auto issue = [&](int c, int s) {
        uint32_t mb = bar + s * 8;
        uint32_t sd = sb + (uint32_t)s * G_STGB;
        MBAR_EXPECT(mb, BYTES);
        bulk_g2s(sd,              (const char*)AH + (size_t)(aBlk + c) * G_BLK, G_BLK, mb);
        if (TERMS == 3)
            bulk_g2s(sd + G_BLK,  (const char*)AL + (size_t)(aBlk + c) * G_BLK, G_BLK, mb);
        bulk_g2s(sd + 2 * G_BLK,  (const char*)BH + (size_t)(bBlk + c) * G_BLK, G_BLK, mb);
        bulk_g2s(sd + 3 * G_BLK,  (const char*)BL + (size_t)(bBlk + c) * G_BLK, G_BLK, mb);
    };

    if (tid == 0) { issue(0, 0); issue(1, 1); }

    float acc[4][4][4];
#pragma unroll
    for (int mi = 0; mi < 4; mi++)
#pragma unroll
        for (int ni = 0; ni < 4; ni++)
#pragma unroll
            for (int j = 0; j < 4; j++) acc[mi][ni][j] = 0.f;

    for (int c = 0; c < G_NCH; c++) {
        const int s = c % G_NSTG;
        MBAR_WAIT(bar + s * 8, (c / G_NSTG) & 1);

        const uint32_t sA = sb + (uint32_t)s * G_STGB;
        const uint32_t sB = sA + 2 * G_BLK;
#pragma unroll
        for (int kk = 0; kk < 2; kk++) {
            const int ch = kk * 2 + sel;
            uint32_t ah[4][4], al[4][4];
#pragma unroll
            for (int mi = 0; mi < 4; mi++) {
                int r = wm * 64 + mi * 16 + row16;
                uint32_t addr = sA + (uint32_t)(r * 64 + ((ch ^ ((r >> 1) & 3)) << 4));
                ldm4(ah[mi], addr);
                if (TERMS == 3) ldm4(al[mi], addr + G_BLK);
            }
            uint32_t bh[2][4], bl[2][4];
#pragma unroll
            for (int g = 0; g < 2; g++) {
                int r = wn * 32 + g * 16 + row16;
                uint32_t addr = sB + (uint32_t)(r * 64 + ((ch ^ ((r >> 1) & 3)) << 4));
                ldm4(bh[g], addr);
                ldm4(bl[g], addr + G_BLK);
            }
#pragma unroll
            for (int mi = 0; mi < 4; mi++)
#pragma unroll
                for (int ni = 0; ni < 4; ni++) {
                    const int g = ni >> 1, o = ni & 1;
                    mma16816(acc[mi][ni], ah[mi], bh[g][o], bh[g][o + 2]);
                    mma16816(acc[mi][ni], ah[mi], bl[g][o], bl[g][o + 2]);
                    if (TERMS == 3)
                        mma16816(acc[mi][ni], al[mi], bh[g][o], bh[g][o + 2]);
                }
        }
        __syncthreads();
        if (c + 2 < G_NCH && tid == 0) issue(c + 2, (c + 2) % G_NSTG);
    }

#pragma unroll
    for (int mi = 0; mi < 4; mi++)
#pragma unroll
        for (int ni = 0; ni < 4; ni++) {
            int row = bm + wm * 64 + mi * 16 + (lid >> 2);
            int col = bn + wn * 32 + ni * 8 + (lid & 3) * 2;
            float v0 = acc[mi][ni][0] * scale, v1 = acc[mi][ni][1] * scale;
            float v2 = acc[mi][ni][2] * scale, v3 = acc[mi][ni][3] * scale;
            if (outF) {
                float b0 = bias ? bias[col] : 0.f, b1 = bias ? bias[col + 1] : 0.f;
                *(float2*)&outF[(size_t)row * D_ + col]       = make_float2(v0 + b0, v1 + b1);
                *(float2*)&outF[(size_t)(row + 8) * D_ + col] = make_float2(v2 + b0, v3 + b1);
            } else {
                __half2 h0 = __floats2half2_rn(v0, v1);
                __half2 h1 = __floats2half2_rn(v2, v3);
                *(__half2*)&outH[(size_t)row * D_ + col]       = h0;
                *(__half2*)&outH[(size_t)(row + 8) * D_ + col] = h1;
                if (outL) {
                    __half2 l0 = __floats2half2_rn(v0 - __low2float(h0), v1 - __high2float(h0));
                    __half2 l1 = __floats2half2_rn(v2 - __low2float(h1), v3 - __high2float(h1));
                    *(__half2*)&outL[(size_t)row * D_ + col]       = l0;
                    *(__half2*)&outL[(size_t)(row + 8) * D_ + col] = l1;
                }
            }
        }
}

// ---------------------------------------------------------------------------
// Flash attention (R10-verified mainloop): BM=64, 3-term S, 2-term PV,
// big q-tiles first. Epilogue writes CH in TILED layout (for the Wo GEMM).
// ---------------------------------------------------------------------------
#define F_QTILE 9216                       // 64 * 144
#define F_STAGE (4 * F_QTILE)
#define F_SMEM  (2 * F_QTILE + 2 * F_STAGE)  // 92160

__device__ __forceinline__ void f_load_kv(
    const __half* __restrict__ KH, const __half* __restrict__ KL,
    const __half* __restrict__ VH, const __half* __restrict__ VL,
    uint32_t sbase, size_t base, int kt, int tid)
{
#pragma unroll
    for (int i = 0; i < 16; i++) {
        const __half* src = (i < 4) ? KH : (i < 8) ? KL : (i < 12) ? VH : VL;
        int tile = i >> 2;
        int r = (tid >> 3) + (i & 3) * 16;
        uint32_t sa = sbase + (uint32_t)(tile * F_QTILE + r * 144 + (tid & 7) * 16);
        cp_async16(sa, src + base + (size_t)(kt * 64 + r) * D_ + (tid & 7) * 8);
    }
}

__global__ void __launch_bounds__(128) flash16_kernel(
    const __half* __restrict__ QH, const __half* __restrict__ QL,
    const __half* __restrict__ KH, const __half* __restrict__ KL,
    const __half* __restrict__ VH, const __half* __restrict__ VL,
    __half* __restrict__ CH)
{
    extern __shared__ char fsm[];
    const uint32_t sb = smem_u32(fsm);
    const int qt = (int)gridDim.x - 1 - (int)blockIdx.x;
    const int bh = blockIdx.y;
    const int b = bh >> 4, h = bh & 15;
    const int tid = threadIdx.x, wid = tid >> 5, lid = tid & 31;
    const size_t base = ((size_t)b * T_) * D_ + (size_t)h * HD_;

#pragma unroll
    for (int i = 0; i < 8; i++) {
        const __half* src = (i < 4) ? QH : QL;
        int r = (tid >> 3) + (i & 3) * 16;
        uint32_t sa = sb + (uint32_t)((i < 4 ? 0 : F_QTILE) + r * 144 + (tid & 7) * 16);
        cp_async16(sa, src + base + (size_t)(qt * 64 + r) * D_ + (tid & 7) * 8);
    }
    f_load_kv(KH, KL, VH, VL, sb + 2 * F_QTILE, base, 0, tid);
    CP_COMMIT();
    if (qt >= 1) {
        f_load_kv(KH, KL, VH, VL, sb + 2 * F_QTILE + F_STAGE, base, 1, tid);
        CP_COMMIT();
    }

    uint32_t qfh[4][4], qfl[4][4];
    float oacc[8][4];
    float m_[2] = {-INFINITY, -INFINITY}, l_[2] = {0.f, 0.f};
#pragma unroll
    for (int ni = 0; ni < 8; ni++)
#pragma unroll
        for (int j = 0; j < 4; j++) oacc[ni][j] = 0.f;

    for (int kt = 0; kt <= qt; kt++) {
        if (kt < qt) CP_WAIT(1); else CP_WAIT(0);
        __syncthreads();

        if (kt == 0) {
#pragma unroll
            for (int dc = 0; dc < 4; dc++) {
                uint32_t a = sb + (uint32_t)((wid * 16 + (lid & 15)) * 144
                             + dc * 32 + (lid >> 4) * 16);
                ldm4(qfh[dc], a);
                ldm4(qfl[dc], a + F_QTILE);
            }
        }

        const uint32_t ks = sb + 2 * F_QTILE + (uint32_t)(kt & 1) * F_STAGE;

        float sacc[8][4];
#pragma unroll
        for (int ni = 0; ni < 8; ni++)
#pragma unroll
            for (int j = 0; j < 4; j++) sacc[ni][j] = 0.f;

#pragma unroll
        for (int dc = 0; dc < 4; dc++) {
#pragma unroll
            for (int g = 0; g < 4; g++) {
                uint32_t ka = ks + (uint32_t)((g * 16 + (lid & 7) + ((lid >> 4) & 1) * 8) * 144
                              + dc * 32 + ((lid >> 3) & 1) * 16);
                uint32_t kh4[4], kl4[4];
                ldm4(kh4, ka);
                ldm4(kl4, ka + F_QTILE);
                mma16816(sacc[2 * g],     qfh[dc], kh4[0], kh4[1]);
                mma16816(sacc[2 * g],     qfh[dc], kl4[0], kl4[1]);
                mma16816(sacc[2 * g],     qfl[dc], kh4[0], kh4[1]);
                mma16816(sacc[2 * g + 1], qfh[dc], kh4[2], kh4[3]);
                mma16816(sacc[2 * g + 1], qfh[dc], kl4[2], kl4[3]);
                mma16816(sacc[2 * g + 1], qfl[dc], kh4[2], kh4[3]);
            }
        }

        if (kt == qt) {
            int r0 = wid * 16 + (lid >> 2);
#pragma unroll
            for (int ni = 0; ni < 8; ni++) {
                int c0 = ni * 8 + (lid & 3) * 2;
                if (c0     > r0)     sacc[ni][0] = -INFINITY;
                if (c0 + 1 > r0)     sacc[ni][1] = -INFINITY;
                if (c0     > r0 + 8) sacc[ni][2] = -INFINITY;
                if (c0 + 1 > r0 + 8) sacc[ni][3] = -INFINITY;
            }
        }

#pragma unroll
        for (int r = 0; r < 2; r++) {
            float mt = -INFINITY;
#pragma unroll
            for (int ni = 0; ni < 8; ni++)
                mt = fmaxf(mt, fmaxf(sacc[ni][2 * r], sacc[ni][2 * r + 1]));
            mt = fmaxf(mt, __shfl_xor_sync(0xffffffffu, mt, 1));
            mt = fmaxf(mt, __shfl_xor_sync(0xffffffffu, mt, 2));
            float mn = fmaxf(m_[r], mt);
            float sc = __expf(m_[r] - mn);
            float ps = 0.f;
#pragma unroll
            for (int ni = 0; ni < 8; ni++) {
                float p0 = __expf(sacc[ni][2 * r]     - mn);
                float p1 = __expf(sacc[ni][2 * r + 1] - mn);
                sacc[ni][2 * r] = p0; sacc[ni][2 * r + 1] = p1;
                ps += p0 + p1;
            }
            ps += __shfl_xor_sync(0xffffffffu, ps, 1);
            ps += __shfl_xor_sync(0xffffffffu, ps, 2);
            l_[r] = l_[r] * sc + ps;
            m_[r] = mn;
#pragma unroll
            for (int ni = 0; ni < 8; ni++) {
                oacc[ni][2 * r]     *= sc;
                oacc[ni][2 * r + 1] *= sc;
            }
        }

        uint32_t pah[4][4];
#pragma unroll
        for (int kc = 0; kc < 4; kc++) {
#pragma unroll
            for (int q = 0; q < 4; q++) {
                int ni = 2 * kc + (q >> 1);
                __half2 hp = __floats2half2_rn(sacc[ni][(q & 1) * 2],
                                               sacc[ni][(q & 1) * 2 + 1]);
                pah[kc][q] = h2_bits(hp);
            }
        }

        const uint32_t vs = ks + 2 * F_QTILE;
#pragma unroll
        for (int kc = 0; kc < 4; kc++) {
#pragma unroll
            for (int g = 0; g < 4; g++) {
                uint32_t va = vs + (uint32_t)((kc * 16 + (lid & 7) + ((lid >> 3) & 1) * 8) * 144
                              + (g * 16 + ((lid >> 4) & 1) * 8) * 2);
                uint32_t vh4[4], vl4[4];
                ldm4t(vh4, va);
                ldm4t(vl4, va + F_QTILE);
                mma16816(oacc[2 * g],     pah[kc], vh4[0], vh4[1]);
                mma16816(oacc[2 * g],     pah[kc], vl4[0], vl4[1]);
                mma16816(oacc[2 * g + 1], pah[kc], vh4[2], vh4[3]);
                mma16816(oacc[2 * g + 1], pah[kc], vl4[2], vl4[3]);
            }
        }

        __syncthreads();
        if (kt + 2 <= qt) {
            f_load_kv(KH, KL, VH, VL, sb + 2 * F_QTILE + (uint32_t)(kt & 1) * F_STAGE,
                      base, kt + 2, tid);
            CP_COMMIT();
        }
    }

    // epilogue: normalize, write CH in TILED layout
    float inv0 = 1.f / l_[0], inv1 = 1.f / l_[1];
    int m0 = b * T_ + qt * 64 + wid * 16 + (lid >> 2);
#pragma unroll
    for (int ni = 0; ni < 8; ni++) {
        int colD = h * HD_ + ni * 8 + (lid & 3) * 2;
        __half2 h0 = __floats2half2_rn(oacc[ni][0] * inv0, oacc[ni][1] * inv0);
        __half2 h1 = __floats2half2_rn(oacc[ni][2] * inv1, oacc[ni][3] * inv1);
        *(__half2*)&CH[tiled_off(m0,     colD)] = h0;
        *(__half2*)&CH[tiled_off(m0 + 8, colD)] = h1;
    }
}

// ---------------------------------------------------------------------------
extern "C" void kernel_launch(void* const* d_in, const int* in_sizes, int n_in,
                              void* d_out, int out_size)
{
    const float* X  = (const float*)d_in[0];
    const float* Wq = (const float*)d_in[1];
    const float* Wk = (const float*)d_in[2];
    const float* Wv = (const float*)d_in[3];
    const float* Wo = (const float*)d_in[4];
    const float* bo = (const float*)d_in[5];
    float* Y = (float*)d_out;

    __half *gXH, *gXL, *gQH, *gQL, *gKH, *gKL, *gVH, *gVL, *gCH, *gWT;
    cudaGetSymbolAddress((void**)&gXH, g_XH);
    cudaGetSymbolAddress((void**)&gXL, g_XL);
    cudaGetSymbolAddress((void**)&gQH, g_QH);
    cudaGetSymbolAddress((void**)&gQL, g_QL);
    cudaGetSymbolAddress((void**)&gKH, g_KH);
    cudaGetSymbolAddress((void**)&gKL, g_KL);
    cudaGetSymbolAddress((void**)&gVH, g_VH);
    cudaGetSymbolAddress((void**)&gVL, g_VL);
    cudaGetSymbolAddress((void**)&gCH, g_CH);
    cudaGetSymbolAddress((void**)&gWT, g_WT16);
    const size_t WSZ = (size_t)D_ * D_;

    cudaFuncSetAttribute(gemm16_kernel<3>,
                         cudaFuncAttributeMaxDynamicSharedMemorySize, G_SMEM);
    cudaFuncSetAttribute(gemm16_kernel<2>,
                         cudaFuncAttributeMaxDynamicSharedMemorySize, G_SMEM);
    cudaFuncSetAttribute(flash16_kernel,
                         cudaFuncAttributeMaxDynamicSharedMemorySize, F_SMEM);

    const int n4 = (M_ * D_) / 4;
    split16_kernel<<<(n4 + 255) / 256, 256>>>((const float4*)X, gXH, gXL, n4);
    transpose_split16_all<<<dim3(32, 32, 4), dim3(32, 8)>>>(Wq, Wk, Wv, Wo, gWT);

    dim3 gg(D_ / 128, M_ / 128);   // (8, 32) = 256 CTAs
    gemm16_kernel<3><<<gg, 256, G_SMEM>>>(gXH, gXL, gWT + 0 * WSZ, gWT + 3 * WSZ,
                                          nullptr, 0.125f, nullptr, gQH, gQL);
    gemm16_kernel<3><<<gg, 256, G_SMEM>>>(gXH, gXL, gWT + 1 * WSZ, gWT + 4 * WSZ,
                                          nullptr, 1.0f, nullptr, gKH, gKL);
    gemm16_kernel<2><<<gg, 256, G_SMEM>>>(gXH, gXL, gWT + 2 * WSZ, gWT + 5 * WSZ,
                                          nullptr, 1.0f, nullptr, gVH, gVL);

    flash16_kernel<<<dim3(T_ / 64, B_ * H_), 128, F_SMEM>>>(
        gQH, gQL, gKH, gKL, gVH, gVL, gCH);

    gemm16_kernel<2><<<gg, 256, G_SMEM>>>(gCH, nullptr, gWT + 6 * WSZ, gWT + 7 * WSZ,
                                          bo, 1.0f, Y, nullptr, nullptr);
}

// round 12
// speedup vs baseline: 1.4575x; 1.0409x over previous
#include <cuda_runtime.h>
#include <cuda_fp16.h>
#include <math.h>
#include <stdint.h>

// Problem shape (fixed)
#define B_  2
#define T_  2048
#define D_  1024
#define H_  16
#define HD_ 64
#define M_  (B_*T_)   // 4096

// ---------------------------------------------------------------------------
// Scratch (__device__ globals)
// GEMM-tiled: 8KB blocks = 128 rows x 32 halves, SW64 (g_XH/XL, g_CH, g_WT16)
// FLASH-tiled: per (b,h), 32 tiles of 64 tokens x 64 halves (8KB), SW128
//              (g_QH..g_VL)
// ---------------------------------------------------------------------------
__device__ __half g_XH[(size_t)M_ * D_];
__device__ __half g_XL[(size_t)M_ * D_];
__device__ __half g_QH[(size_t)M_ * D_];
__device__ __half g_QL[(size_t)M_ * D_];
__device__ __half g_KH[(size_t)M_ * D_];
__device__ __half g_KL[(size_t)M_ * D_];
__device__ __half g_VH[(size_t)M_ * D_];
__device__ __half g_VL[(size_t)M_ * D_];
__device__ __half g_CH[(size_t)M_ * D_];
// [0]=WqH [1]=WkH [2]=WvH [3]=WqL [4]=WkL [5]=WvL [6]=WoH [7]=WoL
__device__ __half g_WT16[8][(size_t)D_ * D_];

// ---------------------------------------------------------------------------
// PTX helpers
// ---------------------------------------------------------------------------
__device__ __forceinline__ uint32_t smem_u32(const void* p) {
    uint32_t a;
    asm("{ .reg .u64 t; cvta.to.shared.u64 t, %1; cvt.u32.u64 %0, t; }"
        : "=r"(a) : "l"(p));
    return a;
}

__device__ __forceinline__ void bulk_g2s(uint32_t sdst, const void* gsrc,
                                         uint32_t bytes, uint32_t mbar) {
    asm volatile(
        "cp.async.bulk.shared::cluster.global.mbarrier::complete_tx::bytes "
        "[%0], [%1], %2, [%3];"
        :: "r"(sdst), "l"(gsrc), "r"(bytes), "r"(mbar) : "memory");
}

#define MBAR_INIT(addr, cnt) \
    asm volatile("mbarrier.init.shared.b64 [%0], %1;" :: "r"(addr), "r"(cnt) : "memory")
#define MBAR_EXPECT(addr, bytes) \
    asm volatile("mbarrier.arrive.expect_tx.shared.b64 _, [%0], %1;" \
                 :: "r"(addr), "r"(bytes) : "memory")
#define MBAR_WAIT(addr, par) do {                                                  \
    uint32_t _m = (uint32_t)(addr); uint32_t _p = (uint32_t)(par);                 \
    asm volatile("{\n\t.reg .pred P1;\n\t"                                         \
        "WL_%=:\n\t"                                                                \
        "mbarrier.try_wait.parity.acquire.cta.shared::cta.b64 P1, [%0], %1;\n\t"   \
        "@P1 bra.uni WD_%=;\n\t"                                                    \
        "bra.uni WL_%=;\n\t"                                                        \
        "WD_%=:\n\t}" :: "r"(_m), "r"(_p) : "memory");                              \
} while (0)

__device__ __forceinline__ void ldm4(uint32_t* r, uint32_t addr) {
    asm volatile("ldmatrix.sync.aligned.m8n8.x4.shared.b16 {%0,%1,%2,%3}, [%4];"
                 : "=r"(r[0]), "=r"(r[1]), "=r"(r[2]), "=r"(r[3]) : "r"(addr));
}

__device__ __forceinline__ void ldm4t(uint32_t* r, uint32_t addr) {
    asm volatile("ldmatrix.sync.aligned.m8n8.x4.trans.shared.b16 {%0,%1,%2,%3}, [%4];"
                 : "=r"(r[0]), "=r"(r[1]), "=r"(r[2]), "=r"(r[3]) : "r"(addr));
}

__device__ __forceinline__ void mma16816(float* d, const uint32_t* a,
                                         uint32_t b0, uint32_t b1) {
    asm volatile(
        "mma.sync.aligned.m16n8k16.row.col.f32.f16.f16.f32 "
        "{%0,%1,%2,%3},{%4,%5,%6,%7},{%8,%9},{%0,%1,%2,%3};"
        : "+f"(d[0]), "+f"(d[1]), "+f"(d[2]), "+f"(d[3])
        : "r"(a[0]), "r"(a[1]), "r"(a[2]), "r"(a[3]), "r"(b0), "r"(b1));
}

__device__ __forceinline__ uint32_t h2_bits(__half2 v) {
    return *(uint32_t*)&v;
}

// GEMM-tiled offset (128-row x 32-col blocks, SW64)
__device__ __forceinline__ size_t tiled_off(int m, int col) {
    int blk = ((m >> 7) << 5) + (col >> 5);
    int r = m & 127, cb = col & 31;
    int chunk = (cb >> 3) ^ ((r >> 1) & 3);
    return (size_t)blk * 4096 + r * 32 + (chunk << 3) + (cb & 7);
}

// FLASH-tiled offset: m in [0,4096), n = h*64 + d. 64x64 tiles, SW128.
__device__ __forceinline__ size_t flash_off(int m, int n) {
    int b = m >> 11, t = m & 2047;
    int h = n >> 6, d = n & 63;
    size_t tb = ((size_t)(((b << 4) + h) * 32 + (t >> 6))) << 12;
    int r = t & 63;
    return tb + r * 64 + ((((d >> 3) ^ (r & 7)) << 3)) + (d & 7);
}

// ---------------------------------------------------------------------------
// Prepass 1: fp32 -> (fp16 hi, lo), GEMM-tiled
// ---------------------------------------------------------------------------
__global__ void split16_kernel(const float4* __restrict__ in,
                               __half* __restrict__ hi, __half* __restrict__ lo,
                               int n4) {
    int i = blockIdx.x * blockDim.x + threadIdx.x;
    if (i >= n4) return;
    float4 v = in[i];
    __half hx = __float2half_rn(v.x), hy = __float2half_rn(v.y);
    __half hz = __float2half_rn(v.z), hw = __float2half_rn(v.w);
    __half lx = __float2half_rn(v.x - __half2float(hx));
    __half ly = __float2half_rn(v.y - __half2float(hy));
    __half lz = __float2half_rn(v.z - __half2float(hz));
    __half lw = __float2half_rn(v.w - __half2float(hw));
    __half2 h0 = __halves2half2(hx, hy), h1 = __halves2half2(hz, hw);
    __half2 l0 = __halves2half2(lx, ly), l1 = __halves2half2(lz, lw);
    int e = i * 4;
    int m = e >> 10, col = e & 1023;
    size_t off = tiled_off(m, col);
    *(uint2*)&hi[off] = make_uint2(h2_bits(h0), h2_bits(h1));
    *(uint2*)&lo[off] = make_uint2(h2_bits(l0), h2_bits(l1));
}

// ---------------------------------------------------------------------------
// Prepass 2: W[k][n] -> GEMM-tiled WT_hi[n][k], WT_lo[n][k]
// ---------------------------------------------------------------------------
__global__ void transpose_split16_all(const float* __restrict__ Wq,
                                      const float* __restrict__ Wk,
                                      const float* __restrict__ Wv,
                                      const float* __restrict__ Wo,
                                      __half* __restrict__ baseW) {
    __shared__ float t[32][33];
    const int z = blockIdx.z;
    const float* W = (z == 0) ? Wq : (z == 1) ? Wk : (z == 2) ? Wv : Wo;
    const size_t WSZ = (size_t)D_ * D_;
    __half* TH = baseW + ((z < 3) ? (size_t)z * WSZ : 6 * WSZ);
    __half* TL = baseW + ((z < 3) ? (size_t)(3 + z) * WSZ : 7 * WSZ);

    const int tx = threadIdx.x, ty = threadIdx.y;   // 32 x 8
    const int bn = blockIdx.x * 32;
    const int bk = blockIdx.y * 32;
#pragma unroll
    for (int i = 0; i < 4; i++)
        t[ty + 8 * i][tx] = W[(size_t)(bk + ty + 8 * i) * D_ + bn + tx];
    __syncthreads();
#pragma unroll
    for (int i = 0; i < 4; i++) {
        int row = ty + 8 * i;
        float v = t[tx][row];
        __half h = __float2half_rn(v);
        size_t o = tiled_off(bn + row, bk + tx);
        TH[o] = h;
        TL[o] = __float2half_rn(v - __half2float(h));
    }
}

// ---------------------------------------------------------------------------
// Bulk-copy GEMM. FOUT: 0 = fp32 row-major (+bias), 1 = flash-tiled fp16 (hi,lo)
// ---------------------------------------------------------------------------
#define G_BLK    8192
#define G_STGB   (4 * G_BLK)
#define G_NSTG   3
#define G_SMEM   (G_NSTG * G_STGB + 64)
#define G_NCH    (D_ / 32)

template<int TERMS, int FOUT>
__global__ void __launch_bounds__(256, 1) gemm16_kernel(
    const __half* __restrict__ AH, const __half* __restrict__ AL,
    const __half* __restrict__ BH, const __half* __restrict__ BL,
    const float* __restrict__ bias, float scale,
    float* __restrict__ outF,
    __half* __restrict__ outH, __half* __restrict__ outL)
{
    extern __shared__ char smem[];
    const uint32_t sb  = smem_u32(smem);
    const uint32_t bar = sb + G_NSTG * G_STGB;
    const int tid = threadIdx.x;
    const int lid = tid & 31;
    const int wid = tid >> 5;
    const int wm  = wid >> 2;
    const int wn  = wid & 3;
    const int row16 = lid & 15;
    const int sel   = lid >> 4;
    const int bm = blockIdx.y << 7;
    const int bn = blockIdx.x << 7;
    const int aBlk = blockIdx.y << 5;
    const int bBlk = blockIdx.x << 5;

    if (tid == 0) {
#pragma unroll
        for (int s = 0; s < G_NSTG; s++) MBAR_INIT(bar + s * 8, 1);
    }
    __syncthreads();

    const uint32_t BYTES = (TERMS == 3) ? (uint32_t)G_STGB : (uint32_t)(3 * G_BLK);
    auto issue = [&](int c, int s) {
        uint32_t mb = bar + s * 8;
        uint32_t sd = sb + (uint32_t)s * G_STGB;
        MBAR_EXPECT(mb, BYTES);
        bulk_g2s(sd,              (const char*)AH + (size_t)(aBlk + c) * G_BLK, G_BLK, mb);
        if (TERMS == 3)
            bulk_g2s(sd + G_BLK,  (const char*)AL + (size_t)(aBlk + c) * G_BLK, G_BLK, mb);
        bulk_g2s(sd + 2 * G_BLK,  (const char*)BH + (size_t)(bBlk + c) * G_BLK, G_BLK, mb);
        bulk_g2s(sd + 3 * G_BLK,  (const char*)BL + (size_t)(bBlk + c) * G_BLK, G_BLK, mb);
    };

    if (tid == 0) { issue(0, 0); issue(1, 1); }

    float acc[4][4][4];
#pragma unroll
    for (int mi = 0; mi < 4; mi++)
#pragma unroll
        for (int ni = 0; ni < 4; ni++)
#pragma unroll
            for (int j = 0; j < 4; j++) acc[mi][ni][j] = 0.f;

    for (int c = 0; c < G_NCH; c++) {
        const int s = c % G_NSTG;
        MBAR_WAIT(bar + s * 8, (c / G_NSTG) & 1);

        const uint32_t sA = sb + (uint32_t)s * G_STGB;
        const uint32_t sB = sA + 2 * G_BLK;
#pragma unroll
        for (int kk = 0; kk < 2; kk++) {
            const int ch = kk * 2 + sel;
            uint32_t ah[4][4], al[4][4];
#pragma unroll
            for (int mi = 0; mi < 4; mi++) {
                int r = wm * 64 + mi * 16 + row16;
                uint32_t addr = sA + (uint32_t)(r * 64 + ((ch ^ ((r >> 1) & 3)) << 4));
                ldm4(ah[mi], addr);
                if (TERMS == 3) ldm4(al[mi], addr + G_BLK);
            }
            uint32_t bh[2][4], bl[2][4];
#pragma unroll
            for (int g = 0; g < 2; g++) {
                int r = wn * 32 + g * 16 + row16;
                uint32_t addr = sB + (uint32_t)(r * 64 + ((ch ^ ((r >> 1) & 3)) << 4));
                ldm4(bh[g], addr);
                ldm4(bl[g], addr + G_BLK);
            }
#pragma unroll
            for (int mi = 0; mi < 4; mi++)
#pragma unroll
                for (int ni = 0; ni < 4; ni++) {
                    const int g = ni >> 1, o = ni & 1;
                    mma16816(acc[mi][ni], ah[mi], bh[g][o], bh[g][o + 2]);
                    mma16816(acc[mi][ni], ah[mi], bl[g][o], bl[g][o + 2]);
                    if (TERMS == 3)
                        mma16816(acc[mi][ni], al[mi], bh[g][o], bh[g][o + 2]);
                }
        }
        __syncthreads();
        if (c + 2 < G_NCH && tid == 0) issue(c + 2, (c + 2) % G_NSTG);
    }

#pragma unroll
    for (int mi = 0; mi < 4; mi++)
#pragma unroll
        for (int ni = 0; ni < 4; ni++) {
            int row = bm + wm * 64 + mi * 16 + (lid >> 2);
            int col = bn + wn * 32 + ni * 8 + (lid & 3) * 2;
            float v0 = acc[mi][ni][0] * scale, v1 = acc[mi][ni][1] * scale;
            float v2 = acc[mi][ni][2] * scale, v3 = acc[mi][ni][3] * scale;
            if (FOUT == 0) {
                float b0 = bias ? bias[col] : 0.f, b1 = bias ? bias[col + 1] : 0.f;
                *(float2*)&outF[(size_t)row * D_ + col]       = make_float2(v0 + b0, v1 + b1);
                *(float2*)&outF[(size_t)(row + 8) * D_ + col] = make_float2(v2 + b0, v3 + b1);
            } else {
                __half2 h0 = __floats2half2_rn(v0, v1);
                __half2 h1 = __floats2half2_rn(v2, v3);
                size_t o0 = flash_off(row, col);
                size_t o1 = flash_off(row + 8, col);
                *(__half2*)&outH[o0] = h0;
                *(__half2*)&outH[o1] = h1;
                if (outL) {
                    __half2 l0 = __floats2half2_rn(v0 - __low2float(h0), v1 - __high2float(h0));
                    __half2 l1 = __floats2half2_rn(v2 - __low2float(h1), v3 - __high2float(h1));
                    *(__half2*)&outL[o0] = l0;
                    *(__half2*)&outL[o1] = l1;
                }
            }
        }
}

// ---------------------------------------------------------------------------
// Flash attention: BM=64, 3-term S, 2-term PV, big-first; bulk-copy K/V.
// Smem: [QH 8K][QL 8K][stage0 KH/KL/VH/VL 32K][stage1 32K][bars]
// Tiles SW128-swizzled: addr(r, gran) = base + r*128 + ((gran ^ (r&7))<<4).
// ---------------------------------------------------------------------------
#define F_TILE 8192
#define F_QB   (2 * F_TILE)
#define F_STGB (4 * F_TILE)
#define F_SMEM (F_QB + 2 * F_STGB + 64)   // 82048

__global__ void __launch_bounds__(128) flash16_kernel(
    const __half* __restrict__ QH, const __half* __restrict__ QL,
    const __half* __restrict__ KH, const __half* __restrict__ KL,
    const __half* __restrict__ VH, const __half* __restrict__ VL,
    __half* __restrict__ CH)
{
    extern __shared__ char fsm[];
    const uint32_t sb  = smem_u32(fsm);
    const uint32_t bar = sb + F_QB + 2 * F_STGB;
    const int qt = (int)gridDim.x - 1 - (int)blockIdx.x;
    const int bh = blockIdx.y;
    const int b = bh >> 4, h = bh & 15;
    const int tid = threadIdx.x, wid = tid >> 5, lid = tid & 31;
    const size_t fb = ((size_t)bh) << 17;   // bh * 32 tiles * 4096 halves

    if (tid == 0) {
        MBAR_INIT(bar, 1); MBAR_INIT(bar + 8, 1); MBAR_INIT(bar + 16, 1);
    }
    __syncthreads();

    auto issue_kv = [&](int kt, int s) {
        uint32_t mb = bar + 8 + s * 8;
        uint32_t sd = sb + F_QB + (uint32_t)s * F_STGB;
        size_t go = (fb + ((size_t)kt << 12)) * 2;   // bytes
        MBAR_EXPECT(mb, F_STGB);
        bulk_g2s(sd,              (const char*)KH + go, F_TILE, mb);
        bulk_g2s(sd + F_TILE,     (const char*)KL + go, F_TILE, mb);
        bulk_g2s(sd + 2 * F_TILE, (const char*)VH + go, F_TILE, mb);
        bulk_g2s(sd + 3 * F_TILE, (const char*)VL + go, F_TILE, mb);
    };

    if (tid == 0) {
        size_t qo = (fb + ((size_t)qt << 12)) * 2;
        MBAR_EXPECT(bar, F_QB);
        bulk_g2s(sb,          (const char*)QH + qo, F_TILE, bar);
        bulk_g2s(sb + F_TILE, (const char*)QL + qo, F_TILE, bar);
        issue_kv(0, 0);
        if (qt >= 1) issue_kv(1, 1);
    }

    // Q fragments (register-resident for the whole block)
    MBAR_WAIT(bar, 0);
    uint32_t qfh[4][4], qfl[4][4];
    {
        int r = wid * 16 + (lid & 15);
#pragma unroll
        for (int dc = 0; dc < 4; dc++) {
            int gran = dc * 2 + (lid >> 4);
            uint32_t a = sb + (uint32_t)(r * 128 + ((gran ^ (r & 7)) << 4));
            ldm4(qfh[dc], a);
            ldm4(qfl[dc], a + F_TILE);
        }
    }

    float oacc[8][4];
    float m_[2] = {-INFINITY, -INFINITY}, l_[2] = {0.f, 0.f};
#pragma unroll
    for (int ni = 0; ni < 8; ni++)
#pragma unroll
        for (int j = 0; j < 4; j++) oacc[ni][j] = 0.f;

    for (int kt = 0; kt <= qt; kt++) {
        const int s = kt & 1;
        MBAR_WAIT(bar + 8 + s * 8, (kt >> 1) & 1);

        const uint32_t ks = sb + F_QB + (uint32_t)s * F_STGB;

        // ---- S = Q K^T (3-term) ----
        float sacc[8][4];
#pragma unroll
        for (int ni = 0; ni < 8; ni++)
#pragma unroll
            for (int j = 0; j < 4; j++) sacc[ni][j] = 0.f;

#pragma unroll
        for (int dc = 0; dc < 4; dc++) {
#pragma unroll
            for (int g = 0; g < 4; g++) {
                int rr = g * 16 + (lid & 7) + ((lid >> 4) & 1) * 8;
                int gran = dc * 2 + ((lid >> 3) & 1);
                uint32_t ka = ks + (uint32_t)(rr * 128 + ((gran ^ (rr & 7)) << 4));
                uint32_t kh4[4], kl4[4];
                ldm4(kh4, ka);
                ldm4(kl4, ka + F_TILE);
                mma16816(sacc[2 * g],     qfh[dc], kh4[0], kh4[1]);
                mma16816(sacc[2 * g],     qfh[dc], kl4[0], kl4[1]);
                mma16816(sacc[2 * g],     qfl[dc], kh4[0], kh4[1]);
                mma16816(sacc[2 * g + 1], qfh[dc], kh4[2], kh4[3]);
                mma16816(sacc[2 * g + 1], qfh[dc], kl4[2], kl4[3]);
                mma16816(sacc[2 * g + 1], qfl[dc], kh4[2], kh4[3]);
            }
        }

        // ---- causal mask (diagonal tile) ----
        if (kt == qt) {
            int r0 = wid * 16 + (lid >> 2);
#pragma unroll
            for (int ni = 0; ni < 8; ni++) {
                int c0 = ni * 8 + (lid & 3) * 2;
                if (c0     > r0)     sacc[ni][0] = -INFINITY;
                if (c0 + 1 > r0)     sacc[ni][1] = -INFINITY;
                if (c0     > r0 + 8) sacc[ni][2] = -INFINITY;
                if (c0 + 1 > r0 + 8) sacc[ni][3] = -INFINITY;
            }
        }

        // ---- online softmax ----
#pragma unroll
        for (int r = 0; r < 2; r++) {
            float mt = -INFINITY;
#pragma unroll
            for (int ni = 0; ni < 8; ni++)
                mt = fmaxf(mt, fmaxf(sacc[ni][2 * r], sacc[ni][2 * r + 1]));
            mt = fmaxf(mt, __shfl_xor_sync(0xffffffffu, mt, 1));
            mt = fmaxf(mt, __shfl_xor_sync(0xffffffffu, mt, 2));
            float mn = fmaxf(m_[r], mt);
            float sc = __expf(m_[r] - mn);
            float ps = 0.f;
#pragma unroll
            for (int ni = 0; ni < 8; ni++) {
                float p0 = __expf(sacc[ni][2 * r]     - mn);
                float p1 = __expf(sacc[ni][2 * r + 1] - mn);
                sacc[ni][2 * r] = p0; sacc[ni][2 * r + 1] = p1;
                ps += p0 + p1;
            }
            ps += __shfl_xor_sync(0xffffffffu, ps, 1);
            ps += __shfl_xor_sync(0xffffffffu, ps, 2);
            l_[r] = l_[r] * sc + ps;
            m_[r] = mn;
#pragma unroll
            for (int ni = 0; ni < 8; ni++) {
                oacc[ni][2 * r]     *= sc;
                oacc[ni][2 * r + 1] *= sc;
            }
        }

        // ---- pack P (hi only) ----
        uint32_t pah[4][4];
#pragma unroll
        for (int kc = 0; kc < 4; kc++) {
#pragma unroll
            for (int q = 0; q < 4; q++) {
                int ni = 2 * kc + (q >> 1);
                __half2 hp = __floats2half2_rn(sacc[ni][(q & 1) * 2],
                                               sacc[ni][(q & 1) * 2 + 1]);
                pah[kc][q] = h2_bits(hp);
            }
        }

        // ---- O += P V (2-term) ----
        const uint32_t vs = ks + 2 * F_TILE;
#pragma unroll
        for (int kc = 0; kc < 4; kc++) {
#pragma unroll
            for (int g = 0; g < 4; g++) {
                int rv = kc * 16 + (lid & 7) + ((lid >> 3) & 1) * 8;
                int gran = g * 2 + (lid >> 4);
                uint32_t va = vs + (uint32_t)(rv * 128 + ((gran ^ (rv & 7)) << 4));
                uint32_t vh4[4], vl4[4];
                ldm4t(vh4, va);
                ldm4t(vl4, va + F_TILE);
                mma16816(oacc[2 * g],     pah[kc], vh4[0], vh4[1]);
                mma16816(oacc[2 * g],     pah[kc], vl4[0], vl4[1]);
                mma16816(oacc[2 * g + 1], pah[kc], vh4[2], vh4[3]);
                mma16816(oacc[2 * g + 1], pah[kc], vl4[2], vl4[3]);
            }
        }

        __syncthreads();   // all warps done with stage s before refill
        if (kt + 2 <= qt && tid == 0) issue_kv(kt + 2, s);
    }

    // ---- epilogue: normalize, write CH in GEMM-tiled layout ----
    float inv0 = 1.f / l_[0], inv1 = 1.f / l_[1];
    int m0 = b * T_ + qt * 64 + wid * 16 + (lid >> 2);
#pragma unroll
    for (int ni = 0; ni < 8; ni++) {
        int colD = h * HD_ + ni * 8 + (lid & 3) * 2;
        __half2 h0 = __floats2half2_rn(oacc[ni][0] * inv0, oacc[ni][1] * inv0);
        __half2 h1 = __floats2half2_rn(oacc[ni][2] * inv1, oacc[ni][3] * inv1);
        *(__half2*)&CH[tiled_off(m0,     colD)] = h0;
        *(__half2*)&CH[tiled_off(m0 + 8, colD)] = h1;
    }
}

// ---------------------------------------------------------------------------
extern "C" void kernel_launch(void* const* d_in, const int* in_sizes, int n_in,
                              void* d_out, int out_size)
{
    const float* X  = (const float*)d_in[0];
    const float* Wq = (const float*)d_in[1];
    const float* Wk = (const float*)d_in[2];
    const float* Wv = (const float*)d_in[3];
    const float* Wo = (const float*)d_in[4];
    const float* bo = (const float*)d_in[5];
    float* Y = (float*)d_out;

    __half *gXH, *gXL, *gQH, *gQL, *gKH, *gKL, *gVH, *gVL, *gCH, *gWT;
    cudaGetSymbolAddress((void**)&gXH, g_XH);
    cudaGetSymbolAddress((void**)&gXL, g_XL);
    cudaGetSymbolAddress((void**)&gQH, g_QH);
    cudaGetSymbolAddress((void**)&gQL, g_QL);
    cudaGetSymbolAddress((void**)&gKH, g_KH);
    cudaGetSymbolAddress((void**)&gKL, g_KL);
    cudaGetSymbolAddress((void**)&gVH, g_VH);
    cudaGetSymbolAddress((void**)&gVL, g_VL);
    cudaGetSymbolAddress((void**)&gCH, g_CH);
    cudaGetSymbolAddress((void**)&gWT, g_WT16);
    const size_t WSZ = (size_t)D_ * D_;

    cudaFuncSetAttribute((const void*)gemm16_kernel<3, 1>,
                         cudaFuncAttributeMaxDynamicSharedMemorySize, G_SMEM);
    cudaFuncSetAttribute((const void*)gemm16_kernel<2, 1>,
                         cudaFuncAttributeMaxDynamicSharedMemorySize, G_SMEM);
    cudaFuncSetAttribute((const void*)gemm16_kernel<2, 0>,
                         cudaFuncAttributeMaxDynamicSharedMemorySize, G_SMEM);
    cudaFuncSetAttribute((const void*)flash16_kernel,
                         cudaFuncAttributeMaxDynamicSharedMemorySize, F_SMEM);

    const int n4 = (M_ * D_) / 4;
    split16_kernel<<<(n4 + 255) / 256, 256>>>((const float4*)X, gXH, gXL, n4);
    transpose_split16_all<<<dim3(32, 32, 4), dim3(32, 8)>>>(Wq, Wk, Wv, Wo, gWT);

    dim3 gg(D_ / 128, M_ / 128);   // (8, 32) = 256 CTAs
    gemm16_kernel<3, 1><<<gg, 256, G_SMEM>>>(gXH, gXL, gWT + 0 * WSZ, gWT + 3 * WSZ,
                                             nullptr, 0.125f, nullptr, gQH, gQL);
    gemm16_kernel<3, 1><<<gg, 256, G_SMEM>>>(gXH, gXL, gWT + 1 * WSZ, gWT + 4 * WSZ,
                                             nullptr, 1.0f, nullptr, gKH, gKL);
    gemm16_kernel<2, 1><<<gg, 256, G_SMEM>>>(gXH, gXL, gWT + 2 * WSZ, gWT + 5 * WSZ,
                                             nullptr, 1.0f, nullptr, gVH, gVL);

    flash16_kernel<<<dim3(T_ / 64, B_ * H_), 128, F_SMEM>>>(
        gQH, gQL, gKH, gKL, gVH, gVL, gCH);

    gemm16_kernel<2, 0><<<gg, 256, G_SMEM>>>(gCH, nullptr, gWT + 6 * WSZ, gWT + 7 * WSZ,
                                             bo, 1.0f, Y, nullptr, nullptr);
}

// round 13
// speedup vs baseline: 1.4975x; 1.0274x over previous
#include <cuda_runtime.h>
#include <cuda_fp16.h>
#include <math.h>
#include <stdint.h>

// Problem shape (fixed)
#define B_  2
#define T_  2048
#define D_  1024
#define H_  16
#define HD_ 64
#define M_  (B_*T_)   // 4096

// ---------------------------------------------------------------------------
// Scratch (__device__ globals)
// GEMM-tiled: 8KB blocks = 128 rows x 32 halves, SW64 (g_XH/XL, g_CH, g_WT16)
// FLASH-tiled: per (b,h), 32 tiles of 64 tokens x 64 halves (8KB), SW128
// ---------------------------------------------------------------------------
__device__ __half g_XH[(size_t)M_ * D_];
__device__ __half g_XL[(size_t)M_ * D_];
__device__ __half g_QH[(size_t)M_ * D_];
__device__ __half g_QL[(size_t)M_ * D_];
__device__ __half g_KH[(size_t)M_ * D_];
__device__ __half g_KL[(size_t)M_ * D_];
__device__ __half g_VH[(size_t)M_ * D_];
__device__ __half g_VL[(size_t)M_ * D_];
__device__ __half g_CH[(size_t)M_ * D_];
// [0]=WqH [1]=WkH [2]=WvH [3]=WqL [4]=WkL [5]=WvL [6]=WoH [7]=WoL
__device__ __half g_WT16[8][(size_t)D_ * D_];

// ---------------------------------------------------------------------------
// PTX helpers
// ---------------------------------------------------------------------------
__device__ __forceinline__ uint32_t smem_u32(const void* p) {
    uint32_t a;
    asm("{ .reg .u64 t; cvta.to.shared.u64 t, %1; cvt.u32.u64 %0, t; }"
        : "=r"(a) : "l"(p));
    return a;
}

__device__ __forceinline__ void bulk_g2s(uint32_t sdst, const void* gsrc,
                                         uint32_t bytes, uint32_t mbar) {
    asm volatile(
        "cp.async.bulk.shared::cluster.global.mbarrier::complete_tx::bytes "
        "[%0], [%1], %2, [%3];"
        :: "r"(sdst), "l"(gsrc), "r"(bytes), "r"(mbar) : "memory");
}

#define MBAR_INIT(addr, cnt) \
    asm volatile("mbarrier.init.shared.b64 [%0], %1;" :: "r"(addr), "r"(cnt) : "memory")
#define MBAR_EXPECT(addr, bytes) \
    asm volatile("mbarrier.arrive.expect_tx.shared.b64 _, [%0], %1;" \
                 :: "r"(addr), "r"(bytes) : "memory")
#define MBAR_WAIT(addr, par) do {                                                  \
    uint32_t _m = (uint32_t)(addr); uint32_t _p = (uint32_t)(par);                 \
    asm volatile("{\n\t.reg .pred P1;\n\t"                                         \
        "WL_%=:\n\t"                                                                \
        "mbarrier.try_wait.parity.acquire.cta.shared::cta.b64 P1, [%0], %1;\n\t"   \
        "@P1 bra.uni WD_%=;\n\t"                                                    \
        "bra.uni WL_%=;\n\t"                                                        \
        "WD_%=:\n\t}" :: "r"(_m), "r"(_p) : "memory");                              \
} while (0)

__device__ __forceinline__ void ldm4(uint32_t* r, uint32_t addr) {
    asm volatile("ldmatrix.sync.aligned.m8n8.x4.shared.b16 {%0,%1,%2,%3}, [%4];"
                 : "=r"(r[0]), "=r"(r[1]), "=r"(r[2]), "=r"(r[3]) : "r"(addr));
}

__device__ __forceinline__ void ldm4t(uint32_t* r, uint32_t addr) {
    asm volatile("ldmatrix.sync.aligned.m8n8.x4.trans.shared.b16 {%0,%1,%2,%3}, [%4];"
                 : "=r"(r[0]), "=r"(r[1]), "=r"(r[2]), "=r"(r[3]) : "r"(addr));
}

__device__ __forceinline__ void mma16816(float* d, const uint32_t* a,
                                         uint32_t b0, uint32_t b1) {
    asm volatile(
        "mma.sync.aligned.m16n8k16.row.col.f32.f16.f16.f32 "
        "{%0,%1,%2,%3},{%4,%5,%6,%7},{%8,%9},{%0,%1,%2,%3};"
        : "+f"(d[0]), "+f"(d[1]), "+f"(d[2]), "+f"(d[3])
        : "r"(a[0]), "r"(a[1]), "r"(a[2]), "r"(a[3]), "r"(b0), "r"(b1));
}

__device__ __forceinline__ uint32_t h2_bits(__half2 v) {
    return *(uint32_t*)&v;
}

// GEMM-tiled offset (128-row x 32-col blocks, SW64)
__device__ __forceinline__ size_t tiled_off(int m, int col) {
    int blk = ((m >> 7) << 5) + (col >> 5);
    int r = m & 127, cb = col & 31;
    int chunk = (cb >> 3) ^ ((r >> 1) & 3);
    return (size_t)blk * 4096 + r * 32 + (chunk << 3) + (cb & 7);
}

// FLASH-tiled offset (general form; used only in prepasses / flash epilogue)
__device__ __forceinline__ size_t flash_off(int m, int n) {
    int b = m >> 11, t = m & 2047;
    int h = n >> 6, d = n & 63;
    size_t tb = ((size_t)(((b << 4) + h) * 32 + (t >> 6))) << 12;
    int r = t & 63;
    return tb + r * 64 + ((((d >> 3) ^ (r & 7)) << 3)) + (d & 7);
}

// ---------------------------------------------------------------------------
// Prepass 1: fp32 -> (fp16 hi, lo), GEMM-tiled
// ---------------------------------------------------------------------------
__global__ void split16_kernel(const float4* __restrict__ in,
                               __half* __restrict__ hi, __half* __restrict__ lo,
                               int n4) {
    int i = blockIdx.x * blockDim.x + threadIdx.x;
    if (i >= n4) return;
    float4 v = in[i];
    __half hx = __float2half_rn(v.x), hy = __float2half_rn(v.y);
    __half hz = __float2half_rn(v.z), hw = __float2half_rn(v.w);
    __half lx = __float2half_rn(v.x - __half2float(hx));
    __half ly = __float2half_rn(v.y - __half2float(hy));
    __half lz = __float2half_rn(v.z - __half2float(hz));
    __half lw = __float2half_rn(v.w - __half2float(hw));
    __half2 h0 = __halves2half2(hx, hy), h1 = __halves2half2(hz, hw);
    __half2 l0 = __halves2half2(lx, ly), l1 = __halves2half2(lz, lw);
    int e = i * 4;
    int m = e >> 10, col = e & 1023;
    size_t off = tiled_off(m, col);
    *(uint2*)&hi[off] = make_uint2(h2_bits(h0), h2_bits(h1));
    *(uint2*)&lo[off] = make_uint2(h2_bits(l0), h2_bits(l1));
}

// ---------------------------------------------------------------------------
// Prepass 2: W[k][n] -> GEMM-tiled WT_hi[n][k], WT_lo[n][k]
// ---------------------------------------------------------------------------
__global__ void transpose_split16_all(const float* __restrict__ Wq,
                                      const float* __restrict__ Wk,
                                      const float* __restrict__ Wv,
                                      const float* __restrict__ Wo,
                                      __half* __restrict__ baseW) {
    __shared__ float t[32][33];
    const int z = blockIdx.z;
    const float* W = (z == 0) ? Wq : (z == 1) ? Wk : (z == 2) ? Wv : Wo;
    const size_t WSZ = (size_t)D_ * D_;
    __half* TH = baseW + ((z < 3) ? (size_t)z * WSZ : 6 * WSZ);
    __half* TL = baseW + ((z < 3) ? (size_t)(3 + z) * WSZ : 7 * WSZ);

    const int tx = threadIdx.x, ty = threadIdx.y;   // 32 x 8
    const int bn = blockIdx.x * 32;
    const int bk = blockIdx.y * 32;
#pragma unroll
    for (int i = 0; i < 4; i++)
        t[ty + 8 * i][tx] = W[(size_t)(bk + ty + 8 * i) * D_ + bn + tx];
    __syncthreads();
#pragma unroll
    for (int i = 0; i < 4; i++) {
        int row = ty + 8 * i;
        float v = t[tx][row];
        __half h = __float2half_rn(v);
        size_t o = tiled_off(bn + row, bk + tx);
        TH[o] = h;
        TL[o] = __float2half_rn(v - __half2float(h));
    }
}

// ---------------------------------------------------------------------------
// Bulk-copy GEMM. FOUT: 0 = fp32 row-major (+bias), 1 = flash-tiled fp16 (hi,lo)
// __launch_bounds__(256, 2) caps regs at 128 (R11-proven sufficient).
// ---------------------------------------------------------------------------
#define G_BLK    8192
#define G_STGB   (4 * G_BLK)
#define G_NSTG   3
#define G_SMEM   (G_NSTG * G_STGB + 64)
#define G_NCH    (D_ / 32)

template<int TERMS, int FOUT>
__global__ void __launch_bounds__(256, 2) gemm16_kernel(
    const __half* __restrict__ AH, const __half* __restrict__ AL,
    const __half* __restrict__ BH, const __half* __restrict__ BL,
    const float* __restrict__ bias, float scale,
    float* __restrict__ outF,
    __half* __restrict__ outH, __half* __restrict__ outL)
{
    extern __shared__ char smem[];
    const uint32_t sb  = smem_u32(smem);
    const uint32_t bar = sb + G_NSTG * G_STGB;
    const int tid = threadIdx.x;
    const int lid = tid & 31;
    const int wid = tid >> 5;
    const int wm  = wid >> 2;
    const int wn  = wid & 3;
    const int row16 = lid & 15;
    const int sel   = lid >> 4;
    const int bm = blockIdx.y << 7;
    const int bn = blockIdx.x << 7;
    const int aBlk = blockIdx.y << 5;
    const int bBlk = blockIdx.x << 5;

    if (tid == 0) {
#pragma unroll
        for (int s = 0; s < G_NSTG; s++) MBAR_INIT(bar + s * 8, 1);
    }
    __syncthreads();

    const uint32_t BYTES = (TERMS == 3) ? (uint32_t)G_STGB : (uint32_t)(3 * G_BLK);
    auto issue = [&](int c, int s) {
        uint32_t mb = bar + s * 8;
        uint32_t sd = sb + (uint32_t)s * G_STGB;
        MBAR_EXPECT(mb, BYTES);
        bulk_g2s(sd,              (const char*)AH + (size_t)(aBlk + c) * G_BLK, G_BLK, mb);
        if (TERMS == 3)
            bulk_g2s(sd + G_BLK,  (const char*)AL + (size_t)(aBlk + c) * G_BLK, G_BLK, mb);
        bulk_g2s(sd + 2 * G_BLK,  (const char*)BH + (size_t)(bBlk + c) * G_BLK, G_BLK, mb);
        bulk_g2s(sd + 3 * G_BLK,  (const char*)BL + (size_t)(bBlk + c) * G_BLK, G_BLK, mb);
    };

    if (tid == 0) { issue(0, 0); issue(1, 1); }

    float acc[4][4][4];
#pragma unroll
    for (int mi = 0; mi < 4; mi++)
#pragma unroll
        for (int ni = 0; ni < 4; ni++)
#pragma unroll
            for (int j = 0; j < 4; j++) acc[mi][ni][j] = 0.f;

    for (int c = 0; c < G_NCH; c++) {
        const int s = c % G_NSTG;
        MBAR_WAIT(bar + s * 8, (c / G_NSTG) & 1);

        const uint32_t sA = sb + (uint32_t)s * G_STGB;
        const uint32_t sB = sA + 2 * G_BLK;
#pragma unroll
        for (int kk = 0; kk < 2; kk++) {
            const int ch = kk * 2 + sel;
            uint32_t ah[4][4], al[4][4];
#pragma unroll
            for (int mi = 0; mi < 4; mi++) {
                int r = wm * 64 + mi * 16 + row16;
                uint32_t addr = sA + (uint32_t)(r * 64 + ((ch ^ ((r >> 1) & 3)) << 4));
                ldm4(ah[mi], addr);
                if (TERMS == 3) ldm4(al[mi], addr + G_BLK);
            }
            uint32_t bh[2][4], bl[2][4];
#pragma unroll
            for (int g = 0; g < 2; g++) {
                int r = wn * 32 + g * 16 + row16;
                uint32_t addr = sB + (uint32_t)(r * 64 + ((ch ^ ((r >> 1) & 3)) << 4));
                ldm4(bh[g], addr);
                ldm4(bl[g], addr + G_BLK);
            }
#pragma unroll
            for (int mi = 0; mi < 4; mi++)
#pragma unroll
                for (int ni = 0; ni < 4; ni++) {
                    const int g = ni >> 1, o = ni & 1;
                    mma16816(acc[mi][ni], ah[mi], bh[g][o], bh[g][o + 2]);
                    mma16816(acc[mi][ni], ah[mi], bl[g][o], bl[g][o + 2]);
                    if (TERMS == 3)
                        mma16816(acc[mi][ni], al[mi], bh[g][o], bh[g][o + 2]);
                }
        }
        __syncthreads();
        if (c + 2 < G_NCH && tid == 0) issue(c + 2, (c + 2) % G_NSTG);
    }

    if (FOUT == 0) {
#pragma unroll
        for (int mi = 0; mi < 4; mi++)
#pragma unroll
            for (int ni = 0; ni < 4; ni++) {
                int row = bm + wm * 64 + mi * 16 + (lid >> 2);
                int col = bn + wn * 32 + ni * 8 + (lid & 3) * 2;
                float v0 = acc[mi][ni][0] * scale, v1 = acc[mi][ni][1] * scale;
                float v2 = acc[mi][ni][2] * scale, v3 = acc[mi][ni][3] * scale;
                float b0 = bias ? bias[col] : 0.f, b1 = bias ? bias[col + 1] : 0.f;
                *(float2*)&outF[(size_t)row * D_ + col]       = make_float2(v0 + b0, v1 + b1);
                *(float2*)&outF[(size_t)(row + 8) * D_ + col] = make_float2(v2 + b0, v3 + b1);
            }
    } else {
        // Lean flash-tiled epilogue. Alignment invariants (bm%128==0, bn%128==0):
        //   b    = bm>>11 (const), tile row index = (bm&2047)/64 + wm (const)
        //   hcol = (bn + wn*32)>>6 (const), r = lid>>2 + mi*16, +8 row = +512
        //   d    = (wn&1)*32 + (lid&3)*2 + ni*8
        const int bq   = bm >> 11;
        const int trow = ((bm & 2047) >> 6) + wm;
        const int hcol = (bn + wn * 32) >> 6;
        const size_t tb = ((size_t)(((bq << 4) + hcol) * 32 + trow)) << 12;
        const int r0 = lid >> 2;
        const int d0 = ((wn & 1) << 5) + ((lid & 3) << 1);
#pragma unroll
        for (int mi = 0; mi < 4; mi++) {
            const int r = r0 + mi * 16;
            const uint32_t rsw = (uint32_t)(r & 7);
#pragma unroll
            for (int ni = 0; ni < 4; ni++) {
                const int d = d0 + ni * 8;
                size_t off = tb + (size_t)(r * 64)
                           + ((((uint32_t)(d >> 3) ^ rsw) << 3)) + (d & 7);
                float v0 = acc[mi][ni][0] * scale, v1 = acc[mi][ni][1] * scale;
                float v2 = acc[mi][ni][2] * scale, v3 = acc[mi][ni][3] * scale;
                __half2 h0 = __floats2half2_rn(v0, v1);
                __half2 h1 = __floats2half2_rn(v2, v3);
                *(__half2*)&outH[off]       = h0;
                *(__half2*)&outH[off + 512] = h1;
                if (outL) {
                    __half2 l0 = __floats2half2_rn(v0 - __low2float(h0), v1 - __high2float(h0));
                    __half2 l1 = __floats2half2_rn(v2 - __low2float(h1), v3 - __high2float(h1));
                    *(__half2*)&outL[off]       = l0;
                    *(__half2*)&outL[off + 512] = l1;
                }
            }
        }
    }
}

// ---------------------------------------------------------------------------
// Flash attention (R12-verified): BM=64, 3-term S, 2-term PV, big-first,
// bulk-copy K/V, SW128 flash tiles.
// ---------------------------------------------------------------------------
#define F_TILE 8192
#define F_QB   (2 * F_TILE)
#define F_STGB (4 * F_TILE)
#define F_SMEM (F_QB + 2 * F_STGB + 64)   // 82048

__global__ void __launch_bounds__(128) flash16_kernel(
    const __half* __restrict__ QH, const __half* __restrict__ QL,
    const __half* __restrict__ KH, const __half* __restrict__ KL,
    const __half* __restrict__ VH, const __half* __restrict__ VL,
    __half* __restrict__ CH)
{
    extern __shared__ char fsm[];
    const uint32_t sb  = smem_u32(fsm);
    const uint32_t bar = sb + F_QB + 2 * F_STGB;
    const int qt = (int)gridDim.x - 1 - (int)blockIdx.x;
    const int bh = blockIdx.y;
    const int b = bh >> 4, h = bh & 15;
    const int tid = threadIdx.x, wid = tid >> 5, lid = tid & 31;
    const size_t fb = ((size_t)bh) << 17;

    if (tid == 0) {
        MBAR_INIT(bar, 1); MBAR_INIT(bar + 8, 1); MBAR_INIT(bar + 16, 1);
    }
    __syncthreads();

    auto issue_kv = [&](int kt, int s) {
        uint32_t mb = bar + 8 + s * 8;
        uint32_t sd = sb + F_QB + (uint32_t)s * F_STGB;
        size_t go = (fb + ((size_t)kt << 12)) * 2;
        MBAR_EXPECT(mb, F_STGB);
        bulk_g2s(sd,              (const char*)KH + go, F_TILE, mb);
        bulk_g2s(sd + F_TILE,     (const char*)KL + go, F_TILE, mb);
        bulk_g2s(sd + 2 * F_TILE, (const char*)VH + go, F_TILE, mb);
        bulk_g2s(sd + 3 * F_TILE, (const char*)VL + go, F_TILE, mb);
    };

    if (tid == 0) {
        size_t qo = (fb + ((size_t)qt << 12)) * 2;
        MBAR_EXPECT(bar, F_QB);
        bulk_g2s(sb,          (const char*)QH + qo, F_TILE, bar);
        bulk_g2s(sb + F_TILE, (const char*)QL + qo, F_TILE, bar);
        issue_kv(0, 0);
        if (qt >= 1) issue_kv(1, 1);
    }

    MBAR_WAIT(bar, 0);
    uint32_t qfh[4][4], qfl[4][4];
    {
        int r = wid * 16 + (lid & 15);
#pragma unroll
        for (int dc = 0; dc < 4; dc++) {
            int gran = dc * 2 + (lid >> 4);
            uint32_t a = sb + (uint32_t)(r * 128 + ((gran ^ (r & 7)) << 4));
            ldm4(qfh[dc], a);
            ldm4(qfl[dc], a + F_TILE);
        }
    }

    float oacc[8][4];
    float m_[2] = {-INFINITY, -INFINITY}, l_[2] = {0.f, 0.f};
#pragma unroll
    for (int ni = 0; ni < 8; ni++)
#pragma unroll
        for (int j = 0; j < 4; j++) oacc[ni][j] = 0.f;

    for (int kt = 0; kt <= qt; kt++) {
        const int s = kt & 1;
        MBAR_WAIT(bar + 8 + s * 8, (kt >> 1) & 1);

        const uint32_t ks = sb + F_QB + (uint32_t)s * F_STGB;

        float sacc[8][4];
#pragma unroll
        for (int ni = 0; ni < 8; ni++)
#pragma unroll
            for (int j = 0; j < 4; j++) sacc[ni][j] = 0.f;

#pragma unroll
        for (int dc = 0; dc < 4; dc++) {
#pragma unroll
            for (int g = 0; g < 4; g++) {
                int rr = g * 16 + (lid & 7) + ((lid >> 4) & 1) * 8;
                int gran = dc * 2 + ((lid >> 3) & 1);
                uint32_t ka = ks + (uint32_t)(rr * 128 + ((gran ^ (rr & 7)) << 4));
                uint32_t kh4[4], kl4[4];
                ldm4(kh4, ka);
                ldm4(kl4, ka + F_TILE);
                mma16816(sacc[2 * g],     qfh[dc], kh4[0], kh4[1]);
                mma16816(sacc[2 * g],     qfh[dc], kl4[0], kl4[1]);
                mma16816(sacc[2 * g],     qfl[dc], kh4[0], kh4[1]);
                mma16816(sacc[2 * g + 1], qfh[dc], kh4[2], kh4[3]);
                mma16816(sacc[2 * g + 1], qfh[dc], kl4[2], kl4[3]);
                mma16816(sacc[2 * g + 1], qfl[dc], kh4[2], kh4[3]);
            }
        }

        if (kt == qt) {
            int r0 = wid * 16 + (lid >> 2);
#pragma unroll
            for (int ni = 0; ni < 8; ni++) {
                int c0 = ni * 8 + (lid & 3) * 2;
                if (c0     > r0)     sacc[ni][0] = -INFINITY;
                if (c0 + 1 > r0)     sacc[ni][1] = -INFINITY;
                if (c0     > r0 + 8) sacc[ni][2] = -INFINITY;
                if (c0 + 1 > r0 + 8) sacc[ni][3] = -INFINITY;
            }
        }

#pragma unroll
        for (int r = 0; r < 2; r++) {
            float mt = -INFINITY;
#pragma unroll
            for (int ni = 0; ni < 8; ni++)
                mt = fmaxf(mt, fmaxf(sacc[ni][2 * r], sacc[ni][2 * r + 1]));
            mt = fmaxf(mt, __shfl_xor_sync(0xffffffffu, mt, 1));
            mt = fmaxf(mt, __shfl_xor_sync(0xffffffffu, mt, 2));
            float mn = fmaxf(m_[r], mt);
            float sc = __expf(m_[r] - mn);
            float ps = 0.f;
#pragma unroll
            for (int ni = 0; ni < 8; ni++) {
                float p0 = __expf(sacc[ni][2 * r]     - mn);
                float p1 = __expf(sacc[ni][2 * r + 1] - mn);
                sacc[ni][2 * r] = p0; sacc[ni][2 * r + 1] = p1;
                ps += p0 + p1;
            }
            ps += __shfl_xor_sync(0xffffffffu, ps, 1);
            ps += __shfl_xor_sync(0xffffffffu, ps, 2);
            l_[r] = l_[r] * sc + ps;
            m_[r] = mn;
#pragma unroll
            for (int ni = 0; ni < 8; ni++) {
                oacc[ni][2 * r]     *= sc;
                oacc[ni][2 * r + 1] *= sc;
            }
        }

        uint32_t pah[4][4];
#pragma unroll
        for (int kc = 0; kc < 4; kc++) {
#pragma unroll
            for (int q = 0; q < 4; q++) {
                int ni = 2 * kc + (q >> 1);
                __half2 hp = __floats2half2_rn(sacc[ni][(q & 1) * 2],
                                               sacc[ni][(q & 1) * 2 + 1]);
                pah[kc][q] = h2_bits(hp);
            }
        }

        const uint32_t vs = ks + 2 * F_TILE;
#pragma unroll
        for (int kc = 0; kc < 4; kc++) {
#pragma unroll
            for (int g = 0; g < 4; g++) {
                int rv = kc * 16 + (lid & 7) + ((lid >> 3) & 1) * 8;
                int gran = g * 2 + (lid >> 4);
                uint32_t va = vs + (uint32_t)(rv * 128 + ((gran ^ (rv & 7)) << 4));
                uint32_t vh4[4], vl4[4];
                ldm4t(vh4, va);
                ldm4t(vl4, va + F_TILE);
                mma16816(oacc[2 * g],     pah[kc], vh4[0], vh4[1]);
                mma16816(oacc[2 * g],     pah[kc], vl4[0], vl4[1]);
                mma16816(oacc[2 * g + 1], pah[kc], vh4[2], vh4[3]);
                mma16816(oacc[2 * g + 1], pah[kc], vl4[2], vl4[3]);
            }
        }

        __syncthreads();
        if (kt + 2 <= qt && tid == 0) issue_kv(kt + 2, s);
    }

    float inv0 = 1.f / l_[0], inv1 = 1.f / l_[1];
    int m0 = b * T_ + qt * 64 + wid * 16 + (lid >> 2);
#pragma unroll
    for (int ni = 0; ni < 8; ni++) {
        int colD = h * HD_ + ni * 8 + (lid & 3) * 2;
        __half2 h0 = __floats2half2_rn(oacc[ni][0] * inv0, oacc[ni][1] * inv0);
        __half2 h1 = __floats2half2_rn(oacc[ni][2] * inv1, oacc[ni][3] * inv1);
        *(__half2*)&CH[tiled_off(m0,     colD)] = h0;
        *(__half2*)&CH[tiled_off(m0 + 8, colD)] = h1;
    }
}

// ---------------------------------------------------------------------------
extern "C" void kernel_launch(void* const* d_in, const int* in_sizes, int n_in,
                              void* d_out, int out_size)
{
    const float* X  = (const float*)d_in[0];
    const float* Wq = (const float*)d_in[1];
    const float* Wk = (const float*)d_in[2];
    const float* Wv = (const float*)d_in[3];
    const float* Wo = (const float*)d_in[4];
    const float* bo = (const float*)d_in[5];
    float* Y = (float*)d_out;

    __half *gXH, *gXL, *gQH, *gQL, *gKH, *gKL, *gVH, *gVL, *gCH, *gWT;
    cudaGetSymbolAddress((void**)&gXH, g_XH);
    cudaGetSymbolAddress((void**)&gXL, g_XL);
    cudaGetSymbolAddress((void**)&gQH, g_QH);
    cudaGetSymbolAddress((void**)&gQL, g_QL);
    cudaGetSymbolAddress((void**)&gKH, g_KH);
    cudaGetSymbolAddress((void**)&gKL, g_KL);
    cudaGetSymbolAddress((void**)&gVH, g_VH);
    cudaGetSymbolAddress((void**)&gVL, g_VL);
    cudaGetSymbolAddress((void**)&gCH, g_CH);
    cudaGetSymbolAddress((void**)&gWT, g_WT16);
    const size_t WSZ = (size_t)D_ * D_;

    cudaFuncSetAttribute((const void*)gemm16_kernel<3, 1>,
                         cudaFuncAttributeMaxDynamicSharedMemorySize, G_SMEM);
    cudaFuncSetAttribute((const void*)gemm16_kernel<2, 1>,
                         cudaFuncAttributeMaxDynamicSharedMemorySize, G_SMEM);
    cudaFuncSetAttribute((const void*)gemm16_kernel<2, 0>,
                         cudaFuncAttributeMaxDynamicSharedMemorySize, G_SMEM);
    cudaFuncSetAttribute((const void*)flash16_kernel,
                         cudaFuncAttributeMaxDynamicSharedMemorySize, F_SMEM);

    const int n4 = (M_ * D_) / 4;
    split16_kernel<<<(n4 + 255) / 256, 256>>>((const float4*)X, gXH, gXL, n4);
    transpose_split16_all<<<dim3(32, 32, 4), dim3(32, 8)>>>(Wq, Wk, Wv, Wo, gWT);

    dim3 gg(D_ / 128, M_ / 128);   // (8, 32) = 256 CTAs
    gemm16_kernel<3, 1><<<gg, 256, G_SMEM>>>(gXH, gXL, gWT + 0 * WSZ, gWT + 3 * WSZ,
                                             nullptr, 0.125f, nullptr, gQH, gQL);
    gemm16_kernel<3, 1><<<gg, 256, G_SMEM>>>(gXH, gXL, gWT + 1 * WSZ, gWT + 4 * WSZ,
                                             nullptr, 1.0f, nullptr, gKH, gKL);
    gemm16_kernel<2, 1><<<gg, 256, G_SMEM>>>(gXH, gXL, gWT + 2 * WSZ, gWT + 5 * WSZ,
                                             nullptr, 1.0f, nullptr, gVH, gVL);

    flash16_kernel<<<dim3(T_ / 64, B_ * H_), 128, F_SMEM>>>(
        gQH, gQL, gKH, gKL, gVH, gVL, gCH);

    gemm16_kernel<2, 0><<<gg, 256, G_SMEM>>>(gCH, nullptr, gWT + 6 * WSZ, gWT + 7 * WSZ,
                                             bo, 1.0f, Y, nullptr, nullptr);
}

// round 14
// speedup vs baseline: 1.5024x; 1.0033x over previous
#include <cuda_runtime.h>
#include <cuda_fp16.h>
#include <math.h>
#include <stdint.h>

// Problem shape (fixed)
#define B_  2
#define T_  2048
#define D_  1024
#define H_  16
#define HD_ 64
#define M_  (B_*T_)   // 4096

// ---------------------------------------------------------------------------
// Scratch (__device__ globals)
// GEMM-tiled: 8KB blocks = 128 rows x 32 halves, SW64 (g_XH/XL, g_CH, g_WT16)
// FLASH-tiled: per (b,h), 32 tiles of 64 tokens x 64 halves (8KB), SW128
// ---------------------------------------------------------------------------
__device__ __half g_XH[(size_t)M_ * D_];
__device__ __half g_XL[(size_t)M_ * D_];
__device__ __half g_QH[(size_t)M_ * D_];
__device__ __half g_QL[(size_t)M_ * D_];
__device__ __half g_KH[(size_t)M_ * D_];
__device__ __half g_KL[(size_t)M_ * D_];
__device__ __half g_VH[(size_t)M_ * D_];
__device__ __half g_VL[(size_t)M_ * D_];
__device__ __half g_CH[(size_t)M_ * D_];
// [0]=WqH [1]=WkH [2]=WvH [3]=WqL [4]=WkL [5]=WvL [6]=WoH [7]=WoL
__device__ __half g_WT16[8][(size_t)D_ * D_];

// ---------------------------------------------------------------------------
// PTX helpers
// ---------------------------------------------------------------------------
__device__ __forceinline__ uint32_t smem_u32(const void* p) {
    uint32_t a;
    asm("{ .reg .u64 t; cvta.to.shared.u64 t, %1; cvt.u32.u64 %0, t; }"
        : "=r"(a) : "l"(p));
    return a;
}

__device__ __forceinline__ void bulk_g2s(uint32_t sdst, const void* gsrc,
                                         uint32_t bytes, uint32_t mbar) {
    asm volatile(
        "cp.async.bulk.shared::cluster.global.mbarrier::complete_tx::bytes "
        "[%0], [%1], %2, [%3];"
        :: "r"(sdst), "l"(gsrc), "r"(bytes), "r"(mbar) : "memory");
}

#define MBAR_INIT(addr, cnt) \
    asm volatile("mbarrier.init.shared.b64 [%0], %1;" :: "r"(addr), "r"(cnt) : "memory")
#define MBAR_EXPECT(addr, bytes) \
    asm volatile("mbarrier.arrive.expect_tx.shared.b64 _, [%0], %1;" \
                 :: "r"(addr), "r"(bytes) : "memory")
#define MBAR_ARRIVE(addr) \
    asm volatile("mbarrier.arrive.shared.b64 _, [%0];" :: "r"(addr) : "memory")
#define MBAR_WAIT(addr, par) do {                                                  \
    uint32_t _m = (uint32_t)(addr); uint32_t _p = (uint32_t)(par);                 \
    asm volatile("{\n\t.reg .pred P1;\n\t"                                         \
        "WL_%=:\n\t"                                                                \
        "mbarrier.try_wait.parity.acquire.cta.shared::cta.b64 P1, [%0], %1;\n\t"   \
        "@P1 bra.uni WD_%=;\n\t"                                                    \
        "bra.uni WL_%=;\n\t"                                                        \
        "WD_%=:\n\t}" :: "r"(_m), "r"(_p) : "memory");                              \
} while (0)

__device__ __forceinline__ void ldm4(uint32_t* r, uint32_t addr) {
    asm volatile("ldmatrix.sync.aligned.m8n8.x4.shared.b16 {%0,%1,%2,%3}, [%4];"
                 : "=r"(r[0]), "=r"(r[1]), "=r"(r[2]), "=r"(r[3]) : "r"(addr));
}

__device__ __forceinline__ void ldm4t(uint32_t* r, uint32_t addr) {
    asm volatile("ldmatrix.sync.aligned.m8n8.x4.trans.shared.b16 {%0,%1,%2,%3}, [%4];"
                 : "=r"(r[0]), "=r"(r[1]), "=r"(r[2]), "=r"(r[3]) : "r"(addr));
}

__device__ __forceinline__ void mma16816(float* d, const uint32_t* a,
                                         uint32_t b0, uint32_t b1) {
    asm volatile(
        "mma.sync.aligned.m16n8k16.row.col.f32.f16.f16.f32 "
        "{%0,%1,%2,%3},{%4,%5,%6,%7},{%8,%9},{%0,%1,%2,%3};"
        : "+f"(d[0]), "+f"(d[1]), "+f"(d[2]), "+f"(d[3])
        : "r"(a[0]), "r"(a[1]), "r"(a[2]), "r"(a[3]), "r"(b0), "r"(b1));
}

__device__ __forceinline__ uint32_t h2_bits(__half2 v) {
    return *(uint32_t*)&v;
}

// GEMM-tiled offset (128-row x 32-col blocks, SW64)
__device__ __forceinline__ size_t tiled_off(int m, int col) {
    int blk = ((m >> 7) << 5) + (col >> 5);
    int r = m & 127, cb = col & 31;
    int chunk = (cb >> 3) ^ ((r >> 1) & 3);
    return (size_t)blk * 4096 + r * 32 + (chunk << 3) + (cb & 7);
}

// ---------------------------------------------------------------------------
// Prepass 1: fp32 -> (fp16 hi, lo), GEMM-tiled
// ---------------------------------------------------------------------------
__global__ void split16_kernel(const float4* __restrict__ in,
                               __half* __restrict__ hi, __half* __restrict__ lo,
                               int n4) {
    int i = blockIdx.x * blockDim.x + threadIdx.x;
    if (i >= n4) return;
    float4 v = in[i];
    __half hx = __float2half_rn(v.x), hy = __float2half_rn(v.y);
    __half hz = __float2half_rn(v.z), hw = __float2half_rn(v.w);
    __half lx = __float2half_rn(v.x - __half2float(hx));
    __half ly = __float2half_rn(v.y - __half2float(hy));
    __half lz = __float2half_rn(v.z - __half2float(hz));
    __half lw = __float2half_rn(v.w - __half2float(hw));
    __half2 h0 = __halves2half2(hx, hy), h1 = __halves2half2(hz, hw);
    __half2 l0 = __halves2half2(lx, ly), l1 = __halves2half2(lz, lw);
    int e = i * 4;
    int m = e >> 10, col = e & 1023;
    size_t off = tiled_off(m, col);
    *(uint2*)&hi[off] = make_uint2(h2_bits(h0), h2_bits(h1));
    *(uint2*)&lo[off] = make_uint2(h2_bits(l0), h2_bits(l1));
}

// ---------------------------------------------------------------------------
// Prepass 2: W[k][n] -> GEMM-tiled WT_hi[n][k], WT_lo[n][k]
// ---------------------------------------------------------------------------
__global__ void transpose_split16_all(const float* __restrict__ Wq,
                                      const float* __restrict__ Wk,
                                      const float* __restrict__ Wv,
                                      const float* __restrict__ Wo,
                                      __half* __restrict__ baseW) {
    __shared__ float t[32][33];
    const int z = blockIdx.z;
    const float* W = (z == 0) ? Wq : (z == 1) ? Wk : (z == 2) ? Wv : Wo;
    const size_t WSZ = (size_t)D_ * D_;
    __half* TH = baseW + ((z < 3) ? (size_t)z * WSZ : 6 * WSZ);
    __half* TL = baseW + ((z < 3) ? (size_t)(3 + z) * WSZ : 7 * WSZ);

    const int tx = threadIdx.x, ty = threadIdx.y;   // 32 x 8
    const int bn = blockIdx.x * 32;
    const int bk = blockIdx.y * 32;
#pragma unroll
    for (int i = 0; i < 4; i++)
        t[ty + 8 * i][tx] = W[(size_t)(bk + ty + 8 * i) * D_ + bn + tx];
    __syncthreads();
#pragma unroll
    for (int i = 0; i < 4; i++) {
        int row = ty + 8 * i;
        float v = t[tx][row];
        __half h = __float2half_rn(v);
        size_t o = tiled_off(bn + row, bk + tx);
        TH[o] = h;
        TL[o] = __float2half_rn(v - __half2float(h));
    }
}

// ---------------------------------------------------------------------------
// Bulk-copy GEMM with full/empty mbarrier ring (no per-chunk __syncthreads).
// FOUT: 0 = fp32 row-major (+bias), 1 = flash-tiled fp16 (hi,lo).
// FOUT=1 supports fused dual-output: CTAs with bn>=1024 write (oH1,oL1)
// with scaleAlt (enables fused Q+K launch over concatenated weights).
// ---------------------------------------------------------------------------
#define G_BLK    8192
#define G_STGB   (4 * G_BLK)
#define G_NSTG   3
#define G_SMEM   (G_NSTG * G_STGB + 128)
#define G_NCH    (D_ / 32)

template<int TERMS, int FOUT>
__global__ void __launch_bounds__(256, 2) gemm16_kernel(
    const __half* __restrict__ AH, const __half* __restrict__ AL,
    const __half* __restrict__ BH, const __half* __restrict__ BL,
    const float* __restrict__ bias, float scale, float scaleAlt,
    float* __restrict__ outF,
    __half* __restrict__ oH0, __half* __restrict__ oL0,
    __half* __restrict__ oH1, __half* __restrict__ oL1)
{
    extern __shared__ char smem[];
    const uint32_t sb  = smem_u32(smem);
    const uint32_t bar = sb + G_NSTG * G_STGB;          // full[3] @ +0,8,16
    const uint32_t ebar = bar + 24;                      // empty[3] @ +24,32,40
    const int tid = threadIdx.x;
    const int lid = tid & 31;
    const int wid = tid >> 5;
    const int wm  = wid >> 2;
    const int wn  = wid & 3;
    const int row16 = lid & 15;
    const int sel   = lid >> 4;
    const int bm = blockIdx.y << 7;
    const int bn = blockIdx.x << 7;
    const int aBlk = blockIdx.y << 5;
    const int bBlk = blockIdx.x << 5;

    if (tid == 0) {
#pragma unroll
        for (int s = 0; s < G_NSTG; s++) {
            MBAR_INIT(bar + s * 8, 1);
            MBAR_INIT(ebar + s * 8, 256);
        }
    }
    __syncthreads();

    const uint32_t BYTES = (TERMS == 3) ? (uint32_t)G_STGB : (uint32_t)(3 * G_BLK);
    auto issue = [&](int c, int s) {
        uint32_t mb = bar + s * 8;
        uint32_t sd = sb + (uint32_t)s * G_STGB;
        MBAR_EXPECT(mb, BYTES);
        bulk_g2s(sd,              (const char*)AH + (size_t)(aBlk + c) * G_BLK, G_BLK, mb);
        if (TERMS == 3)
            bulk_g2s(sd + G_BLK,  (const char*)AL + (size_t)(aBlk + c) * G_BLK, G_BLK, mb);
        bulk_g2s(sd + 2 * G_BLK,  (const char*)BH + (size_t)(bBlk + c) * G_BLK, G_BLK, mb);
        bulk_g2s(sd + 3 * G_BLK,  (const char*)BL + (size_t)(bBlk + c) * G_BLK, G_BLK, mb);
    };

    if (tid == 0) { issue(0, 0); issue(1, 1); issue(2, 2); }

    float acc[4][4][4];
#pragma unroll
    for (int mi = 0; mi < 4; mi++)
#pragma unroll
        for (int ni = 0; ni < 4; ni++)
#pragma unroll
            for (int j = 0; j < 4; j++) acc[mi][ni][j] = 0.f;

    for (int c = 0; c < G_NCH; c++) {
        const int s = c % G_NSTG;
        MBAR_WAIT(bar + s * 8, (c / G_NSTG) & 1);

        const uint32_t sA = sb + (uint32_t)s * G_STGB;
        const uint32_t sB = sA + 2 * G_BLK;
#pragma unroll
        for (int kk = 0; kk < 2; kk++) {
            const int ch = kk * 2 + sel;
            uint32_t ah[4][4], al[4][4];
#pragma unroll
            for (int mi = 0; mi < 4; mi++) {
                int r = wm * 64 + mi * 16 + row16;
                uint32_t addr = sA + (uint32_t)(r * 64 + ((ch ^ ((r >> 1) & 3)) << 4));
                ldm4(ah[mi], addr);
                if (TERMS == 3) ldm4(al[mi], addr + G_BLK);
            }
            uint32_t bh[2][4], bl[2][4];
#pragma unroll
            for (int g = 0; g < 2; g++) {
                int r = wn * 32 + g * 16 + row16;
                uint32_t addr = sB + (uint32_t)(r * 64 + ((ch ^ ((r >> 1) & 3)) << 4));
                ldm4(bh[g], addr);
                ldm4(bl[g], addr + G_BLK);
            }
#pragma unroll
            for (int mi = 0; mi < 4; mi++)
#pragma unroll
                for (int ni = 0; ni < 4; ni++) {
                    const int g = ni >> 1, o = ni & 1;
                    mma16816(acc[mi][ni], ah[mi], bh[g][o], bh[g][o + 2]);
                    mma16816(acc[mi][ni], ah[mi], bl[g][o], bl[g][o + 2]);
                    if (TERMS == 3)
                        mma16816(acc[mi][ni], al[mi], bh[g][o], bh[g][o + 2]);
                }
        }
        // Consumer release: all fragments consumed by MMAs above.
        MBAR_ARRIVE(ebar + s * 8);
        if (tid == 0 && c + 3 < G_NCH) {
            const int cn = c + 3, sn = cn % G_NSTG;
            MBAR_WAIT(ebar + sn * 8, (cn / G_NSTG - 1) & 1);
            issue(cn, sn);
        }
    }

    if (FOUT == 0) {
#pragma unroll
        for (int mi = 0; mi < 4; mi++)
#pragma unroll
            for (int ni = 0; ni < 4; ni++) {
                int row = bm + wm * 64 + mi * 16 + (lid >> 2);
                int col = bn + wn * 32 + ni * 8 + (lid & 3) * 2;
                float v0 = acc[mi][ni][0] * scale, v1 = acc[mi][ni][1] * scale;
                float v2 = acc[mi][ni][2] * scale, v3 = acc[mi][ni][3] * scale;
                float b0 = bias ? bias[col] : 0.f, b1 = bias ? bias[col + 1] : 0.f;
                *(float2*)&outF[(size_t)row * D_ + col]       = make_float2(v0 + b0, v1 + b1);
                *(float2*)&outF[(size_t)(row + 8) * D_ + col] = make_float2(v2 + b0, v3 + b1);
            }
    } else {
        // Lean flash-tiled epilogue; uniform per-CTA output select (fused QK).
        const int second = bn >> 10;
        const int nb = bn & 1023;
        const float scl = second ? scaleAlt : scale;
        __half* outH = second ? oH1 : oH0;
        __half* outL = second ? oL1 : oL0;
        const int bq   = bm >> 11;
        const int trow = ((bm & 2047) >> 6) + wm;
        const int hcol = (nb + wn * 32) >> 6;
        const size_t tb = ((size_t)(((bq << 4) + hcol) * 32 + trow)) << 12;
        const int r0 = lid >> 2;
        const int d0 = ((wn & 1) << 5) + ((lid & 3) << 1);
#pragma unroll
        for (int mi = 0; mi < 4; mi++) {
            const int r = r0 + mi * 16;
            const uint32_t rsw = (uint32_t)(r & 7);
#pragma unroll
            for (int ni = 0; ni < 4; ni++) {
                const int d = d0 + ni * 8;
                size_t off = tb + (size_t)(r * 64)
                           + ((((uint32_t)(d >> 3) ^ rsw) << 3)) + (d & 7);
                float v0 = acc[mi][ni][0] * scl, v1 = acc[mi][ni][1] * scl;
                float v2 = acc[mi][ni][2] * scl, v3 = acc[mi][ni][3] * scl;
                __half2 h0 = __floats2half2_rn(v0, v1);
                __half2 h1 = __floats2half2_rn(v2, v3);
                *(__half2*)&outH[off]       = h0;
                *(__half2*)&outH[off + 512] = h1;
                if (outL) {
                    __half2 l0 = __floats2half2_rn(v0 - __low2float(h0), v1 - __high2float(h0));
                    __half2 l1 = __floats2half2_rn(v2 - __low2float(h1), v3 - __high2float(h1));
                    *(__half2*)&outL[off]       = l0;
                    *(__half2*)&outL[off + 512] = l1;
                }
            }
        }
    }
}

// ---------------------------------------------------------------------------
// Flash attention: BM=64, 3-term S, 2-term PV, big-first, bulk-copy K/V,
// SW128 flash tiles, full/empty mbarrier ring (no per-iter __syncthreads).
// ---------------------------------------------------------------------------
#define F_TILE 8192
#define F_QB   (2 * F_TILE)
#define F_STGB (4 * F_TILE)
#define F_SMEM (F_QB + 2 * F_STGB + 128)

__global__ void __launch_bounds__(128) flash16_kernel(
    const __half* __restrict__ QH, const __half* __restrict__ QL,
    const __half* __restrict__ KH, const __half* __restrict__ KL,
    const __half* __restrict__ VH, const __half* __restrict__ VL,
    __half* __restrict__ CH)
{
    extern __shared__ char fsm[];
    const uint32_t sb  = smem_u32(fsm);
    const uint32_t bar = sb + F_QB + 2 * F_STGB;  // q@0, full[2]@8,16, empty[2]@24,32
    const int qt = (int)gridDim.x - 1 - (int)blockIdx.x;
    const int bh = blockIdx.y;
    const int b = bh >> 4, h = bh & 15;
    const int tid = threadIdx.x, wid = tid >> 5, lid = tid & 31;
    const size_t fb = ((size_t)bh) << 17;

    if (tid == 0) {
        MBAR_INIT(bar, 1);
        MBAR_INIT(bar + 8, 1);  MBAR_INIT(bar + 16, 1);
        MBAR_INIT(bar + 24, 128); MBAR_INIT(bar + 32, 128);
    }
    __syncthreads();

    auto issue_kv = [&](int kt, int s) {
        uint32_t mb = bar + 8 + s * 8;
        uint32_t sd = sb + F_QB + (uint32_t)s * F_STGB;
        size_t go = (fb + ((size_t)kt << 12)) * 2;
        MBAR_EXPECT(mb, F_STGB);
        bulk_g2s(sd,              (const char*)KH + go, F_TILE, mb);
        bulk_g2s(sd + F_TILE,     (const char*)KL + go, F_TILE, mb);
        bulk_g2s(sd + 2 * F_TILE, (const char*)VH + go, F_TILE, mb);
        bulk_g2s(sd + 3 * F_TILE, (const char*)VL + go, F_TILE, mb);
    };

    if (tid == 0) {
        size_t qo = (fb + ((size_t)qt << 12)) * 2;
        MBAR_EXPECT(bar, F_QB);
        bulk_g2s(sb,          (const char*)QH + qo, F_TILE, bar);
        bulk_g2s(sb + F_TILE, (const char*)QL + qo, F_TILE, bar);
        issue_kv(0, 0);
        if (qt >= 1) issue_kv(1, 1);
    }

    MBAR_WAIT(bar, 0);
    uint32_t qfh[4][4], qfl[4][4];
    {
        int r = wid * 16 + (lid & 15);
#pragma unroll
        for (int dc = 0; dc < 4; dc++) {
            int gran = dc * 2 + (lid >> 4);
            uint32_t a = sb + (uint32_t)(r * 128 + ((gran ^ (r & 7)) << 4));
            ldm4(qfh[dc], a);
            ldm4(qfl[dc], a + F_TILE);
        }
    }

    float oacc[8][4];
    float m_[2] = {-INFINITY, -INFINITY}, l_[2] = {0.f, 0.f};
#pragma unroll
    for (int ni = 0; ni < 8; ni++)
#pragma unroll
        for (int j = 0; j < 4; j++) oacc[ni][j] = 0.f;

    for (int kt = 0; kt <= qt; kt++) {
        const int s = kt & 1;
        MBAR_WAIT(bar + 8 + s * 8, (kt >> 1) & 1);

        const uint32_t ks = sb + F_QB + (uint32_t)s * F_STGB;

        float sacc[8][4];
#pragma unroll
        for (int ni = 0; ni < 8; ni++)
#pragma unroll
            for (int j = 0; j < 4; j++) sacc[ni][j] = 0.f;

#pragma unroll
        for (int dc = 0; dc < 4; dc++) {
#pragma unroll
            for (int g = 0; g < 4; g++) {
                int rr = g * 16 + (lid & 7) + ((lid >> 4) & 1) * 8;
                int gran = dc * 2 + ((lid >> 3) & 1);
                uint32_t ka = ks + (uint32_t)(rr * 128 + ((gran ^ (rr & 7)) << 4));
                uint32_t kh4[4], kl4[4];
                ldm4(kh4, ka);
                ldm4(kl4, ka + F_TILE);
                mma16816(sacc[2 * g],     qfh[dc], kh4[0], kh4[1]);
                mma16816(sacc[2 * g],     qfh[dc], kl4[0], kl4[1]);
                mma16816(sacc[2 * g],     qfl[dc], kh4[0], kh4[1]);
                mma16816(sacc[2 * g + 1], qfh[dc], kh4[2], kh4[3]);
                mma16816(sacc[2 * g + 1], qfh[dc], kl4[2], kl4[3]);
                mma16816(sacc[2 * g + 1], qfl[dc], kh4[2], kh4[3]);
            }
        }

        if (kt == qt) {
            int r0 = wid * 16 + (lid >> 2);
#pragma unroll
            for (int ni = 0; ni < 8; ni++) {
                int c0 = ni * 8 + (lid & 3) * 2;
                if (c0     > r0)     sacc[ni][0] = -INFINITY;
                if (c0 + 1 > r0)     sacc[ni][1] = -INFINITY;
                if (c0     > r0 + 8) sacc[ni][2] = -INFINITY;
                if (c0 + 1 > r0 + 8) sacc[ni][3] = -INFINITY;
            }
        }

#pragma unroll
        for (int r = 0; r < 2; r++) {
            float mt = -INFINITY;
#pragma unroll
            for (int ni = 0; ni < 8; ni++)
                mt = fmaxf(mt, fmaxf(sacc[ni][2 * r], sacc[ni][2 * r + 1]));
            mt = fmaxf(mt, __shfl_xor_sync(0xffffffffu, mt, 1));
            mt = fmaxf(mt, __shfl_xor_sync(0xffffffffu, mt, 2));
            float mn = fmaxf(m_[r], mt);
            float sc = __expf(m_[r] - mn);
            float ps = 0.f;
#pragma unroll
            for (int ni = 0; ni < 8; ni++) {
                float p0 = __expf(sacc[ni][2 * r]     - mn);
                float p1 = __expf(sacc[ni][2 * r + 1] - mn);
                sacc[ni][2 * r] = p0; sacc[ni][2 * r + 1] = p1;
                ps += p0 + p1;
            }
            ps += __shfl_xor_sync(0xffffffffu, ps, 1);
            ps += __shfl_xor_sync(0xffffffffu, ps, 2);
            l_[r] = l_[r] * sc + ps;
            m_[r] = mn;
#pragma unroll
            for (int ni = 0; ni < 8; ni++) {
                oacc[ni][2 * r]     *= sc;
                oacc[ni][2 * r + 1] *= sc;
            }
        }

        uint32_t pah[4][4];
#pragma unroll
        for (int kc = 0; kc < 4; kc++) {
#pragma unroll
            for (int q = 0; q < 4; q++) {
                int ni = 2 * kc + (q >> 1);
                __half2 hp = __floats2half2_rn(sacc[ni][(q & 1) * 2],
                                               sacc[ni][(q & 1) * 2 + 1]);
                pah[kc][q] = h2_bits(hp);
            }
        }

        const uint32_t vs = ks + 2 * F_TILE;
#pragma unroll
        for (int kc = 0; kc < 4; kc++) {
#pragma unroll
            for (int g = 0; g < 4; g++) {
                int rv = kc * 16 + (lid & 7) + ((lid >> 3) & 1) * 8;
                int gran = g * 2 + (lid >> 4);
                uint32_t va = vs + (uint32_t)(rv * 128 + ((gran ^ (rv & 7)) << 4));
                uint32_t vh4[4], vl4[4];
                ldm4t(vh4, va);
                ldm4t(vl4, va + F_TILE);
                mma16816(oacc[2 * g],     pah[kc], vh4[0], vh4[1]);
                mma16816(oacc[2 * g],     pah[kc], vl4[0], vl4[1]);
                mma16816(oacc[2 * g + 1], pah[kc], vh4[2], vh4[3]);
                mma16816(oacc[2 * g + 1], pah[kc], vl4[2], vl4[3]);
            }
        }

        // Consumer release for stage s (K and V reads consumed by MMAs above)
        MBAR_ARRIVE(bar + 24 + s * 8);
        if (tid == 0 && kt + 2 <= qt) {
            MBAR_WAIT(bar + 24 + s * 8, (kt >> 1) & 1);
            issue_kv(kt + 2, s);
        }
    }

    float inv0 = 1.f / l_[0], inv1 = 1.f / l_[1];
    int m0 = b * T_ + qt * 64 + wid * 16 + (lid >> 2);
#pragma unroll
    for (int ni = 0; ni < 8; ni++) {
        int colD = h * HD_ + ni * 8 + (lid & 3) * 2;
        __half2 h0 = __floats2half2_rn(oacc[ni][0] * inv0, oacc[ni][1] * inv0);
        __half2 h1 = __floats2half2_rn(oacc[ni][2] * inv1, oacc[ni][3] * inv1);
        *(__half2*)&CH[tiled_off(m0,     colD)] = h0;
        *(__half2*)&CH[tiled_off(m0 + 8, colD)] = h1;
    }
}

// ---------------------------------------------------------------------------
extern "C" void kernel_launch(void* const* d_in, const int* in_sizes, int n_in,
                              void* d_out, int out_size)
{
    const float* X  = (const float*)d_in[0];
    const float* Wq = (const float*)d_in[1];
    const float* Wk = (const float*)d_in[2];
    const float* Wv = (const float*)d_in[3];
    const float* Wo = (const float*)d_in[4];
    const float* bo = (const float*)d_in[5];
    float* Y = (float*)d_out;

    __half *gXH, *gXL, *gQH, *gQL, *gKH, *gKL, *gVH, *gVL, *gCH, *gWT;
    cudaGetSymbolAddress((void**)&gXH, g_XH);
    cudaGetSymbolAddress((void**)&gXL, g_XL);
    cudaGetSymbolAddress((void**)&gQH, g_QH);
    cudaGetSymbolAddress((void**)&gQL, g_QL);
    cudaGetSymbolAddress((void**)&gKH, g_KH);
    cudaGetSymbolAddress((void**)&gKL, g_KL);
    cudaGetSymbolAddress((void**)&gVH, g_VH);
    cudaGetSymbolAddress((void**)&gVL, g_VL);
    cudaGetSymbolAddress((void**)&gCH, g_CH);
    cudaGetSymbolAddress((void**)&gWT, g_WT16);
    const size_t WSZ = (size_t)D_ * D_;

    cudaFuncSetAttribute((const void*)gemm16_kernel<3, 1>,
                         cudaFuncAttributeMaxDynamicSharedMemorySize, G_SMEM);
    cudaFuncSetAttribute((const void*)gemm16_kernel<2, 1>,
                         cudaFuncAttributeMaxDynamicSharedMemorySize, G_SMEM);
    cudaFuncSetAttribute((const void*)gemm16_kernel<2, 0>,
                         cudaFuncAttributeMaxDynamicSharedMemorySize, G_SMEM);
    cudaFuncSetAttribute((const void*)flash16_kernel,
                         cudaFuncAttributeMaxDynamicSharedMemorySize, F_SMEM);

    const int n4 = (M_ * D_) / 4;
    split16_kernel<<<(n4 + 255) / 256, 256>>>((const float4*)X, gXH, gXL, n4);
    transpose_split16_all<<<dim3(32, 32, 4), dim3(32, 8)>>>(Wq, Wk, Wv, Wo, gWT);

    // Fused Q+K projection: B spans WqH|WkH (hi) and WqL|WkL (lo), contiguous.
    // CTAs with bn<1024 -> Q (scale 0.125); bn>=1024 -> K (scale 1.0).
    gemm16_kernel<3, 1><<<dim3(2 * D_ / 128, M_ / 128), 256, G_SMEM>>>(
        gXH, gXL, gWT + 0 * WSZ, gWT + 3 * WSZ,
        nullptr, 0.125f, 1.0f, nullptr, gQH, gQL, gKH, gKL);
    // V projection (2-term)
    gemm16_kernel<2, 1><<<dim3(D_ / 128, M_ / 128), 256, G_SMEM>>>(
        gXH, gXL, gWT + 2 * WSZ, gWT + 5 * WSZ,
        nullptr, 1.0f, 1.0f, nullptr, gVH, gVL, gVH, gVL);

    flash16_kernel<<<dim3(T_ / 64, B_ * H_), 128, F_SMEM>>>(
        gQH, gQL, gKH, gKL, gVH, gVL, gCH);

    // Output projection (2-term, fp32 out + bias)
    gemm16_kernel<2, 0><<<dim3(D_ / 128, M_ / 128), 256, G_SMEM>>>(
        gCH, nullptr, gWT + 6 * WSZ, gWT + 7 * WSZ,
        bo, 1.0f, 1.0f, Y, nullptr, nullptr, nullptr, nullptr);
}